// round 5
// baseline (speedup 1.0000x reference)
#include <cuda_runtime.h>
#include <cuda_bf16.h>
#include <cuda_fp8.h>
#include <math.h>
#include <stdint.h>

#define SEQ     4096
#define BATCH   2
#define ROWS    (BATCH*SEQ)     // 8192
#define DIMK    2048
#define D_INNER 4096
#define NHEADS  64
#define NPROJ   8480
#define OFF_Z   0
#define OFF_XC  4096
#define OFF_B   8192
#define OFF_C   8256
#define OFF_DT  8320
#define OFF_TH  8384
#define OFF_LAM 8416
#define NCHUNK  64
#define RMS_EPS 1.1920929e-07f

typedef __nv_fp8_e4m3 fp8;

// ---------------- device scratch ----------------
// fp8 weights (z+xc rows of in-proj), 3 exponent-shifted copies: q, q*2^-5, q*2^-9
__device__ fp8   g_Wq0[8192 * DIMK];
__device__ fp8   g_Wq5[8192 * DIMK];
__device__ fp8   g_Wq9[8192 * DIMK];
__device__ float g_Ws8[8192 * 16];
__device__ fp8   g_Wo0[DIMK * D_INNER];
__device__ fp8   g_Wo5[DIMK * D_INNER];
__device__ fp8   g_Wo9[DIMK * D_INNER];
__device__ float g_Wos[DIMK * 32];
// bf16 weights for sensitive 288 cols (B,C,dt,theta,lambda), padded to 384 rows
__device__ __nv_bfloat16 g_Wqb[384 * DIMK];
__device__ float         g_Wsb[384 * 16];
// activations
__device__ __nv_bfloat16 g_xh[ROWS * DIMK];
__device__ __nv_bfloat16 g_xl[ROWS * DIMK];
__device__ fp8 g_xq0[ROWS * DIMK];
__device__ fp8 g_xq1[ROWS * DIMK];
__device__ fp8 g_xq2[ROWS * DIMK];
__device__ fp8 g_Yq0[ROWS * D_INNER];
__device__ fp8 g_Yq1[ROWS * D_INNER];
__device__ fp8 g_Yq2[ROWS * D_INNER];
__device__ float g_P [ROWS * NPROJ];
__device__ float g_Bv[ROWS * 64];
__device__ float g_Cv[ROWS * 64];
__device__ float g_Ad[ROWS * 64];
__device__ float g_ga[ROWS * 64];
__device__ float g_be[ROWS * 64];
__device__ float g_td[ROWS * 32];
__device__ float g_Y [ROWS * D_INNER];
__device__ float g_S [BATCH * NCHUNK * NHEADS * 64 * 64];
__device__ float g_eA[BATCH * NCHUNK * NHEADS * 64];
__device__ float g_cd[BATCH * NCHUNK * NHEADS];

__device__ __forceinline__ float siluf(float x) { return x / (1.f + expf(-x)); }

__device__ __forceinline__ uint32_t s2u(const void* p) {
    uint32_t a;
    asm("{ .reg .u64 t; cvta.to.shared.u64 t, %1; cvt.u32.u64 %0, t; }" : "=r"(a) : "l"(p));
    return a;
}

__device__ __forceinline__ void cpasync16(uint32_t dst, const void* src) {
    asm volatile("cp.async.cg.shared.global [%0], [%1], 16;" :: "r"(dst), "l"(src));
}
#define CP_COMMIT() asm volatile("cp.async.commit_group;" ::: "memory")
#define CP_WAIT1()  asm volatile("cp.async.wait_group 1;" ::: "memory")

#define LDSM4(r0,r1,r2,r3,a) \
    asm volatile("ldmatrix.sync.aligned.m8n8.x4.shared.b16 {%0,%1,%2,%3}, [%4];" \
        : "=r"(r0),"=r"(r1),"=r"(r2),"=r"(r3) : "r"(a))

#define MMA16816(d,a,b0,b1) \
    asm volatile("mma.sync.aligned.m16n8k16.row.col.f32.bf16.bf16.f32 " \
        "{%0,%1,%2,%3}, {%4,%5,%6,%7}, {%8,%9}, {%0,%1,%2,%3};" \
        : "+f"((d)[0]),"+f"((d)[1]),"+f"((d)[2]),"+f"((d)[3]) \
        : "r"((a)[0]),"r"((a)[1]),"r"((a)[2]),"r"((a)[3]),"r"(b0),"r"(b1))

#define MMA8(d,a,b0,b1) \
    asm volatile("mma.sync.aligned.m16n8k32.row.col.f32.e4m3.e4m3.f32 " \
        "{%0,%1,%2,%3}, {%4,%5,%6,%7}, {%8,%9}, {%0,%1,%2,%3};" \
        : "+f"((d)[0]),"+f"((d)[1]),"+f"((d)[2]),"+f"((d)[3]) \
        : "r"((a)[0]),"r"((a)[1]),"r"((a)[2]),"r"((a)[3]),"r"(b0),"r"(b1))

// ================= fp8 3-term emulated GEMM =================
// C[M,Nw] = A[M,K] * B[N,K]^T; A split into e4m3 terms (x, r1*2^5, r2*2^9),
// B copies (q, q*2^-5, q*2^-9); group scales folded every 128 K.
#define PADB 48
#define ARR_B (128*PADB)          // 6144 bytes
#define BUF_B (6*ARR_B)           // 36864 bytes: A0,A1,A2,B0,B5,B9
#define SS8_OFF (2*BUF_B)         // 73728

template<int NG>
__global__ void __launch_bounds__(256, 1)
k_mmq8(const fp8* __restrict__ A0, const fp8* __restrict__ A1, const fp8* __restrict__ A2,
       const fp8* __restrict__ B0, const fp8* __restrict__ B5, const fp8* __restrict__ B9,
       const float* __restrict__ Bs, float* __restrict__ C, int Nw, int Nlim, int K)
{
    extern __shared__ uint8_t sh8[];
    float* ss = (float*)(sh8 + SS8_OFF);
    const uint32_t sb = s2u(sh8);
    const int tid  = threadIdx.x;
    const int lane = tid & 31;
    const int wid  = tid >> 5;
    const int m0 = blockIdx.x * 128;
    const int n0 = blockIdx.y * 128;
    const int mw = (wid >> 2) * 64;
    const int nw = (wid & 3) * 32;

    const fp8* srcs[6] = { A0, A1, A2, B0, B5, B9 };

    for (int idx = tid; idx < 128 * NG; idx += 256) {
        int g = idx >> 7, nl = idx & 127;
        ss[g * 132 + nl] = Bs[(size_t)(n0 + nl) * NG + g];
    }

    float acc[4][4][4];
#pragma unroll
    for (int i = 0; i < 4; i++)
#pragma unroll
        for (int j = 0; j < 4; j++)
#pragma unroll
            for (int k = 0; k < 4; k++) acc[i][j][k] = 0.f;

    const int NK = K >> 5;

#define FILL8(buf, kc) do {                                                      \
        int kb = (kc) * 32;                                                      \
_Pragma("unroll")                                                                \
        for (int i = 0; i < 6; i++) {                                            \
            int idx = i * 256 + tid;                                             \
            int arr = idx >> 8;                                                  \
            int r   = (idx >> 1) & 127;                                          \
            int c   = (idx & 1) * 16;                                            \
            int grow = (arr < 3) ? (m0 + r) : (n0 + r);                          \
            const fp8* sp = srcs[arr] + (size_t)grow * K + kb + c;               \
            uint32_t dp = sb + (buf) * BUF_B + arr * ARR_B + r * PADB + c;       \
            cpasync16(dp, sp);                                                   \
        }                                                                        \
    } while (0)

    FILL8(0, 0);
    CP_COMMIT();

    const int rowoff = (lane & 7) + ((lane >> 3) & 1) * 8;
    const int colb = (lane >> 4) * 16;
    const int c0 = (lane & 3) * 2;

    for (int g = 0; g < NG; g++) {
        float accg[4][4][4];
#pragma unroll
        for (int i = 0; i < 4; i++)
#pragma unroll
            for (int j = 0; j < 4; j++)
#pragma unroll
                for (int k = 0; k < 4; k++) accg[i][j][k] = 0.f;

#pragma unroll
        for (int kq = 0; kq < 4; kq++) {
            const int kc = g * 4 + kq;
            const int buf = kc & 1;
            if (kc + 1 < NK) FILL8(buf ^ 1, kc + 1);
            CP_COMMIT();
            CP_WAIT1();
            __syncthreads();

            uint32_t bfr[3][2][4];
#pragma unroll
            for (int w = 0; w < 3; w++)
#pragma unroll
                for (int nj = 0; nj < 2; nj++) {
                    uint32_t a = sb + buf * BUF_B + (3 + w) * ARR_B +
                                 (nw + nj * 16 + rowoff) * PADB + colb;
                    LDSM4(bfr[w][nj][0], bfr[w][nj][1], bfr[w][nj][2], bfr[w][nj][3], a);
                }
#pragma unroll
            for (int term = 0; term < 3; term++) {
                uint32_t afr[4][4];
#pragma unroll
                for (int mi = 0; mi < 4; mi++) {
                    uint32_t a = sb + buf * BUF_B + term * ARR_B +
                                 (mw + mi * 16 + rowoff) * PADB + colb;
                    LDSM4(afr[mi][0], afr[mi][1], afr[mi][2], afr[mi][3], a);
                }
#pragma unroll
                for (int mi = 0; mi < 4; mi++)
#pragma unroll
                    for (int ni = 0; ni < 4; ni++) {
                        int nj = ni >> 1, s = ni & 1;
                        MMA8(accg[mi][ni], afr[mi], bfr[term][nj][s], bfr[term][nj][s + 2]);
                    }
            }
            __syncthreads();
        }

#pragma unroll
        for (int ni = 0; ni < 4; ni++) {
            float2 sv = *(const float2*)&ss[g * 132 + nw + ni * 8 + c0];
#pragma unroll
            for (int mi = 0; mi < 4; mi++) {
                acc[mi][ni][0] = fmaf(sv.x, accg[mi][ni][0], acc[mi][ni][0]);
                acc[mi][ni][1] = fmaf(sv.y, accg[mi][ni][1], acc[mi][ni][1]);
                acc[mi][ni][2] = fmaf(sv.x, accg[mi][ni][2], acc[mi][ni][2]);
                acc[mi][ni][3] = fmaf(sv.y, accg[mi][ni][3], acc[mi][ni][3]);
            }
        }
    }

    const int r0 = lane >> 2;
#pragma unroll
    for (int mi = 0; mi < 4; mi++) {
#pragma unroll
        for (int ni = 0; ni < 4; ni++) {
            int m = m0 + mw + mi * 16 + r0;
            int n = n0 + nw + ni * 8 + c0;
            if (n < Nlim) {
                *(float2*)&C[(size_t)m * Nw + n]       = make_float2(acc[mi][ni][0], acc[mi][ni][1]);
                *(float2*)&C[(size_t)(m + 8) * Nw + n] = make_float2(acc[mi][ni][2], acc[mi][ni][3]);
            }
        }
    }
#undef FILL8
}

// ================= bf16 2-term GEMM (sensitive columns) =================
#define PADH 40
#define ARR_H (128*PADH)
#define BUF_H (3*ARR_H)
#define SS_OFF (2*BUF_H)

__global__ void __launch_bounds__(256, 1)
k_mmq(const __nv_bfloat16* __restrict__ Ah, const __nv_bfloat16* __restrict__ Al,
      const __nv_bfloat16* __restrict__ Bq, const float* __restrict__ Bs,
      float* __restrict__ C, int Nw, int Nlim, int K)
{
    const int NG = 16;
    extern __shared__ __nv_bfloat16 sh[];
    float* ss = (float*)(sh + SS_OFF);
    const uint32_t sb = s2u(sh);
    const int tid  = threadIdx.x;
    const int lane = tid & 31;
    const int wid  = tid >> 5;
    const int m0 = blockIdx.x * 128;
    const int n0 = blockIdx.y * 128;
    const int mw = (wid >> 2) * 64;
    const int nw = (wid & 3) * 32;

    for (int idx = tid; idx < 128 * NG; idx += 256) {
        int g = idx >> 7, nl = idx & 127;
        ss[g * 132 + nl] = Bs[(size_t)(n0 + nl) * NG + g];
    }

    float acc[4][4][4];
#pragma unroll
    for (int i = 0; i < 4; i++)
#pragma unroll
        for (int j = 0; j < 4; j++)
#pragma unroll
            for (int k = 0; k < 4; k++) acc[i][j][k] = 0.f;

    const int NK = K >> 5;

#define FILLQ(buf, kc) do {                                                      \
        int kb = (kc) * 32;                                                      \
_Pragma("unroll")                                                                \
        for (int i = 0; i < 6; i++) {                                            \
            int idx = i * 256 + tid;                                             \
            int arr = idx >> 9;                                                  \
            int r   = (idx >> 2) & 127;                                          \
            int c   = idx & 3;                                                   \
            const __nv_bfloat16* sp = (arr == 0) ? (Ah + (size_t)(m0 + r) * K)   \
                                    : (arr == 1) ? (Al + (size_t)(m0 + r) * K)   \
                                                 : (Bq + (size_t)(n0 + r) * K);  \
            uint32_t dp = sb + ((buf) * BUF_H + arr * ARR_H + r * PADH + c * 8) * 2; \
            cpasync16(dp, sp + kb + c * 8);                                      \
        }                                                                        \
    } while (0)

    FILLQ(0, 0);
    CP_COMMIT();

    const int rowoff = (lane & 7) + ((lane >> 3) & 1) * 8;
    const int coloff = (lane >> 4) * 8;
    const int c0 = (lane & 3) * 2;

    for (int g = 0; g < NG; g++) {
        float accg[4][4][4];
#pragma unroll
        for (int i = 0; i < 4; i++)
#pragma unroll
            for (int j = 0; j < 4; j++)
#pragma unroll
                for (int k = 0; k < 4; k++) accg[i][j][k] = 0.f;

#pragma unroll
        for (int kq = 0; kq < 4; kq++) {
            const int kc = g * 4 + kq;
            const int buf = kc & 1;
            if (kc + 1 < NK) FILLQ(buf ^ 1, kc + 1);
            CP_COMMIT();
            CP_WAIT1();
            __syncthreads();

#pragma unroll
            for (int kk = 0; kk < 2; kk++) {
                uint32_t afr[2][4][4];
                uint32_t bfr[2][4];
#pragma unroll
                for (int hl = 0; hl < 2; hl++)
#pragma unroll
                    for (int mi = 0; mi < 4; mi++) {
                        uint32_t a = sb + (buf * BUF_H + hl * ARR_H +
                            (mw + mi * 16 + rowoff) * PADH + kk * 16 + coloff) * 2;
                        LDSM4(afr[hl][mi][0], afr[hl][mi][1], afr[hl][mi][2], afr[hl][mi][3], a);
                    }
#pragma unroll
                for (int nj = 0; nj < 2; nj++) {
                    uint32_t a = sb + (buf * BUF_H + 2 * ARR_H +
                        (nw + nj * 16 + rowoff) * PADH + kk * 16 + coloff) * 2;
                    LDSM4(bfr[nj][0], bfr[nj][1], bfr[nj][2], bfr[nj][3], a);
                }
#pragma unroll
                for (int term = 0; term < 2; term++)
#pragma unroll
                    for (int mi = 0; mi < 4; mi++)
#pragma unroll
                        for (int ni = 0; ni < 4; ni++) {
                            int nj = ni >> 1, s = ni & 1;
                            MMA16816(accg[mi][ni], afr[term][mi],
                                     bfr[nj][s], bfr[nj][s + 2]);
                        }
            }
            __syncthreads();
        }

#pragma unroll
        for (int ni = 0; ni < 4; ni++) {
            float2 sv = *(const float2*)&ss[g * 132 + nw + ni * 8 + c0];
#pragma unroll
            for (int mi = 0; mi < 4; mi++) {
                acc[mi][ni][0] = fmaf(sv.x, accg[mi][ni][0], acc[mi][ni][0]);
                acc[mi][ni][1] = fmaf(sv.y, accg[mi][ni][1], acc[mi][ni][1]);
                acc[mi][ni][2] = fmaf(sv.x, accg[mi][ni][2], acc[mi][ni][2]);
                acc[mi][ni][3] = fmaf(sv.y, accg[mi][ni][3], acc[mi][ni][3]);
            }
        }
    }

    const int r0 = lane >> 2;
#pragma unroll
    for (int mi = 0; mi < 4; mi++) {
#pragma unroll
        for (int ni = 0; ni < 4; ni++) {
            int m = m0 + mw + mi * 16 + r0;
            int n = n0 + nw + ni * 8 + c0;
            if (n < Nlim) {
                *(float2*)&C[(size_t)m * Nw + n]       = make_float2(acc[mi][ni][0], acc[mi][ni][1]);
                *(float2*)&C[(size_t)(m + 8) * Nw + n] = make_float2(acc[mi][ni][2], acc[mi][ni][3]);
            }
        }
    }
#undef FILLQ
}

// ---------------- dequant helpers ----------------
__device__ __forceinline__ float wq_of_group(const float* s, int lane, int i, float scale) {
    float q = rintf(s[lane + 32*i] / scale);
    return fminf(fmaxf(q, -8.f), 7.f);
}

// fq4 -> 3 fp8 exponent-shifted copies + scale
__global__ void k_dequant8(const float* __restrict__ src, fp8* __restrict__ w0,
                           fp8* __restrict__ w5, fp8* __restrict__ w9,
                           float* __restrict__ ds, int ngroups)
{
    int g = blockIdx.x * 4 + (threadIdx.x >> 5);
    if (g >= ngroups) return;
    int lane = threadIdx.x & 31;
    const float* s = src + (size_t)g * 128;
    float v[4], m = 0.f;
#pragma unroll
    for (int i = 0; i < 4; i++) { v[i] = s[lane + 32*i]; m = fmaxf(m, fabsf(v[i])); }
#pragma unroll
    for (int o = 16; o; o >>= 1) m = fmaxf(m, __shfl_xor_sync(0xffffffffu, m, o));
    float scale = fmaxf(m, 1e-10f) / 7.0f;
    if (lane == 0) ds[g] = scale;
#pragma unroll
    for (int i = 0; i < 4; i++) {
        float q = rintf(v[i] / scale);
        q = fminf(fmaxf(q, -8.f), 7.f);
        size_t o = (size_t)g * 128 + lane + 32*i;
        w0[o] = fp8(q);
        w5[o] = fp8(q * 0.03125f);        // q*2^-5, exact in e4m3
        w9[o] = fp8(q * 0.001953125f);    // q*2^-9, exact (denormals)
    }
}

// fq4 -> bf16 q + scale (sensitive columns)
__global__ void k_dequantb(const float* __restrict__ src, __nv_bfloat16* __restrict__ dq,
                           float* __restrict__ ds, int ngroups)
{
    int g = blockIdx.x * 4 + (threadIdx.x >> 5);
    if (g >= ngroups) return;
    int lane = threadIdx.x & 31;
    const float* s = src + (size_t)g * 128;
    float v[4], m = 0.f;
#pragma unroll
    for (int i = 0; i < 4; i++) { v[i] = s[lane + 32*i]; m = fmaxf(m, fabsf(v[i])); }
#pragma unroll
    for (int o = 16; o; o >>= 1) m = fmaxf(m, __shfl_xor_sync(0xffffffffu, m, o));
    float scale = fmaxf(m, 1e-10f) / 7.0f;
    if (lane == 0) ds[g] = scale;
#pragma unroll
    for (int i = 0; i < 4; i++) {
        float q = rintf(v[i] / scale);
        q = fminf(fmaxf(q, -8.f), 7.f);
        dq[(size_t)g * 128 + lane + 32*i] = __float2bfloat16(q);
    }
}

// ---------------- activation splits ----------------
__device__ __forceinline__ void fp8_split3(float v, fp8& a0, fp8& a1, fp8& a2) {
    fp8 h0 = fp8(v);
    float r1 = v - float(h0);
    fp8 h1 = fp8(r1 * 32.f);
    float r2 = r1 - float(h1) * 0.03125f;
    fp8 h2 = fp8(r2 * 512.f);
    a0 = h0; a1 = h1; a2 = h2;
}

__global__ void k_split(const float* __restrict__ src, __nv_bfloat16* __restrict__ dh,
                        __nv_bfloat16* __restrict__ dl,
                        fp8* __restrict__ q0, fp8* __restrict__ q1, fp8* __restrict__ q2)
{
    size_t i = ((size_t)blockIdx.x * 256 + threadIdx.x) * 4;
    float4 v = *(const float4*)(src + i);
    float vv[4] = {v.x, v.y, v.z, v.w};
#pragma unroll
    for (int k = 0; k < 4; k++) {
        __nv_bfloat16 h = __float2bfloat16(vv[k]);
        dh[i + k] = h;
        dl[i + k] = __float2bfloat16(vv[k] - __bfloat162float(h));
        fp8_split3(vv[k], q0[i + k], q1[i + k], q2[i + k]);
    }
}

// ---------------- pointwise epilogue ----------------
__global__ void k_point(const float* __restrict__ Bb, const float* __restrict__ Cb,
                        const float* __restrict__ Alog, const float* __restrict__ dtb)
{
    int row = blockIdx.x;
    int t = threadIdx.x;
    const float* pr = g_P + (size_t)row * NPROJ;
    __shared__ float red[6];

    float dtr = pr[OFF_DT + t] + dtb[t];
    float dt = (dtr > 20.f) ? dtr : log1pf(expf(dtr));
    float Ad = -expf(Alog[t]) * dt;
    float lam = 1.f / (1.f + expf(-pr[OFF_LAM + t]));
    g_Ad[row*64 + t] = Ad;
    g_ga[row*64 + t] = lam * dt;
    g_be[row*64 + t] = (1.f - lam) * dt * expf(Ad);

    float bv = pr[OFF_B + t];
    float cv = pr[OFF_C + t];

    float s0 = dt, s1 = bv*bv, s2 = cv*cv;
#pragma unroll
    for (int o = 16; o; o >>= 1) {
        s0 += __shfl_xor_sync(0xffffffffu, s0, o);
        s1 += __shfl_xor_sync(0xffffffffu, s1, o);
        s2 += __shfl_xor_sync(0xffffffffu, s2, o);
    }
    int w = t >> 5;
    if ((t & 31) == 0) { red[w*3+0] = s0; red[w*3+1] = s1; red[w*3+2] = s2; }
    __syncthreads();
    float dt_avg = (red[0] + red[3]) * (1.f/64.f);
    float rb = rsqrtf((red[1] + red[4]) * (1.f/64.f) + RMS_EPS);
    float rc = rsqrtf((red[2] + red[5]) * (1.f/64.f) + RMS_EPS);

    g_Bv[row*64 + t] = bv * rb + Bb[t];
    g_Cv[row*64 + t] = cv * rc + Cb[t];
    if (t < 32) g_td[row*32 + t] = pr[OFF_TH + t] * dt_avg;
}

// ---------------- cumsum of theta*dt_avg ----------------
__global__ void k_scan()
{
    int b = blockIdx.x >> 5;
    int n = blockIdx.x & 31;
    int tid = threadIdx.x;
    __shared__ float ps[256];
    float loc[16];
    float run = 0.f;
    int base = (b*SEQ + tid*16) * 32 + n;
#pragma unroll
    for (int j = 0; j < 16; j++) { run += g_td[base + j*32]; loc[j] = run; }
    ps[tid] = run;
    __syncthreads();
#pragma unroll
    for (int o = 1; o < 256; o <<= 1) {
        float v = (tid >= o) ? ps[tid - o] : 0.f;
        __syncthreads();
        ps[tid] += v;
        __syncthreads();
    }
    float off = (tid > 0) ? ps[tid - 1] : 0.f;
#pragma unroll
    for (int j = 0; j < 16; j++) g_td[base + j*32] = loc[j] + off;
}

// ---------------- rope ----------------
__global__ void k_rope()
{
    int row = blockIdx.x;
    int t = threadIdx.x;
    float a = g_td[row*32 + t];
    float ca = cosf(a), sa = sinf(a);
    float br = g_Bv[row*64 + t], bi = g_Bv[row*64 + 32 + t];
    g_Bv[row*64 + t]      = br*ca - bi*sa;
    g_Bv[row*64 + 32 + t] = br*sa + bi*ca;
    float cr = g_Cv[row*64 + t], ci = g_Cv[row*64 + 32 + t];
    g_Cv[row*64 + t]      = cr*ca - ci*sa;
    g_Cv[row*64 + 32 + t] = cr*sa + ci*ca;
}

// ---------------- intra-chunk ----------------
#define SM_CHUNK_BYTES ((4352*5 + 128) * 4)
__launch_bounds__(256)
__global__ void k_chunk()
{
    extern __shared__ float sm[];
    float* sX  = sm;
    float* sB  = sm + 4352;
    float* sBT = sm + 8704;
    float* sCT = sm + 13056;
    float* sGT = sm + 17408;
    float* sA  = sm + 21760;
    float* sW  = sm + 21824;

    const int h = blockIdx.x, c = blockIdx.y, b = blockIdx.z;
    const int tid = threadIdx.x;

    if (tid < 64) {
        int row_g = b*SEQ + c*64 + tid;
        sA[tid] = g_Ad[row_g*64 + h];
    }
    __syncthreads();
#pragma unroll
    for (int o = 1; o < 64; o <<= 1) {
        float v = (tid < 64 && tid >= o) ? sA[tid - o] : 0.f;
        __syncthreads();
        if (tid < 64) sA[tid] += v;
        __syncthreads();
    }
    float Alast = sA[63];
    if (tid < 64) {
        sW[tid] = expf(Alast - sA[tid]);
        g_eA[((b*NCHUNK + c)*NHEADS + h)*64 + tid] = expf(sA[tid]);
    }
    if (tid == 0) g_cd[(b*NCHUNK + c)*NHEADS + h] = expf(Alast);

#pragma unroll
    for (int it = 0; it < 4; it++) {
        int idx = tid + it*256;
        int l = idx >> 4;
        int p4 = (idx & 15) << 2;
        int row_g = b*SEQ + c*64 + l;
        const float* xp = g_P + (size_t)row_g*NPROJ + OFF_XC + h*64 + p4;
        float4 xc = *(const float4*)xp;
        float ga = g_ga[row_g*64 + h];
        float be = g_be[row_g*64 + h];
        float4 xv;
        xv.x = siluf(xc.x)*ga; xv.y = siluf(xc.y)*ga; xv.z = siluf(xc.z)*ga; xv.w = siluf(xc.w)*ga;
        if (c*64 + l > 0) {
            float4 xq = *(const float4*)(xp - NPROJ);
            xv.x += siluf(xq.x)*be; xv.y += siluf(xq.y)*be; xv.z += siluf(xq.z)*be; xv.w += siluf(xq.w)*be;
        }
        *(float4*)&sX[l*68 + p4] = xv;
        float4 bb = *(const float4*)&g_Bv[row_g*64 + p4];
        *(float4*)&sB[l*68 + p4] = bb;
        sBT[(p4+0)*68 + l] = bb.x; sBT[(p4+1)*68 + l] = bb.y;
        sBT[(p4+2)*68 + l] = bb.z; sBT[(p4+3)*68 + l] = bb.w;
        float4 cc = *(const float4*)&g_Cv[row_g*64 + p4];
        sCT[(p4+0)*68 + l] = cc.x; sCT[(p4+1)*68 + l] = cc.y;
        sCT[(p4+2)*68 + l] = cc.z; sCT[(p4+3)*68 + l] = cc.w;
    }
    __syncthreads();

    const int ti = tid >> 4, tj = tid & 15;

    {
        const int l0 = ti*4, s0 = tj*4;
        float acc[4][4];
#pragma unroll
        for (int i = 0; i < 4; i++)
#pragma unroll
            for (int j = 0; j < 4; j++) acc[i][j] = 0.f;
#pragma unroll
        for (int n = 0; n < 64; n++) {
            float4 cl = *(const float4*)&sCT[n*68 + l0];
            float4 bs = *(const float4*)&sBT[n*68 + s0];
            float clv[4] = {cl.x, cl.y, cl.z, cl.w};
            float bsv[4] = {bs.x, bs.y, bs.z, bs.w};
#pragma unroll
            for (int i = 0; i < 4; i++)
#pragma unroll
                for (int j = 0; j < 4; j++)
                    acc[i][j] = fmaf(clv[i], bsv[j], acc[i][j]);
        }
        float al[4];
#pragma unroll
        for (int i = 0; i < 4; i++) al[i] = sA[l0 + i];
#pragma unroll
        for (int j = 0; j < 4; j++) {
            int s = s0 + j;
            float as = sA[s];
#pragma unroll
            for (int i = 0; i < 4; i++) {
                int l = l0 + i;
                sGT[s*68 + l] = (s <= l) ? acc[i][j] * expf(al[i] - as) : 0.f;
            }
        }
    }
    __syncthreads();

    {
        const int l0 = ti*4, p0 = tj*4;
        float acc[4][4];
#pragma unroll
        for (int i = 0; i < 4; i++)
#pragma unroll
            for (int j = 0; j < 4; j++) acc[i][j] = 0.f;
#pragma unroll
        for (int s = 0; s < 64; s++) {
            float4 gt = *(const float4*)&sGT[s*68 + l0];
            float4 xr = *(const float4*)&sX[s*68 + p0];
            float gv[4] = {gt.x, gt.y, gt.z, gt.w};
            float xvv[4] = {xr.x, xr.y, xr.z, xr.w};
#pragma unroll
            for (int i = 0; i < 4; i++)
#pragma unroll
                for (int j = 0; j < 4; j++)
                    acc[i][j] = fmaf(gv[i], xvv[j], acc[i][j]);
        }
#pragma unroll
        for (int i = 0; i < 4; i++) {
            int row_g = b*SEQ + c*64 + l0 + i;
            *(float4*)&g_Y[(size_t)row_g*D_INNER + h*64 + p0] =
                make_float4(acc[i][0], acc[i][1], acc[i][2], acc[i][3]);
        }
    }

    {
        const int p0 = ti*4, n0 = tj*4;
        float acc[4][4];
#pragma unroll
        for (int i = 0; i < 4; i++)
#pragma unroll
            for (int j = 0; j < 4; j++) acc[i][j] = 0.f;
#pragma unroll
        for (int l = 0; l < 64; l++) {
            float w = sW[l];
            float4 xr = *(const float4*)&sX[l*68 + p0];
            float4 br = *(const float4*)&sB[l*68 + n0];
            float wx[4] = {w*xr.x, w*xr.y, w*xr.z, w*xr.w};
            float bvv[4] = {br.x, br.y, br.z, br.w};
#pragma unroll
            for (int i = 0; i < 4; i++)
#pragma unroll
                for (int j = 0; j < 4; j++)
                    acc[i][j] = fmaf(wx[i], bvv[j], acc[i][j]);
        }
        size_t base = (size_t)((b*NCHUNK + c)*NHEADS + h) * 4096;
#pragma unroll
        for (int i = 0; i < 4; i++)
            *(float4*)&g_S[base + (p0 + i)*64 + n0] =
                make_float4(acc[i][0], acc[i][1], acc[i][2], acc[i][3]);
    }
}

// ---------------- inter-chunk scan ----------------
__global__ void k_cscan()
{
    int b = blockIdx.x >> 6;
    int h = blockIdx.x & 63;
    int tid = threadIdx.x;
    float s[16];
#pragma unroll
    for (int i = 0; i < 16; i++) s[i] = 0.f;
    for (int c = 0; c < NCHUNK; c++) {
        size_t base = (size_t)((b*NCHUNK + c)*NHEADS + h) * 4096 + tid*16;
        float cd = g_cd[(b*NCHUNK + c)*NHEADS + h];
        float4 t0 = *(const float4*)&g_S[base + 0];
        float4 t1 = *(const float4*)&g_S[base + 4];
        float4 t2 = *(const float4*)&g_S[base + 8];
        float4 t3 = *(const float4*)&g_S[base + 12];
        *(float4*)&g_S[base + 0]  = make_float4(s[0],  s[1],  s[2],  s[3]);
        *(float4*)&g_S[base + 4]  = make_float4(s[4],  s[5],  s[6],  s[7]);
        *(float4*)&g_S[base + 8]  = make_float4(s[8],  s[9],  s[10], s[11]);
        *(float4*)&g_S[base + 12] = make_float4(s[12], s[13], s[14], s[15]);
        s[0]  = fmaf(cd, s[0],  t0.x); s[1]  = fmaf(cd, s[1],  t0.y);
        s[2]  = fmaf(cd, s[2],  t0.z); s[3]  = fmaf(cd, s[3],  t0.w);
        s[4]  = fmaf(cd, s[4],  t1.x); s[5]  = fmaf(cd, s[5],  t1.y);
        s[6]  = fmaf(cd, s[6],  t1.z); s[7]  = fmaf(cd, s[7],  t1.w);
        s[8]  = fmaf(cd, s[8],  t2.x); s[9]  = fmaf(cd, s[9],  t2.y);
        s[10] = fmaf(cd, s[10], t2.z); s[11] = fmaf(cd, s[11], t2.w);
        s[12] = fmaf(cd, s[12], t3.x); s[13] = fmaf(cd, s[13], t3.y);
        s[14] = fmaf(cd, s[14], t3.z); s[15] = fmaf(cd, s[15], t3.w);
    }
}

// ---------------- Y_off + D skip + z gating ----------------
__launch_bounds__(256)
__global__ void k_off(const float* __restrict__ Dp)
{
    __shared__ float sST[64*68];
    __shared__ float sCT[64*68];
    const int h = blockIdx.x, c = blockIdx.y, b = blockIdx.z;
    const int tid = threadIdx.x;
    size_t sbase = (size_t)((b*NCHUNK + c)*NHEADS + h) * 4096;
#pragma unroll
    for (int it = 0; it < 4; it++) {
        int idx = tid + it*256;
        int r = idx >> 4;
        int n4 = (idx & 15) << 2;
        float4 sv = *(const float4*)&g_S[sbase + r*64 + n4];
        sST[(n4+0)*68 + r] = sv.x; sST[(n4+1)*68 + r] = sv.y;
        sST[(n4+2)*68 + r] = sv.z; sST[(n4+3)*68 + r] = sv.w;
        int row_g = b*SEQ + c*64 + r;
        float4 cv = *(const float4*)&g_Cv[row_g*64 + n4];
        sCT[(n4+0)*68 + r] = cv.x; sCT[(n4+1)*68 + r] = cv.y;
        sCT[(n4+2)*68 + r] = cv.z; sCT[(n4+3)*68 + r] = cv.w;
    }
    __syncthreads();
    const int ti = tid >> 4, tj = tid & 15;
    const int l0 = ti*4, p0 = tj*4;
    float acc[4][4];
#pragma unroll
    for (int i = 0; i < 4; i++)
#pragma unroll
        for (int j = 0; j < 4; j++) acc[i][j] = 0.f;
#pragma unroll
    for (int n = 0; n < 64; n++) {
        float4 cl = *(const float4*)&sCT[n*68 + l0];
        float4 sp = *(const float4*)&sST[n*68 + p0];
        float clv[4] = {cl.x, cl.y, cl.z, cl.w};
        float spv[4] = {sp.x, sp.y, sp.z, sp.w};
#pragma unroll
        for (int i = 0; i < 4; i++)
#pragma unroll
            for (int j = 0; j < 4; j++)
                acc[i][j] = fmaf(clv[i], spv[j], acc[i][j]);
    }
    float Dh = Dp[h];
#pragma unroll
    for (int i = 0; i < 4; i++) {
        int l = l0 + i;
        int row_g = b*SEQ + c*64 + l;
        float e = g_eA[((b*NCHUNK + c)*NHEADS + h)*64 + l];
        const float* pr = g_P + (size_t)row_g*NPROJ;
        float4 xc = *(const float4*)&pr[OFF_XC + h*64 + p0];
        float4 zz = *(const float4*)&pr[OFF_Z  + h*64 + p0];
        float* yp = &g_Y[(size_t)row_g*D_INNER + h*64 + p0];
        float4 yd = *(const float4*)yp;
        float4 o;
        o.x = (yd.x + e*acc[i][0] + Dh*siluf(xc.x)) * siluf(zz.x);
        o.y = (yd.y + e*acc[i][1] + Dh*siluf(xc.y)) * siluf(zz.y);
        o.z = (yd.z + e*acc[i][2] + Dh*siluf(xc.z)) * siluf(zz.z);
        o.w = (yd.w + e*acc[i][3] + Dh*siluf(xc.w)) * siluf(zz.w);
        *(float4*)yp = o;
    }
}

// ---------------- rmsnorm -> fp8 3-term ----------------
__global__ void k_rms()
{
    int row = blockIdx.x;
    int tid = threadIdx.x;
    const float* Yp = g_Y + (size_t)row * D_INNER;
    float4 v[4];
    float ss = 0.f;
#pragma unroll
    for (int i = 0; i < 4; i++) {
        v[i] = *(const float4*)&Yp[tid*16 + i*4];
        ss += v[i].x*v[i].x + v[i].y*v[i].y + v[i].z*v[i].z + v[i].w*v[i].w;
    }
#pragma unroll
    for (int o = 16; o; o >>= 1) ss += __shfl_xor_sync(0xffffffffu, ss, o);
    __shared__ float red[8];
    if ((tid & 31) == 0) red[tid >> 5] = ss;
    __syncthreads();
    float tot = 0.f;
#pragma unroll
    for (int i = 0; i < 8; i++) tot += red[i];
    float r = rsqrtf(tot * (1.f/4096.f) + RMS_EPS);
    size_t base = (size_t)row * D_INNER + tid*16;
#pragma unroll
    for (int i = 0; i < 4; i++) {
        float vv[4] = {v[i].x*r, v[i].y*r, v[i].z*r, v[i].w*r};
#pragma unroll
        for (int k = 0; k < 4; k++)
            fp8_split3(vv[k], g_Yq0[base + i*4 + k], g_Yq1[base + i*4 + k], g_Yq2[base + i*4 + k]);
    }
}

// ---------------- launcher ----------------
extern "C" void kernel_launch(void* const* d_in, const int* in_sizes, int n_in,
                              void* d_out, int out_size)
{
    const float* x    = (const float*)d_in[0];
    const float* Win  = (const float*)d_in[1];
    const float* Wth  = (const float*)d_in[2];
    const float* Wla  = (const float*)d_in[3];
    const float* Wout = (const float*)d_in[4];
    const float* Bb   = (const float*)d_in[5];
    const float* Cb   = (const float*)d_in[6];
    const float* Alog = (const float*)d_in[7];
    const float* Dp   = (const float*)d_in[8];
    const float* dtb  = (const float*)d_in[9];
    float* out = (float*)d_out;

    fp8 *pWq0, *pWq5, *pWq9, *pWo0, *pWo5, *pWo9;
    fp8 *pxq0, *pxq1, *pxq2, *pYq0, *pYq1, *pYq2;
    __nv_bfloat16 *pWqb, *pxh, *pxl;
    float *pWs8, *pWos, *pWsb, *pP;
    cudaGetSymbolAddress((void**)&pWq0, g_Wq0);
    cudaGetSymbolAddress((void**)&pWq5, g_Wq5);
    cudaGetSymbolAddress((void**)&pWq9, g_Wq9);
    cudaGetSymbolAddress((void**)&pWs8, g_Ws8);
    cudaGetSymbolAddress((void**)&pWo0, g_Wo0);
    cudaGetSymbolAddress((void**)&pWo5, g_Wo5);
    cudaGetSymbolAddress((void**)&pWo9, g_Wo9);
    cudaGetSymbolAddress((void**)&pWos, g_Wos);
    cudaGetSymbolAddress((void**)&pWqb, g_Wqb);
    cudaGetSymbolAddress((void**)&pWsb, g_Wsb);
    cudaGetSymbolAddress((void**)&pxh,  g_xh);
    cudaGetSymbolAddress((void**)&pxl,  g_xl);
    cudaGetSymbolAddress((void**)&pxq0, g_xq0);
    cudaGetSymbolAddress((void**)&pxq1, g_xq1);
    cudaGetSymbolAddress((void**)&pxq2, g_xq2);
    cudaGetSymbolAddress((void**)&pYq0, g_Yq0);
    cudaGetSymbolAddress((void**)&pYq1, g_Yq1);
    cudaGetSymbolAddress((void**)&pYq2, g_Yq2);
    cudaGetSymbolAddress((void**)&pP,   g_P);

    const int smemB  = (SS_OFF * 2) + 16 * 132 * 4;        // bf16 kernel
    const int smem8a = SS8_OFF + 16 * 132 * 4;             // fp8, NG=16
    const int smem8b = SS8_OFF + 32 * 132 * 4;             // fp8, NG=32

    cudaFuncSetAttribute(k_chunk,    cudaFuncAttributeMaxDynamicSharedMemorySize, SM_CHUNK_BYTES);
    cudaFuncSetAttribute(k_mmq,      cudaFuncAttributeMaxDynamicSharedMemorySize, smemB);
    cudaFuncSetAttribute(k_mmq8<16>, cudaFuncAttributeMaxDynamicSharedMemorySize, smem8a);
    cudaFuncSetAttribute(k_mmq8<32>, cudaFuncAttributeMaxDynamicSharedMemorySize, smem8b);

    // dequant: fp8 3-copy for z+xc rows (0..8191) and out-proj
    k_dequant8<<<(8192*16 + 3)/4, 128>>>(Win, pWq0, pWq5, pWq9, pWs8, 8192*16);
    k_dequant8<<<(65536 + 3)/4,   128>>>(Wout, pWo0, pWo5, pWo9, pWos, 65536);
    // bf16 q for sensitive rows: Win rows 8192..8383 (B,C,dt) + theta + lambda
    k_dequantb<<<(192*16 + 3)/4, 128>>>(Win + (size_t)8192*DIMK, pWqb, pWsb, 192*16);
    k_dequantb<<<(512 + 3)/4,    128>>>(Wth, pWqb + (size_t)192*DIMK, pWsb + 192*16, 512);
    k_dequantb<<<(1024 + 3)/4,   128>>>(Wla, pWqb + (size_t)224*DIMK, pWsb + 224*16, 1024);

    // split activations (bf16 hi/lo + fp8 3-term)
    k_split<<<ROWS*DIMK/1024, 256>>>(x, pxh, pxl, pxq0, pxq1, pxq2);

    // in-projection: z+xc (8192 cols) via fp8, sensitive 288 cols via bf16
    k_mmq8<16><<<dim3(ROWS/128, 64), 256, smem8a>>>(
        pxq0, pxq1, pxq2, pWq0, pWq5, pWq9, pWs8, pP, NPROJ, 8192, DIMK);
    k_mmq<<<dim3(ROWS/128, 3), 256, smemB>>>(
        pxh, pxl, pWqb, pWsb, pP + 8192, NPROJ, 288, DIMK);

    k_point<<<ROWS, 64>>>(Bb, Cb, Alog, dtb);
    k_scan <<<64, 256>>>();
    k_rope <<<ROWS, 32>>>();

    k_chunk<<<dim3(NHEADS, NCHUNK, BATCH), 256, SM_CHUNK_BYTES>>>();
    k_cscan<<<128, 256>>>();
    k_off  <<<dim3(NHEADS, NCHUNK, BATCH), 256>>>(Dp);

    k_rms<<<ROWS, 256>>>();

    // out-projection via fp8
    k_mmq8<32><<<dim3(ROWS/128, DIMK/128), 256, smem8b>>>(
        pYq0, pYq1, pYq2, pWo0, pWo5, pWo9, pWos, out, DIMK, DIMK, D_INNER);
}

// round 6
// speedup vs baseline: 1.3453x; 1.3453x over previous
#include <cuda_runtime.h>
#include <cuda_bf16.h>
#include <math.h>
#include <stdint.h>

#define SEQ     4096
#define BATCH   2
#define ROWS    (BATCH*SEQ)     // 8192
#define DIMK    2048
#define D_INNER 4096
#define NHEADS  64
#define NPROJ   8480            // 8384 (in_proj) + 32 (theta) + 64 (lambda)
#define NPROJ_PAD 8576          // 67 * 128
#define OFF_Z   0
#define OFF_XC  4096
#define OFF_B   8192
#define OFF_C   8256
#define OFF_DT  8320
#define OFF_TH  8384
#define OFF_LAM 8416
#define NCHUNK  64
#define RMS_EPS 1.1920929e-07f

// ---------------- device scratch (no allocation allowed) ----------------
__device__ __nv_bfloat16 g_Wq [NPROJ_PAD * DIMK];   // fused in-proj q (4-bit ints, exact in bf16)
__device__ float         g_Ws [NPROJ_PAD * 16];     // per-group scales (16 groups of 128 per row)
__device__ __nv_bfloat16 g_Woq[DIMK * D_INNER];     // out-proj q
__device__ float         g_Wos[DIMK * 32];          // out-proj scales (32 groups per row)
__device__ __nv_bfloat16 g_xh [ROWS * DIMK];
__device__ __nv_bfloat16 g_xl [ROWS * DIMK];
__device__ __nv_bfloat16 g_Yh [ROWS * D_INNER];
__device__ __nv_bfloat16 g_Yl [ROWS * D_INNER];
__device__ float g_P [ROWS * NPROJ];                // projection output
__device__ float g_Bv[ROWS * 64];
__device__ float g_Cv[ROWS * 64];
__device__ float g_Ad[ROWS * 64];
__device__ float g_ga[ROWS * 64];
__device__ float g_be[ROWS * 64];
__device__ float g_td[ROWS * 32];
__device__ float g_Y [ROWS * D_INNER];
__device__ float g_S [BATCH * NCHUNK * NHEADS * 64 * 64];
__device__ float g_eA[BATCH * NCHUNK * NHEADS * 64];
__device__ float g_cd[BATCH * NCHUNK * NHEADS];

__device__ __forceinline__ float siluf(float x) { return x / (1.f + expf(-x)); }

__device__ __forceinline__ uint32_t s2u(const void* p) {
    uint32_t a;
    asm("{ .reg .u64 t; cvta.to.shared.u64 t, %1; cvt.u32.u64 %0, t; }" : "=r"(a) : "l"(p));
    return a;
}

// ================= quant-aware emulated-fp32 GEMM via mma.sync =================
// C[M,Nw] = A[M,K] * B[N,K]^T where B = q * scale(group of 128 along K).
// A pre-split into bf16 hi/lo (2 MMA terms), q exact in bf16, scale folded in fp32
// at each 128-K group boundary.
// CTA 128x128, 8 warps (2x4) of 64x32 warp tiles, K-chunk 32, cp.async double buffer.
#define PADH 40                      // 32 halves + 8 pad
#define ARR_H (128*PADH)             // 5120 halves per sub-tile
#define BUF_H (3*ARR_H)              // Ah, Al, Bq
#define SS_OFF (2*BUF_H)             // halves offset where fp32 scales start

__device__ __forceinline__ void cpasync16(uint32_t dst, const void* src) {
    asm volatile("cp.async.cg.shared.global [%0], [%1], 16;" :: "r"(dst), "l"(src));
}
#define CP_COMMIT() asm volatile("cp.async.commit_group;" ::: "memory")
#define CP_WAIT1()  asm volatile("cp.async.wait_group 1;" ::: "memory")

#define LDSM4(r0,r1,r2,r3,a) \
    asm volatile("ldmatrix.sync.aligned.m8n8.x4.shared.b16 {%0,%1,%2,%3}, [%4];" \
        : "=r"(r0),"=r"(r1),"=r"(r2),"=r"(r3) : "r"(a))

#define MMA16816(d,a,b0,b1) \
    asm volatile("mma.sync.aligned.m16n8k16.row.col.f32.bf16.bf16.f32 " \
        "{%0,%1,%2,%3}, {%4,%5,%6,%7}, {%8,%9}, {%0,%1,%2,%3};" \
        : "+f"((d)[0]),"+f"((d)[1]),"+f"((d)[2]),"+f"((d)[3]) \
        : "r"((a)[0]),"r"((a)[1]),"r"((a)[2]),"r"((a)[3]),"r"(b0),"r"(b1))

template<int NG>
__global__ void __launch_bounds__(256, 1)
k_mmq(const __nv_bfloat16* __restrict__ Ah, const __nv_bfloat16* __restrict__ Al,
      const __nv_bfloat16* __restrict__ Bq, const float* __restrict__ Bs,
      float* __restrict__ C, int Nw, int Nlim, int K)
{
    extern __shared__ __nv_bfloat16 sh[];
    float* ss = (float*)(sh + SS_OFF);        // [NG][132] scales for this CTA's n-range
    const uint32_t sb = s2u(sh);
    const int tid  = threadIdx.x;
    const int lane = tid & 31;
    const int wid  = tid >> 5;
    const int m0 = blockIdx.x * 128;
    const int n0 = blockIdx.y * 128;
    const int mw = (wid >> 2) * 64;
    const int nw = (wid & 3) * 32;

    // preload scales for the CTA's 128 weight rows
    for (int idx = tid; idx < 128 * NG; idx += 256) {
        int g = idx >> 7, nl = idx & 127;
        ss[g * 132 + nl] = Bs[(size_t)(n0 + nl) * NG + g];
    }

    float acc[4][4][4];
#pragma unroll
    for (int i = 0; i < 4; i++)
#pragma unroll
        for (int j = 0; j < 4; j++)
#pragma unroll
            for (int k = 0; k < 4; k++) acc[i][j][k] = 0.f;

    const int NK = K >> 5;

#define FILLQ(buf, kc) do {                                                      \
        int kb = (kc) * 32;                                                      \
_Pragma("unroll")                                                                \
        for (int i = 0; i < 6; i++) {                                            \
            int idx = i * 256 + tid;                                             \
            int arr = idx >> 9;                                                  \
            int r   = (idx >> 2) & 127;                                          \
            int c   = idx & 3;                                                   \
            const __nv_bfloat16* sp = (arr == 0) ? (Ah + (size_t)(m0 + r) * K)   \
                                    : (arr == 1) ? (Al + (size_t)(m0 + r) * K)   \
                                                 : (Bq + (size_t)(n0 + r) * K);  \
            uint32_t dp = sb + ((buf) * BUF_H + arr * ARR_H + r * PADH + c * 8) * 2; \
            cpasync16(dp, sp + kb + c * 8);                                      \
        }                                                                        \
    } while (0)

    FILLQ(0, 0);
    CP_COMMIT();

    const int rowoff = (lane & 7) + ((lane >> 3) & 1) * 8;
    const int coloff = (lane >> 4) * 8;
    const int c0 = (lane & 3) * 2;

    for (int g = 0; g < NG; g++) {
        float accg[4][4][4];
#pragma unroll
        for (int i = 0; i < 4; i++)
#pragma unroll
            for (int j = 0; j < 4; j++)
#pragma unroll
                for (int k = 0; k < 4; k++) accg[i][j][k] = 0.f;

#pragma unroll
        for (int kq = 0; kq < 4; kq++) {
            const int kc = g * 4 + kq;
            const int buf = kc & 1;
            if (kc + 1 < NK) FILLQ(buf ^ 1, kc + 1);
            CP_COMMIT();
            CP_WAIT1();
            __syncthreads();

#pragma unroll
            for (int kk = 0; kk < 2; kk++) {
                uint32_t afr[2][4][4];
                uint32_t bfr[2][4];
#pragma unroll
                for (int hl = 0; hl < 2; hl++)
#pragma unroll
                    for (int mi = 0; mi < 4; mi++) {
                        uint32_t a = sb + (buf * BUF_H + hl * ARR_H +
                            (mw + mi * 16 + rowoff) * PADH + kk * 16 + coloff) * 2;
                        LDSM4(afr[hl][mi][0], afr[hl][mi][1], afr[hl][mi][2], afr[hl][mi][3], a);
                    }
#pragma unroll
                for (int nj = 0; nj < 2; nj++) {
                    uint32_t a = sb + (buf * BUF_H + 2 * ARR_H +
                        (nw + nj * 16 + rowoff) * PADH + kk * 16 + coloff) * 2;
                    LDSM4(bfr[nj][0], bfr[nj][1], bfr[nj][2], bfr[nj][3], a);
                }
#pragma unroll
                for (int term = 0; term < 2; term++)
#pragma unroll
                    for (int mi = 0; mi < 4; mi++)
#pragma unroll
                        for (int ni = 0; ni < 4; ni++) {
                            int nj = ni >> 1, s = ni & 1;
                            MMA16816(accg[mi][ni], afr[term][mi],
                                     bfr[nj][s], bfr[nj][s + 2]);
                        }
            }
            __syncthreads();
        }

        // fold group scales (per output column n)
#pragma unroll
        for (int ni = 0; ni < 4; ni++) {
            float2 sv = *(const float2*)&ss[g * 132 + nw + ni * 8 + c0];
#pragma unroll
            for (int mi = 0; mi < 4; mi++) {
                acc[mi][ni][0] = fmaf(sv.x, accg[mi][ni][0], acc[mi][ni][0]);
                acc[mi][ni][1] = fmaf(sv.y, accg[mi][ni][1], acc[mi][ni][1]);
                acc[mi][ni][2] = fmaf(sv.x, accg[mi][ni][2], acc[mi][ni][2]);
                acc[mi][ni][3] = fmaf(sv.y, accg[mi][ni][3], acc[mi][ni][3]);
            }
        }
    }

    // epilogue
    const int r0 = lane >> 2;
#pragma unroll
    for (int mi = 0; mi < 4; mi++) {
#pragma unroll
        for (int ni = 0; ni < 4; ni++) {
            int m = m0 + mw + mi * 16 + r0;
            int n = n0 + nw + ni * 8 + c0;
            if (n < Nlim) {
                *(float2*)&C[(size_t)m * Nw + n]       = make_float2(acc[mi][ni][0], acc[mi][ni][1]);
                *(float2*)&C[(size_t)(m + 8) * Nw + n] = make_float2(acc[mi][ni][2], acc[mi][ni][3]);
            }
        }
    }
#undef FILLQ
}

// ---------------- fq4 dequantization -> q (bf16, exact) + group scale ----------------
__global__ void k_dequantq(const float* __restrict__ src, __nv_bfloat16* __restrict__ dq,
                           float* __restrict__ ds, int ngroups)
{
    int g = blockIdx.x * 4 + (threadIdx.x >> 5);
    if (g >= ngroups) return;
    int lane = threadIdx.x & 31;
    const float* s = src + (size_t)g * 128;
    float v[4];
    float m = 0.f;
#pragma unroll
    for (int i = 0; i < 4; i++) { v[i] = s[lane + 32*i]; m = fmaxf(m, fabsf(v[i])); }
#pragma unroll
    for (int o = 16; o; o >>= 1) m = fmaxf(m, __shfl_xor_sync(0xffffffffu, m, o));
    float scale = fmaxf(m, 1e-10f) / 7.0f;
    if (lane == 0) ds[g] = scale;
#pragma unroll
    for (int i = 0; i < 4; i++) {
        float q = rintf(v[i] / scale);
        q = fminf(fmaxf(q, -8.f), 7.f);
        dq[(size_t)g * 128 + lane + 32*i] = __float2bfloat16(q);  // exact (small int)
    }
}

// ---------------- split fp32 -> bf16 hi/lo ----------------
__global__ void k_split(const float* __restrict__ src, __nv_bfloat16* __restrict__ dh,
                        __nv_bfloat16* __restrict__ dl)
{
    size_t i = ((size_t)blockIdx.x * 256 + threadIdx.x) * 4;
    float4 v = *(const float4*)(src + i);
    float vv[4] = {v.x, v.y, v.z, v.w};
#pragma unroll
    for (int k = 0; k < 4; k++) {
        __nv_bfloat16 h = __float2bfloat16(vv[k]);
        dh[i + k] = h;
        dl[i + k] = __float2bfloat16(vv[k] - __bfloat162float(h));
    }
}

// ---------------- pointwise epilogue per (b,l) row: 64 threads ----------------
__global__ void k_point(const float* __restrict__ Bb, const float* __restrict__ Cb,
                        const float* __restrict__ Alog, const float* __restrict__ dtb)
{
    int row = blockIdx.x;
    int t = threadIdx.x;
    const float* pr = g_P + (size_t)row * NPROJ;
    __shared__ float red[6];

    float dtr = pr[OFF_DT + t] + dtb[t];
    float dt = (dtr > 20.f) ? dtr : log1pf(expf(dtr));
    float Ad = -expf(Alog[t]) * dt;
    float lam = 1.f / (1.f + expf(-pr[OFF_LAM + t]));
    g_Ad[row*64 + t] = Ad;
    g_ga[row*64 + t] = lam * dt;
    g_be[row*64 + t] = (1.f - lam) * dt * expf(Ad);

    float bv = pr[OFF_B + t];
    float cv = pr[OFF_C + t];

    float s0 = dt, s1 = bv*bv, s2 = cv*cv;
#pragma unroll
    for (int o = 16; o; o >>= 1) {
        s0 += __shfl_xor_sync(0xffffffffu, s0, o);
        s1 += __shfl_xor_sync(0xffffffffu, s1, o);
        s2 += __shfl_xor_sync(0xffffffffu, s2, o);
    }
    int w = t >> 5;
    if ((t & 31) == 0) { red[w*3+0] = s0; red[w*3+1] = s1; red[w*3+2] = s2; }
    __syncthreads();
    float dt_avg = (red[0] + red[3]) * (1.f/64.f);
    float rb = rsqrtf((red[1] + red[4]) * (1.f/64.f) + RMS_EPS);
    float rc = rsqrtf((red[2] + red[5]) * (1.f/64.f) + RMS_EPS);

    g_Bv[row*64 + t] = bv * rb + Bb[t];
    g_Cv[row*64 + t] = cv * rc + Cb[t];
    if (t < 32) g_td[row*32 + t] = pr[OFF_TH + t] * dt_avg;
}

// ---------------- cumsum of theta*dt_avg over L per (b, n) ----------------
__global__ void k_scan()
{
    int b = blockIdx.x >> 5;
    int n = blockIdx.x & 31;
    int tid = threadIdx.x;
    __shared__ float ps[256];
    float loc[16];
    float run = 0.f;
    int base = (b*SEQ + tid*16) * 32 + n;
#pragma unroll
    for (int j = 0; j < 16; j++) { run += g_td[base + j*32]; loc[j] = run; }
    ps[tid] = run;
    __syncthreads();
#pragma unroll
    for (int o = 1; o < 256; o <<= 1) {
        float v = (tid >= o) ? ps[tid - o] : 0.f;
        __syncthreads();
        ps[tid] += v;
        __syncthreads();
    }
    float off = (tid > 0) ? ps[tid - 1] : 0.f;
#pragma unroll
    for (int j = 0; j < 16; j++) g_td[base + j*32] = loc[j] + off;
}

// ---------------- rope on B and C (in place) ----------------
__global__ void k_rope()
{
    int row = blockIdx.x;
    int t = threadIdx.x;
    float a = g_td[row*32 + t];
    float ca = cosf(a), sa = sinf(a);
    float br = g_Bv[row*64 + t], bi = g_Bv[row*64 + 32 + t];
    g_Bv[row*64 + t]      = br*ca - bi*sa;
    g_Bv[row*64 + 32 + t] = br*sa + bi*ca;
    float cr = g_Cv[row*64 + t], ci = g_Cv[row*64 + 32 + t];
    g_Cv[row*64 + t]      = cr*ca - ci*sa;
    g_Cv[row*64 + 32 + t] = cr*sa + ci*ca;
}

// ---------------- intra-chunk: Y_diag + per-chunk states ----------------
#define SM_CHUNK_BYTES ((4352*5 + 128) * 4)
__launch_bounds__(256)
__global__ void k_chunk()
{
    extern __shared__ float sm[];
    float* sX  = sm;
    float* sB  = sm + 4352;
    float* sBT = sm + 8704;
    float* sCT = sm + 13056;
    float* sGT = sm + 17408;
    float* sA  = sm + 21760;
    float* sW  = sm + 21824;

    const int h = blockIdx.x, c = blockIdx.y, b = blockIdx.z;
    const int tid = threadIdx.x;

    if (tid < 64) {
        int row_g = b*SEQ + c*64 + tid;
        sA[tid] = g_Ad[row_g*64 + h];
    }
    __syncthreads();
#pragma unroll
    for (int o = 1; o < 64; o <<= 1) {
        float v = (tid < 64 && tid >= o) ? sA[tid - o] : 0.f;
        __syncthreads();
        if (tid < 64) sA[tid] += v;
        __syncthreads();
    }
    float Alast = sA[63];
    if (tid < 64) {
        sW[tid] = expf(Alast - sA[tid]);
        g_eA[((b*NCHUNK + c)*NHEADS + h)*64 + tid] = expf(sA[tid]);
    }
    if (tid == 0) g_cd[(b*NCHUNK + c)*NHEADS + h] = expf(Alast);

#pragma unroll
    for (int it = 0; it < 4; it++) {
        int idx = tid + it*256;
        int l = idx >> 4;
        int p4 = (idx & 15) << 2;
        int row_g = b*SEQ + c*64 + l;
        const float* xp = g_P + (size_t)row_g*NPROJ + OFF_XC + h*64 + p4;
        float4 xc = *(const float4*)xp;
        float ga = g_ga[row_g*64 + h];
        float be = g_be[row_g*64 + h];
        float4 xv;
        xv.x = siluf(xc.x)*ga; xv.y = siluf(xc.y)*ga; xv.z = siluf(xc.z)*ga; xv.w = siluf(xc.w)*ga;
        if (c*64 + l > 0) {
            float4 xq = *(const float4*)(xp - NPROJ);
            xv.x += siluf(xq.x)*be; xv.y += siluf(xq.y)*be; xv.z += siluf(xq.z)*be; xv.w += siluf(xq.w)*be;
        }
        *(float4*)&sX[l*68 + p4] = xv;
        float4 bb = *(const float4*)&g_Bv[row_g*64 + p4];
        *(float4*)&sB[l*68 + p4] = bb;
        sBT[(p4+0)*68 + l] = bb.x; sBT[(p4+1)*68 + l] = bb.y;
        sBT[(p4+2)*68 + l] = bb.z; sBT[(p4+3)*68 + l] = bb.w;
        float4 cc = *(const float4*)&g_Cv[row_g*64 + p4];
        sCT[(p4+0)*68 + l] = cc.x; sCT[(p4+1)*68 + l] = cc.y;
        sCT[(p4+2)*68 + l] = cc.z; sCT[(p4+3)*68 + l] = cc.w;
    }
    __syncthreads();

    const int ti = tid >> 4, tj = tid & 15;

    {
        const int l0 = ti*4, s0 = tj*4;
        float acc[4][4];
#pragma unroll
        for (int i = 0; i < 4; i++)
#pragma unroll
            for (int j = 0; j < 4; j++) acc[i][j] = 0.f;
#pragma unroll
        for (int n = 0; n < 64; n++) {
            float4 cl = *(const float4*)&sCT[n*68 + l0];
            float4 bs = *(const float4*)&sBT[n*68 + s0];
            float clv[4] = {cl.x, cl.y, cl.z, cl.w};
            float bsv[4] = {bs.x, bs.y, bs.z, bs.w};
#pragma unroll
            for (int i = 0; i < 4; i++)
#pragma unroll
                for (int j = 0; j < 4; j++)
                    acc[i][j] = fmaf(clv[i], bsv[j], acc[i][j]);
        }
        float al[4];
#pragma unroll
        for (int i = 0; i < 4; i++) al[i] = sA[l0 + i];
#pragma unroll
        for (int j = 0; j < 4; j++) {
            int s = s0 + j;
            float as = sA[s];
#pragma unroll
            for (int i = 0; i < 4; i++) {
                int l = l0 + i;
                sGT[s*68 + l] = (s <= l) ? acc[i][j] * expf(al[i] - as) : 0.f;
            }
        }
    }
    __syncthreads();

    {
        const int l0 = ti*4, p0 = tj*4;
        float acc[4][4];
#pragma unroll
        for (int i = 0; i < 4; i++)
#pragma unroll
            for (int j = 0; j < 4; j++) acc[i][j] = 0.f;
        // G is lower-triangular: contributions vanish for s > l0+3
        const int smax = l0 + 4;
#pragma unroll 4
        for (int s = 0; s < smax; s++) {
            float4 gt = *(const float4*)&sGT[s*68 + l0];
            float4 xr = *(const float4*)&sX[s*68 + p0];
            float gv[4] = {gt.x, gt.y, gt.z, gt.w};
            float xvv[4] = {xr.x, xr.y, xr.z, xr.w};
#pragma unroll
            for (int i = 0; i < 4; i++)
#pragma unroll
                for (int j = 0; j < 4; j++)
                    acc[i][j] = fmaf(gv[i], xvv[j], acc[i][j]);
        }
#pragma unroll
        for (int i = 0; i < 4; i++) {
            int row_g = b*SEQ + c*64 + l0 + i;
            *(float4*)&g_Y[(size_t)row_g*D_INNER + h*64 + p0] =
                make_float4(acc[i][0], acc[i][1], acc[i][2], acc[i][3]);
        }
    }

    {
        const int p0 = ti*4, n0 = tj*4;
        float acc[4][4];
#pragma unroll
        for (int i = 0; i < 4; i++)
#pragma unroll
            for (int j = 0; j < 4; j++) acc[i][j] = 0.f;
#pragma unroll
        for (int l = 0; l < 64; l++) {
            float w = sW[l];
            float4 xr = *(const float4*)&sX[l*68 + p0];
            float4 br = *(const float4*)&sB[l*68 + n0];
            float wx[4] = {w*xr.x, w*xr.y, w*xr.z, w*xr.w};
            float bvv[4] = {br.x, br.y, br.z, br.w};
#pragma unroll
            for (int i = 0; i < 4; i++)
#pragma unroll
                for (int j = 0; j < 4; j++)
                    acc[i][j] = fmaf(wx[i], bvv[j], acc[i][j]);
        }
        size_t base = (size_t)((b*NCHUNK + c)*NHEADS + h) * 4096;
#pragma unroll
        for (int i = 0; i < 4; i++)
            *(float4*)&g_S[base + (p0 + i)*64 + n0] =
                make_float4(acc[i][0], acc[i][1], acc[i][2], acc[i][3]);
    }
}

// ---------------- inter-chunk scan: 512 CTAs, one (b,h,quarter) each ----------------
__global__ void k_cscan()
{
    int q = blockIdx.x & 3;
    int h = (blockIdx.x >> 2) & 63;
    int b = blockIdx.x >> 8;
    int tid = threadIdx.x;
    int off = q * 1024 + tid * 4;
    float s0 = 0.f, s1 = 0.f, s2 = 0.f, s3 = 0.f;
    const float* cdp = g_cd + b * NCHUNK * NHEADS + h;
    for (int c = 0; c < NCHUNK; c++) {
        size_t base = ((size_t)((b*NCHUNK + c)*NHEADS + h) << 12) + off;
        float cd = cdp[c * NHEADS];
        float4 t = *(const float4*)&g_S[base];
        *(float4*)&g_S[base] = make_float4(s0, s1, s2, s3);
        s0 = fmaf(cd, s0, t.x);
        s1 = fmaf(cd, s1, t.y);
        s2 = fmaf(cd, s2, t.z);
        s3 = fmaf(cd, s3, t.w);
    }
}

// ---------------- Y_off + D skip + z gating ----------------
__launch_bounds__(256)
__global__ void k_off(const float* __restrict__ Dp)
{
    __shared__ float sST[64*68];
    __shared__ float sCT[64*68];
    const int h = blockIdx.x, c = blockIdx.y, b = blockIdx.z;
    const int tid = threadIdx.x;
    size_t sbase = (size_t)((b*NCHUNK + c)*NHEADS + h) * 4096;
#pragma unroll
    for (int it = 0; it < 4; it++) {
        int idx = tid + it*256;
        int r = idx >> 4;
        int n4 = (idx & 15) << 2;
        float4 sv = *(const float4*)&g_S[sbase + r*64 + n4];
        sST[(n4+0)*68 + r] = sv.x; sST[(n4+1)*68 + r] = sv.y;
        sST[(n4+2)*68 + r] = sv.z; sST[(n4+3)*68 + r] = sv.w;
        int row_g = b*SEQ + c*64 + r;
        float4 cv = *(const float4*)&g_Cv[row_g*64 + n4];
        sCT[(n4+0)*68 + r] = cv.x; sCT[(n4+1)*68 + r] = cv.y;
        sCT[(n4+2)*68 + r] = cv.z; sCT[(n4+3)*68 + r] = cv.w;
    }
    __syncthreads();
    const int ti = tid >> 4, tj = tid & 15;
    const int l0 = ti*4, p0 = tj*4;
    float acc[4][4];
#pragma unroll
    for (int i = 0; i < 4; i++)
#pragma unroll
        for (int j = 0; j < 4; j++) acc[i][j] = 0.f;
#pragma unroll
    for (int n = 0; n < 64; n++) {
        float4 cl = *(const float4*)&sCT[n*68 + l0];
        float4 sp = *(const float4*)&sST[n*68 + p0];
        float clv[4] = {cl.x, cl.y, cl.z, cl.w};
        float spv[4] = {sp.x, sp.y, sp.z, sp.w};
#pragma unroll
        for (int i = 0; i < 4; i++)
#pragma unroll
            for (int j = 0; j < 4; j++)
                acc[i][j] = fmaf(clv[i], spv[j], acc[i][j]);
    }
    float Dh = Dp[h];
#pragma unroll
    for (int i = 0; i < 4; i++) {
        int l = l0 + i;
        int row_g = b*SEQ + c*64 + l;
        float e = g_eA[((b*NCHUNK + c)*NHEADS + h)*64 + l];
        const float* pr = g_P + (size_t)row_g*NPROJ;
        float4 xc = *(const float4*)&pr[OFF_XC + h*64 + p0];
        float4 zz = *(const float4*)&pr[OFF_Z  + h*64 + p0];
        float* yp = &g_Y[(size_t)row_g*D_INNER + h*64 + p0];
        float4 yd = *(const float4*)yp;
        float4 o;
        o.x = (yd.x + e*acc[i][0] + Dh*siluf(xc.x)) * siluf(zz.x);
        o.y = (yd.y + e*acc[i][1] + Dh*siluf(xc.y)) * siluf(zz.y);
        o.z = (yd.z + e*acc[i][2] + Dh*siluf(xc.z)) * siluf(zz.z);
        o.w = (yd.w + e*acc[i][3] + Dh*siluf(xc.w)) * siluf(zz.w);
        *(float4*)yp = o;
    }
}

// ---------------- rmsnorm over 4096 per row -> bf16 hi/lo ----------------
__global__ void k_rms()
{
    int row = blockIdx.x;
    int tid = threadIdx.x;
    const float* Yp = g_Y + (size_t)row * D_INNER;
    float4 v[4];
    float ss = 0.f;
#pragma unroll
    for (int i = 0; i < 4; i++) {
        v[i] = *(const float4*)&Yp[tid*16 + i*4];
        ss += v[i].x*v[i].x + v[i].y*v[i].y + v[i].z*v[i].z + v[i].w*v[i].w;
    }
#pragma unroll
    for (int o = 16; o; o >>= 1) ss += __shfl_xor_sync(0xffffffffu, ss, o);
    __shared__ float red[8];
    if ((tid & 31) == 0) red[tid >> 5] = ss;
    __syncthreads();
    float tot = 0.f;
#pragma unroll
    for (int i = 0; i < 8; i++) tot += red[i];
    float r = rsqrtf(tot * (1.f/4096.f) + RMS_EPS);
    size_t base = (size_t)row * D_INNER + tid*16;
#pragma unroll
    for (int i = 0; i < 4; i++) {
        float vv[4] = {v[i].x*r, v[i].y*r, v[i].z*r, v[i].w*r};
#pragma unroll
        for (int k = 0; k < 4; k++) {
            __nv_bfloat16 h = __float2bfloat16(vv[k]);
            g_Yh[base + i*4 + k] = h;
            g_Yl[base + i*4 + k] = __float2bfloat16(vv[k] - __bfloat162float(h));
        }
    }
}

// ---------------- launcher ----------------
extern "C" void kernel_launch(void* const* d_in, const int* in_sizes, int n_in,
                              void* d_out, int out_size)
{
    const float* x    = (const float*)d_in[0];
    const float* Win  = (const float*)d_in[1];
    const float* Wth  = (const float*)d_in[2];
    const float* Wla  = (const float*)d_in[3];
    const float* Wout = (const float*)d_in[4];
    const float* Bb   = (const float*)d_in[5];
    const float* Cb   = (const float*)d_in[6];
    const float* Alog = (const float*)d_in[7];
    const float* Dp   = (const float*)d_in[8];
    const float* dtb  = (const float*)d_in[9];
    float* out = (float*)d_out;

    __nv_bfloat16 *pWq, *pWoq, *pxh, *pxl, *pYh, *pYl;
    float *pWs, *pWos, *pP;
    cudaGetSymbolAddress((void**)&pWq,  g_Wq);
    cudaGetSymbolAddress((void**)&pWs,  g_Ws);
    cudaGetSymbolAddress((void**)&pWoq, g_Woq);
    cudaGetSymbolAddress((void**)&pWos, g_Wos);
    cudaGetSymbolAddress((void**)&pxh,  g_xh);
    cudaGetSymbolAddress((void**)&pxl,  g_xl);
    cudaGetSymbolAddress((void**)&pYh,  g_Yh);
    cudaGetSymbolAddress((void**)&pYl,  g_Yl);
    cudaGetSymbolAddress((void**)&pP,   g_P);

    const int smem1 = (SS_OFF * 2) + 16 * 132 * 4;
    const int smem2 = (SS_OFF * 2) + 32 * 132 * 4;

    cudaFuncSetAttribute(k_chunk,    cudaFuncAttributeMaxDynamicSharedMemorySize, SM_CHUNK_BYTES);
    cudaFuncSetAttribute(k_mmq<16>,  cudaFuncAttributeMaxDynamicSharedMemorySize, smem1);
    cudaFuncSetAttribute(k_mmq<32>,  cudaFuncAttributeMaxDynamicSharedMemorySize, smem2);

    // fq4 dequant -> q + scales into fused weight buffer (pad rows stay zero)
    k_dequantq<<<(8384*16 + 3)/4, 128>>>(Win, pWq, pWs, 8384*16);
    k_dequantq<<<(512 + 3)/4,    128>>>(Wth, pWq + (size_t)8384*DIMK, pWs + (size_t)8384*16, 512);
    k_dequantq<<<(1024 + 3)/4,   128>>>(Wla, pWq + (size_t)8416*DIMK, pWs + (size_t)8416*16, 1024);
    k_dequantq<<<65536/4,        128>>>(Wout, pWoq, pWos, 65536);

    // split activations
    k_split<<<ROWS*DIMK/1024, 256>>>(x, pxh, pxl);

    // in-projection GEMM: 8192 x 8480 x 2048 (2-term + group-scale fold)
    k_mmq<16><<<dim3(ROWS/128, NPROJ_PAD/128), 256, smem1>>>(
        pxh, pxl, pWq, pWs, pP, NPROJ, NPROJ, DIMK);

    k_point<<<ROWS, 64>>>(Bb, Cb, Alog, dtb);
    k_scan <<<64, 256>>>();
    k_rope <<<ROWS, 32>>>();

    k_chunk<<<dim3(NHEADS, NCHUNK, BATCH), 256, SM_CHUNK_BYTES>>>();
    k_cscan<<<512, 256>>>();
    k_off  <<<dim3(NHEADS, NCHUNK, BATCH), 256>>>(Dp);

    k_rms<<<ROWS, 256>>>();

    // out-projection GEMM: 8192 x 2048 x 4096 (2-term + group-scale fold)
    k_mmq<32><<<dim3(ROWS/128, DIMK/128), 256, smem2>>>(
        pYh, pYl, pWoq, pWos, out, DIMK, DIMK, D_INNER);
}

// round 7
// speedup vs baseline: 1.3709x; 1.0190x over previous
#include <cuda_runtime.h>
#include <cuda_bf16.h>
#include <math.h>
#include <stdint.h>

#define SEQ     4096
#define BATCH   2
#define ROWS    (BATCH*SEQ)     // 8192
#define DIMK    2048
#define D_INNER 4096
#define NHEADS  64
#define NPROJ   8480            // 8384 (in_proj) + 32 (theta) + 64 (lambda)
#define NPROJ_PAD 8576          // 67 * 128
#define OFF_Z   0
#define OFF_XC  4096
#define OFF_B   8192
#define OFF_C   8256
#define OFF_DT  8320
#define OFF_TH  8384
#define OFF_LAM 8416
#define NCHUNK  64
#define RMS_EPS 1.1920929e-07f

// ---------------- device scratch (no allocation allowed) ----------------
__device__ __nv_bfloat16 g_Wq [NPROJ_PAD * DIMK];   // fused in-proj q (4-bit ints, exact in bf16)
__device__ float         g_Ws [NPROJ_PAD * 16];     // per-group scales (16 groups of 128 per row)
__device__ __nv_bfloat16 g_Woq[DIMK * D_INNER];     // out-proj q
__device__ float         g_Wos[DIMK * 32];          // out-proj scales (32 groups per row)
__device__ __nv_bfloat16 g_xh [ROWS * DIMK];
__device__ __nv_bfloat16 g_xl [ROWS * DIMK];
__device__ __nv_bfloat16 g_Yh [ROWS * D_INNER];
__device__ __nv_bfloat16 g_Yl [ROWS * D_INNER];
__device__ float g_P [ROWS * NPROJ];                // projection output
__device__ float g_Bv[ROWS * 64];
__device__ float g_Cv[ROWS * 64];
__device__ float g_Ad[ROWS * 64];
__device__ float g_ga[ROWS * 64];
__device__ float g_be[ROWS * 64];
__device__ float g_td[ROWS * 32];
__device__ float g_Y [ROWS * D_INNER];
__device__ float g_S [BATCH * NCHUNK * NHEADS * 64 * 64];
__device__ float g_eA[BATCH * NCHUNK * NHEADS * 64];
__device__ float g_cd[BATCH * NCHUNK * NHEADS];

__device__ __forceinline__ float siluf(float x) { return x / (1.f + expf(-x)); }

__device__ __forceinline__ uint32_t s2u(const void* p) {
    uint32_t a;
    asm("{ .reg .u64 t; cvta.to.shared.u64 t, %1; cvt.u32.u64 %0, t; }" : "=r"(a) : "l"(p));
    return a;
}

// ================= quant-aware emulated-fp32 GEMM via mma.sync =================
// C[M,Nw] = A[M,K] * B[N,K]^T where B = q * scale(group of 128 along K).
// A pre-split into bf16 hi/lo (2 MMA terms), q exact in bf16, scale folded in fp32
// at each 128-K group boundary.
// CTA 128x128, 16 warps (4x4) of 32x32 warp tiles, K-chunk 32, cp.async double buffer.
#define PADH 40                      // 32 halves + 8 pad
#define ARR_H (128*PADH)             // 5120 halves per sub-tile
#define BUF_H (3*ARR_H)              // Ah, Al, Bq
#define SS_OFF (2*BUF_H)             // halves offset where fp32 scales start

__device__ __forceinline__ void cpasync16(uint32_t dst, const void* src) {
    asm volatile("cp.async.cg.shared.global [%0], [%1], 16;" :: "r"(dst), "l"(src));
}
#define CP_COMMIT() asm volatile("cp.async.commit_group;" ::: "memory")
#define CP_WAIT1()  asm volatile("cp.async.wait_group 1;" ::: "memory")

#define LDSM4(r0,r1,r2,r3,a) \
    asm volatile("ldmatrix.sync.aligned.m8n8.x4.shared.b16 {%0,%1,%2,%3}, [%4];" \
        : "=r"(r0),"=r"(r1),"=r"(r2),"=r"(r3) : "r"(a))

#define MMA16816(d,a,b0,b1) \
    asm volatile("mma.sync.aligned.m16n8k16.row.col.f32.bf16.bf16.f32 " \
        "{%0,%1,%2,%3}, {%4,%5,%6,%7}, {%8,%9}, {%0,%1,%2,%3};" \
        : "+f"((d)[0]),"+f"((d)[1]),"+f"((d)[2]),"+f"((d)[3]) \
        : "r"((a)[0]),"r"((a)[1]),"r"((a)[2]),"r"((a)[3]),"r"(b0),"r"(b1))

template<int NG>
__global__ void __launch_bounds__(512, 1)
k_mmq(const __nv_bfloat16* __restrict__ Ah, const __nv_bfloat16* __restrict__ Al,
      const __nv_bfloat16* __restrict__ Bq, const float* __restrict__ Bs,
      float* __restrict__ C, int Nw, int Nlim, int K)
{
    extern __shared__ __nv_bfloat16 sh[];
    float* ss = (float*)(sh + SS_OFF);        // [NG][132] scales for this CTA's n-range
    const uint32_t sb = s2u(sh);
    const int tid  = threadIdx.x;
    const int lane = tid & 31;
    const int wid  = tid >> 5;                // 0..15
    const int m0 = blockIdx.x * 128;
    const int n0 = blockIdx.y * 128;
    const int mw = (wid >> 2) * 32;           // 4 m-strips of 32
    const int nw = (wid & 3) * 32;            // 4 n-strips of 32

    // preload scales for the CTA's 128 weight rows
    for (int idx = tid; idx < 128 * NG; idx += 512) {
        int g = idx >> 7, nl = idx & 127;
        ss[g * 132 + nl] = Bs[(size_t)(n0 + nl) * NG + g];
    }

    float acc[2][4][4];
#pragma unroll
    for (int i = 0; i < 2; i++)
#pragma unroll
        for (int j = 0; j < 4; j++)
#pragma unroll
            for (int k = 0; k < 4; k++) acc[i][j][k] = 0.f;

    const int NK = K >> 5;

#define FILLQ(buf, kc) do {                                                      \
        int kb = (kc) * 32;                                                      \
_Pragma("unroll")                                                                \
        for (int i = 0; i < 3; i++) {                                            \
            int idx = i * 512 + tid;                                             \
            int arr = idx >> 9;                                                  \
            int r   = (idx >> 2) & 127;                                          \
            int c   = idx & 3;                                                   \
            const __nv_bfloat16* sp = (arr == 0) ? (Ah + (size_t)(m0 + r) * K)   \
                                    : (arr == 1) ? (Al + (size_t)(m0 + r) * K)   \
                                                 : (Bq + (size_t)(n0 + r) * K);  \
            uint32_t dp = sb + ((buf) * BUF_H + arr * ARR_H + r * PADH + c * 8) * 2; \
            cpasync16(dp, sp + kb + c * 8);                                      \
        }                                                                        \
    } while (0)

    FILLQ(0, 0);
    CP_COMMIT();

    const int rowoff = (lane & 7) + ((lane >> 3) & 1) * 8;
    const int coloff = (lane >> 4) * 8;
    const int c0 = (lane & 3) * 2;

    for (int g = 0; g < NG; g++) {
        float accg[2][4][4];
#pragma unroll
        for (int i = 0; i < 2; i++)
#pragma unroll
            for (int j = 0; j < 4; j++)
#pragma unroll
                for (int k = 0; k < 4; k++) accg[i][j][k] = 0.f;

#pragma unroll
        for (int kq = 0; kq < 4; kq++) {
            const int kc = g * 4 + kq;
            const int buf = kc & 1;
            if (kc + 1 < NK) FILLQ(buf ^ 1, kc + 1);
            CP_COMMIT();
            CP_WAIT1();
            __syncthreads();

#pragma unroll
            for (int kk = 0; kk < 2; kk++) {
                uint32_t afr[2][2][4];
                uint32_t bfr[2][4];
#pragma unroll
                for (int hl = 0; hl < 2; hl++)
#pragma unroll
                    for (int mi = 0; mi < 2; mi++) {
                        uint32_t a = sb + (buf * BUF_H + hl * ARR_H +
                            (mw + mi * 16 + rowoff) * PADH + kk * 16 + coloff) * 2;
                        LDSM4(afr[hl][mi][0], afr[hl][mi][1], afr[hl][mi][2], afr[hl][mi][3], a);
                    }
#pragma unroll
                for (int nj = 0; nj < 2; nj++) {
                    uint32_t a = sb + (buf * BUF_H + 2 * ARR_H +
                        (nw + nj * 16 + rowoff) * PADH + kk * 16 + coloff) * 2;
                    LDSM4(bfr[nj][0], bfr[nj][1], bfr[nj][2], bfr[nj][3], a);
                }
#pragma unroll
                for (int term = 0; term < 2; term++)
#pragma unroll
                    for (int mi = 0; mi < 2; mi++)
#pragma unroll
                        for (int ni = 0; ni < 4; ni++) {
                            int nj = ni >> 1, s = ni & 1;
                            MMA16816(accg[mi][ni], afr[term][mi],
                                     bfr[nj][s], bfr[nj][s + 2]);
                        }
            }
            __syncthreads();
        }

        // fold group scales (per output column n)
#pragma unroll
        for (int ni = 0; ni < 4; ni++) {
            float2 sv = *(const float2*)&ss[g * 132 + nw + ni * 8 + c0];
#pragma unroll
            for (int mi = 0; mi < 2; mi++) {
                acc[mi][ni][0] = fmaf(sv.x, accg[mi][ni][0], acc[mi][ni][0]);
                acc[mi][ni][1] = fmaf(sv.y, accg[mi][ni][1], acc[mi][ni][1]);
                acc[mi][ni][2] = fmaf(sv.x, accg[mi][ni][2], acc[mi][ni][2]);
                acc[mi][ni][3] = fmaf(sv.y, accg[mi][ni][3], acc[mi][ni][3]);
            }
        }
    }

    // epilogue
    const int r0 = lane >> 2;
#pragma unroll
    for (int mi = 0; mi < 2; mi++) {
#pragma unroll
        for (int ni = 0; ni < 4; ni++) {
            int m = m0 + mw + mi * 16 + r0;
            int n = n0 + nw + ni * 8 + c0;
            if (n < Nlim) {
                *(float2*)&C[(size_t)m * Nw + n]       = make_float2(acc[mi][ni][0], acc[mi][ni][1]);
                *(float2*)&C[(size_t)(m + 8) * Nw + n] = make_float2(acc[mi][ni][2], acc[mi][ni][3]);
            }
        }
    }
#undef FILLQ
}

// ---------------- fq4 dequantization -> q (bf16, exact) + group scale ----------------
__global__ void k_dequantq(const float* __restrict__ src, __nv_bfloat16* __restrict__ dq,
                           float* __restrict__ ds, int ngroups)
{
    int g = blockIdx.x * 4 + (threadIdx.x >> 5);
    if (g >= ngroups) return;
    int lane = threadIdx.x & 31;
    const float* s = src + (size_t)g * 128;
    float v[4];
    float m = 0.f;
#pragma unroll
    for (int i = 0; i < 4; i++) { v[i] = s[lane + 32*i]; m = fmaxf(m, fabsf(v[i])); }
#pragma unroll
    for (int o = 16; o; o >>= 1) m = fmaxf(m, __shfl_xor_sync(0xffffffffu, m, o));
    float scale = fmaxf(m, 1e-10f) / 7.0f;
    if (lane == 0) ds[g] = scale;
#pragma unroll
    for (int i = 0; i < 4; i++) {
        float q = rintf(v[i] / scale);
        q = fminf(fmaxf(q, -8.f), 7.f);
        dq[(size_t)g * 128 + lane + 32*i] = __float2bfloat16(q);  // exact (small int)
    }
}

// ---------------- split fp32 -> bf16 hi/lo ----------------
__global__ void k_split(const float* __restrict__ src, __nv_bfloat16* __restrict__ dh,
                        __nv_bfloat16* __restrict__ dl)
{
    size_t i = ((size_t)blockIdx.x * 256 + threadIdx.x) * 4;
    float4 v = *(const float4*)(src + i);
    float vv[4] = {v.x, v.y, v.z, v.w};
#pragma unroll
    for (int k = 0; k < 4; k++) {
        __nv_bfloat16 h = __float2bfloat16(vv[k]);
        dh[i + k] = h;
        dl[i + k] = __float2bfloat16(vv[k] - __bfloat162float(h));
    }
}

// ---------------- pointwise epilogue per (b,l) row: 64 threads ----------------
__global__ void k_point(const float* __restrict__ Bb, const float* __restrict__ Cb,
                        const float* __restrict__ Alog, const float* __restrict__ dtb)
{
    int row = blockIdx.x;
    int t = threadIdx.x;
    const float* pr = g_P + (size_t)row * NPROJ;
    __shared__ float red[6];

    float dtr = pr[OFF_DT + t] + dtb[t];
    float dt = (dtr > 20.f) ? dtr : log1pf(expf(dtr));
    float Ad = -expf(Alog[t]) * dt;
    float lam = 1.f / (1.f + expf(-pr[OFF_LAM + t]));
    g_Ad[row*64 + t] = Ad;
    g_ga[row*64 + t] = lam * dt;
    g_be[row*64 + t] = (1.f - lam) * dt * expf(Ad);

    float bv = pr[OFF_B + t];
    float cv = pr[OFF_C + t];

    float s0 = dt, s1 = bv*bv, s2 = cv*cv;
#pragma unroll
    for (int o = 16; o; o >>= 1) {
        s0 += __shfl_xor_sync(0xffffffffu, s0, o);
        s1 += __shfl_xor_sync(0xffffffffu, s1, o);
        s2 += __shfl_xor_sync(0xffffffffu, s2, o);
    }
    int w = t >> 5;
    if ((t & 31) == 0) { red[w*3+0] = s0; red[w*3+1] = s1; red[w*3+2] = s2; }
    __syncthreads();
    float dt_avg = (red[0] + red[3]) * (1.f/64.f);
    float rb = rsqrtf((red[1] + red[4]) * (1.f/64.f) + RMS_EPS);
    float rc = rsqrtf((red[2] + red[5]) * (1.f/64.f) + RMS_EPS);

    g_Bv[row*64 + t] = bv * rb + Bb[t];
    g_Cv[row*64 + t] = cv * rc + Cb[t];
    if (t < 32) g_td[row*32 + t] = pr[OFF_TH + t] * dt_avg;
}

// ---------------- cumsum of theta*dt_avg over L per (b, n) ----------------
__global__ void k_scan()
{
    int b = blockIdx.x >> 5;
    int n = blockIdx.x & 31;
    int tid = threadIdx.x;
    __shared__ float ps[256];
    float loc[16];
    float run = 0.f;
    int base = (b*SEQ + tid*16) * 32 + n;
#pragma unroll
    for (int j = 0; j < 16; j++) { run += g_td[base + j*32]; loc[j] = run; }
    ps[tid] = run;
    __syncthreads();
#pragma unroll
    for (int o = 1; o < 256; o <<= 1) {
        float v = (tid >= o) ? ps[tid - o] : 0.f;
        __syncthreads();
        ps[tid] += v;
        __syncthreads();
    }
    float off = (tid > 0) ? ps[tid - 1] : 0.f;
#pragma unroll
    for (int j = 0; j < 16; j++) g_td[base + j*32] = loc[j] + off;
}

// ---------------- rope on B and C (in place) ----------------
__global__ void k_rope()
{
    int row = blockIdx.x;
    int t = threadIdx.x;
    float a = g_td[row*32 + t];
    float ca = cosf(a), sa = sinf(a);
    float br = g_Bv[row*64 + t], bi = g_Bv[row*64 + 32 + t];
    g_Bv[row*64 + t]      = br*ca - bi*sa;
    g_Bv[row*64 + 32 + t] = br*sa + bi*ca;
    float cr = g_Cv[row*64 + t], ci = g_Cv[row*64 + 32 + t];
    g_Cv[row*64 + t]      = cr*ca - ci*sa;
    g_Cv[row*64 + 32 + t] = cr*sa + ci*ca;
}

// ---------------- intra-chunk: Y_diag + per-chunk states ----------------
#define SM_CHUNK_BYTES ((4352*5 + 128) * 4)
__launch_bounds__(256)
__global__ void k_chunk()
{
    extern __shared__ float sm[];
    float* sX  = sm;
    float* sB  = sm + 4352;
    float* sBT = sm + 8704;
    float* sCT = sm + 13056;
    float* sGT = sm + 17408;
    float* sA  = sm + 21760;
    float* sW  = sm + 21824;

    const int h = blockIdx.x, c = blockIdx.y, b = blockIdx.z;
    const int tid = threadIdx.x;

    if (tid < 64) {
        int row_g = b*SEQ + c*64 + tid;
        sA[tid] = g_Ad[row_g*64 + h];
    }
    __syncthreads();
#pragma unroll
    for (int o = 1; o < 64; o <<= 1) {
        float v = (tid < 64 && tid >= o) ? sA[tid - o] : 0.f;
        __syncthreads();
        if (tid < 64) sA[tid] += v;
        __syncthreads();
    }
    float Alast = sA[63];
    if (tid < 64) {
        sW[tid] = expf(Alast - sA[tid]);
        g_eA[((b*NCHUNK + c)*NHEADS + h)*64 + tid] = expf(sA[tid]);
    }
    if (tid == 0) g_cd[(b*NCHUNK + c)*NHEADS + h] = expf(Alast);

#pragma unroll
    for (int it = 0; it < 4; it++) {
        int idx = tid + it*256;
        int l = idx >> 4;
        int p4 = (idx & 15) << 2;
        int row_g = b*SEQ + c*64 + l;
        const float* xp = g_P + (size_t)row_g*NPROJ + OFF_XC + h*64 + p4;
        float4 xc = *(const float4*)xp;
        float ga = g_ga[row_g*64 + h];
        float be = g_be[row_g*64 + h];
        float4 xv;
        xv.x = siluf(xc.x)*ga; xv.y = siluf(xc.y)*ga; xv.z = siluf(xc.z)*ga; xv.w = siluf(xc.w)*ga;
        if (c*64 + l > 0) {
            float4 xq = *(const float4*)(xp - NPROJ);
            xv.x += siluf(xq.x)*be; xv.y += siluf(xq.y)*be; xv.z += siluf(xq.z)*be; xv.w += siluf(xq.w)*be;
        }
        *(float4*)&sX[l*68 + p4] = xv;
        float4 bb = *(const float4*)&g_Bv[row_g*64 + p4];
        *(float4*)&sB[l*68 + p4] = bb;
        sBT[(p4+0)*68 + l] = bb.x; sBT[(p4+1)*68 + l] = bb.y;
        sBT[(p4+2)*68 + l] = bb.z; sBT[(p4+3)*68 + l] = bb.w;
        float4 cc = *(const float4*)&g_Cv[row_g*64 + p4];
        sCT[(p4+0)*68 + l] = cc.x; sCT[(p4+1)*68 + l] = cc.y;
        sCT[(p4+2)*68 + l] = cc.z; sCT[(p4+3)*68 + l] = cc.w;
    }
    __syncthreads();

    const int ti = tid >> 4, tj = tid & 15;

    {
        const int l0 = ti*4, s0 = tj*4;
        float acc[4][4];
#pragma unroll
        for (int i = 0; i < 4; i++)
#pragma unroll
            for (int j = 0; j < 4; j++) acc[i][j] = 0.f;
#pragma unroll
        for (int n = 0; n < 64; n++) {
            float4 cl = *(const float4*)&sCT[n*68 + l0];
            float4 bs = *(const float4*)&sBT[n*68 + s0];
            float clv[4] = {cl.x, cl.y, cl.z, cl.w};
            float bsv[4] = {bs.x, bs.y, bs.z, bs.w};
#pragma unroll
            for (int i = 0; i < 4; i++)
#pragma unroll
                for (int j = 0; j < 4; j++)
                    acc[i][j] = fmaf(clv[i], bsv[j], acc[i][j]);
        }
        float al[4];
#pragma unroll
        for (int i = 0; i < 4; i++) al[i] = sA[l0 + i];
#pragma unroll
        for (int j = 0; j < 4; j++) {
            int s = s0 + j;
            float as = sA[s];
#pragma unroll
            for (int i = 0; i < 4; i++) {
                int l = l0 + i;
                sGT[s*68 + l] = (s <= l) ? acc[i][j] * expf(al[i] - as) : 0.f;
            }
        }
    }
    __syncthreads();

    {
        const int l0 = ti*4, p0 = tj*4;
        float acc[4][4];
#pragma unroll
        for (int i = 0; i < 4; i++)
#pragma unroll
            for (int j = 0; j < 4; j++) acc[i][j] = 0.f;
        // G is lower-triangular: contributions vanish for s > l0+3
        const int smax = l0 + 4;
#pragma unroll 4
        for (int s = 0; s < smax; s++) {
            float4 gt = *(const float4*)&sGT[s*68 + l0];
            float4 xr = *(const float4*)&sX[s*68 + p0];
            float gv[4] = {gt.x, gt.y, gt.z, gt.w};
            float xvv[4] = {xr.x, xr.y, xr.z, xr.w};
#pragma unroll
            for (int i = 0; i < 4; i++)
#pragma unroll
                for (int j = 0; j < 4; j++)
                    acc[i][j] = fmaf(gv[i], xvv[j], acc[i][j]);
        }
#pragma unroll
        for (int i = 0; i < 4; i++) {
            int row_g = b*SEQ + c*64 + l0 + i;
            *(float4*)&g_Y[(size_t)row_g*D_INNER + h*64 + p0] =
                make_float4(acc[i][0], acc[i][1], acc[i][2], acc[i][3]);
        }
    }

    {
        const int p0 = ti*4, n0 = tj*4;
        float acc[4][4];
#pragma unroll
        for (int i = 0; i < 4; i++)
#pragma unroll
            for (int j = 0; j < 4; j++) acc[i][j] = 0.f;
#pragma unroll
        for (int l = 0; l < 64; l++) {
            float w = sW[l];
            float4 xr = *(const float4*)&sX[l*68 + p0];
            float4 br = *(const float4*)&sB[l*68 + n0];
            float wx[4] = {w*xr.x, w*xr.y, w*xr.z, w*xr.w};
            float bvv[4] = {br.x, br.y, br.z, br.w};
#pragma unroll
            for (int i = 0; i < 4; i++)
#pragma unroll
                for (int j = 0; j < 4; j++)
                    acc[i][j] = fmaf(wx[i], bvv[j], acc[i][j]);
        }
        size_t base = (size_t)((b*NCHUNK + c)*NHEADS + h) * 4096;
#pragma unroll
        for (int i = 0; i < 4; i++)
            *(float4*)&g_S[base + (p0 + i)*64 + n0] =
                make_float4(acc[i][0], acc[i][1], acc[i][2], acc[i][3]);
    }
}

// ---------------- inter-chunk scan: 512 CTAs, one (b,h,quarter) each ----------------
__global__ void k_cscan()
{
    int q = blockIdx.x & 3;
    int h = (blockIdx.x >> 2) & 63;
    int b = blockIdx.x >> 8;
    int tid = threadIdx.x;
    int off = q * 1024 + tid * 4;
    float s0 = 0.f, s1 = 0.f, s2 = 0.f, s3 = 0.f;
    const float* cdp = g_cd + b * NCHUNK * NHEADS + h;
    for (int c = 0; c < NCHUNK; c++) {
        size_t base = ((size_t)((b*NCHUNK + c)*NHEADS + h) << 12) + off;
        float cd = cdp[c * NHEADS];
        float4 t = *(const float4*)&g_S[base];
        *(float4*)&g_S[base] = make_float4(s0, s1, s2, s3);
        s0 = fmaf(cd, s0, t.x);
        s1 = fmaf(cd, s1, t.y);
        s2 = fmaf(cd, s2, t.z);
        s3 = fmaf(cd, s3, t.w);
    }
}

// ---------------- Y_off + D skip + z gating ----------------
__launch_bounds__(256)
__global__ void k_off(const float* __restrict__ Dp)
{
    __shared__ float sST[64*68];
    __shared__ float sCT[64*68];
    const int h = blockIdx.x, c = blockIdx.y, b = blockIdx.z;
    const int tid = threadIdx.x;
    size_t sbase = (size_t)((b*NCHUNK + c)*NHEADS + h) * 4096;
#pragma unroll
    for (int it = 0; it < 4; it++) {
        int idx = tid + it*256;
        int r = idx >> 4;
        int n4 = (idx & 15) << 2;
        float4 sv = *(const float4*)&g_S[sbase + r*64 + n4];
        sST[(n4+0)*68 + r] = sv.x; sST[(n4+1)*68 + r] = sv.y;
        sST[(n4+2)*68 + r] = sv.z; sST[(n4+3)*68 + r] = sv.w;
        int row_g = b*SEQ + c*64 + r;
        float4 cv = *(const float4*)&g_Cv[row_g*64 + n4];
        sCT[(n4+0)*68 + r] = cv.x; sCT[(n4+1)*68 + r] = cv.y;
        sCT[(n4+2)*68 + r] = cv.z; sCT[(n4+3)*68 + r] = cv.w;
    }
    __syncthreads();
    const int ti = tid >> 4, tj = tid & 15;
    const int l0 = ti*4, p0 = tj*4;
    float acc[4][4];
#pragma unroll
    for (int i = 0; i < 4; i++)
#pragma unroll
        for (int j = 0; j < 4; j++) acc[i][j] = 0.f;
#pragma unroll
    for (int n = 0; n < 64; n++) {
        float4 cl = *(const float4*)&sCT[n*68 + l0];
        float4 sp = *(const float4*)&sST[n*68 + p0];
        float clv[4] = {cl.x, cl.y, cl.z, cl.w};
        float spv[4] = {sp.x, sp.y, sp.z, sp.w};
#pragma unroll
        for (int i = 0; i < 4; i++)
#pragma unroll
            for (int j = 0; j < 4; j++)
                acc[i][j] = fmaf(clv[i], spv[j], acc[i][j]);
    }
    float Dh = Dp[h];
#pragma unroll
    for (int i = 0; i < 4; i++) {
        int l = l0 + i;
        int row_g = b*SEQ + c*64 + l;
        float e = g_eA[((b*NCHUNK + c)*NHEADS + h)*64 + l];
        const float* pr = g_P + (size_t)row_g*NPROJ;
        float4 xc = *(const float4*)&pr[OFF_XC + h*64 + p0];
        float4 zz = *(const float4*)&pr[OFF_Z  + h*64 + p0];
        float* yp = &g_Y[(size_t)row_g*D_INNER + h*64 + p0];
        float4 yd = *(const float4*)yp;
        float4 o;
        o.x = (yd.x + e*acc[i][0] + Dh*siluf(xc.x)) * siluf(zz.x);
        o.y = (yd.y + e*acc[i][1] + Dh*siluf(xc.y)) * siluf(zz.y);
        o.z = (yd.z + e*acc[i][2] + Dh*siluf(xc.z)) * siluf(zz.z);
        o.w = (yd.w + e*acc[i][3] + Dh*siluf(xc.w)) * siluf(zz.w);
        *(float4*)yp = o;
    }
}

// ---------------- rmsnorm over 4096 per row -> bf16 hi/lo ----------------
__global__ void k_rms()
{
    int row = blockIdx.x;
    int tid = threadIdx.x;
    const float* Yp = g_Y + (size_t)row * D_INNER;
    float4 v[4];
    float ss = 0.f;
#pragma unroll
    for (int i = 0; i < 4; i++) {
        v[i] = *(const float4*)&Yp[tid*16 + i*4];
        ss += v[i].x*v[i].x + v[i].y*v[i].y + v[i].z*v[i].z + v[i].w*v[i].w;
    }
#pragma unroll
    for (int o = 16; o; o >>= 1) ss += __shfl_xor_sync(0xffffffffu, ss, o);
    __shared__ float red[8];
    if ((tid & 31) == 0) red[tid >> 5] = ss;
    __syncthreads();
    float tot = 0.f;
#pragma unroll
    for (int i = 0; i < 8; i++) tot += red[i];
    float r = rsqrtf(tot * (1.f/4096.f) + RMS_EPS);
    size_t base = (size_t)row * D_INNER + tid*16;
#pragma unroll
    for (int i = 0; i < 4; i++) {
        float vv[4] = {v[i].x*r, v[i].y*r, v[i].z*r, v[i].w*r};
#pragma unroll
        for (int k = 0; k < 4; k++) {
            __nv_bfloat16 h = __float2bfloat16(vv[k]);
            g_Yh[base + i*4 + k] = h;
            g_Yl[base + i*4 + k] = __float2bfloat16(vv[k] - __bfloat162float(h));
        }
    }
}

// ---------------- launcher ----------------
extern "C" void kernel_launch(void* const* d_in, const int* in_sizes, int n_in,
                              void* d_out, int out_size)
{
    const float* x    = (const float*)d_in[0];
    const float* Win  = (const float*)d_in[1];
    const float* Wth  = (const float*)d_in[2];
    const float* Wla  = (const float*)d_in[3];
    const float* Wout = (const float*)d_in[4];
    const float* Bb   = (const float*)d_in[5];
    const float* Cb   = (const float*)d_in[6];
    const float* Alog = (const float*)d_in[7];
    const float* Dp   = (const float*)d_in[8];
    const float* dtb  = (const float*)d_in[9];
    float* out = (float*)d_out;

    __nv_bfloat16 *pWq, *pWoq, *pxh, *pxl, *pYh, *pYl;
    float *pWs, *pWos, *pP;
    cudaGetSymbolAddress((void**)&pWq,  g_Wq);
    cudaGetSymbolAddress((void**)&pWs,  g_Ws);
    cudaGetSymbolAddress((void**)&pWoq, g_Woq);
    cudaGetSymbolAddress((void**)&pWos, g_Wos);
    cudaGetSymbolAddress((void**)&pxh,  g_xh);
    cudaGetSymbolAddress((void**)&pxl,  g_xl);
    cudaGetSymbolAddress((void**)&pYh,  g_Yh);
    cudaGetSymbolAddress((void**)&pYl,  g_Yl);
    cudaGetSymbolAddress((void**)&pP,   g_P);

    const int smem1 = (SS_OFF * 2) + 16 * 132 * 4;
    const int smem2 = (SS_OFF * 2) + 32 * 132 * 4;

    cudaFuncSetAttribute(k_chunk,    cudaFuncAttributeMaxDynamicSharedMemorySize, SM_CHUNK_BYTES);
    cudaFuncSetAttribute(k_mmq<16>,  cudaFuncAttributeMaxDynamicSharedMemorySize, smem1);
    cudaFuncSetAttribute(k_mmq<32>,  cudaFuncAttributeMaxDynamicSharedMemorySize, smem2);

    // fq4 dequant -> q + scales into fused weight buffer (pad rows stay zero)
    k_dequantq<<<(8384*16 + 3)/4, 128>>>(Win, pWq, pWs, 8384*16);
    k_dequantq<<<(512 + 3)/4,    128>>>(Wth, pWq + (size_t)8384*DIMK, pWs + (size_t)8384*16, 512);
    k_dequantq<<<(1024 + 3)/4,   128>>>(Wla, pWq + (size_t)8416*DIMK, pWs + (size_t)8416*16, 1024);
    k_dequantq<<<65536/4,        128>>>(Wout, pWoq, pWos, 65536);

    // split activations
    k_split<<<ROWS*DIMK/1024, 256>>>(x, pxh, pxl);

    // in-projection GEMM: 8192 x 8480 x 2048 (2-term + group-scale fold)
    k_mmq<16><<<dim3(ROWS/128, NPROJ_PAD/128), 512, smem1>>>(
        pxh, pxl, pWq, pWs, pP, NPROJ, NPROJ, DIMK);

    k_point<<<ROWS, 64>>>(Bb, Cb, Alog, dtb);
    k_scan <<<64, 256>>>();
    k_rope <<<ROWS, 32>>>();

    k_chunk<<<dim3(NHEADS, NCHUNK, BATCH), 256, SM_CHUNK_BYTES>>>();
    k_cscan<<<512, 256>>>();
    k_off  <<<dim3(NHEADS, NCHUNK, BATCH), 256>>>(Dp);

    k_rms<<<ROWS, 256>>>();

    // out-projection GEMM: 8192 x 2048 x 4096 (2-term + group-scale fold)
    k_mmq<32><<<dim3(ROWS/128, DIMK/128), 512, smem2>>>(
        pYh, pYl, pWoq, pWos, out, DIMK, DIMK, D_INNER);
}

// round 9
// speedup vs baseline: 1.4205x; 1.0362x over previous
#include <cuda_runtime.h>
#include <cuda_bf16.h>
#include <math.h>
#include <stdint.h>

#define SEQ     4096
#define BATCH   2
#define ROWS    (BATCH*SEQ)     // 8192
#define DIMK    2048
#define D_INNER 4096
#define NHEADS  64
#define NPROJ   8480            // 8384 (in_proj) + 32 (theta) + 64 (lambda)
#define NPROJ_PAD 8576          // 67 * 128
#define OFF_Z   0
#define OFF_XC  4096
#define OFF_B   8192
#define OFF_C   8256
#define OFF_DT  8320
#define OFF_TH  8384
#define OFF_LAM 8416
#define NCHUNK  64
#define RMS_EPS 1.1920929e-07f

// ---------------- device scratch (no allocation allowed) ----------------
__device__ __nv_bfloat16 g_Wq [NPROJ_PAD * DIMK];   // fused in-proj q (4-bit ints, exact in bf16)
__device__ float         g_Ws [NPROJ_PAD * 16];     // per-group scales (16 groups of 128 per row)
__device__ __nv_bfloat16 g_Woq[DIMK * D_INNER];     // out-proj q
__device__ float         g_Wos[DIMK * 32];          // out-proj scales (32 groups per row)
__device__ __nv_bfloat16 g_xh [ROWS * DIMK];
__device__ __nv_bfloat16 g_xl [ROWS * DIMK];
__device__ __nv_bfloat16 g_Yh [ROWS * D_INNER];
__device__ __nv_bfloat16 g_Yl [ROWS * D_INNER];
__device__ float g_P [ROWS * NPROJ];                // projection output
__device__ float g_Bv[ROWS * 64];
__device__ float g_Cv[ROWS * 64];
__device__ float g_Ad[ROWS * 64];
__device__ float g_ga[ROWS * 64];
__device__ float g_be[ROWS * 64];
__device__ float g_td[ROWS * 32];
__device__ float g_Y [ROWS * D_INNER];
__device__ float g_S [BATCH * NCHUNK * NHEADS * 64 * 64];
__device__ float g_eA[BATCH * NCHUNK * NHEADS * 64];
__device__ float g_cd[BATCH * NCHUNK * NHEADS];

__device__ __forceinline__ float siluf(float x) { return x / (1.f + expf(-x)); }

__device__ __forceinline__ uint32_t s2u(const void* p) {
    uint32_t a;
    asm("{ .reg .u64 t; cvta.to.shared.u64 t, %1; cvt.u32.u64 %0, t; }" : "=r"(a) : "l"(p));
    return a;
}

// ================= quant-aware emulated-fp32 GEMM via mma.sync =================
// C[M,Nw] = A[M,K] * B[N,K]^T where B = q * scale(group of 128 along K).
// A pre-split into bf16 hi/lo (2 MMA terms), q exact in bf16, scale folded in fp32
// at each 128-K group boundary.
// CTA 128x128, 16 warps (4x4) of 32x32 warp tiles, K-chunk 32,
// THREE-stage cp.async ring: 1 barrier per chunk, depth-2 prefetch.
#define PADH 40                      // 32 halves + 8 pad
#define ARR_H (128*PADH)             // 5120 halves per sub-tile
#define BUF_H (3*ARR_H)              // Ah, Al, Bq per stage
#define SS_OFF (3*BUF_H)             // halves offset where fp32 scales start (3 stages)

__device__ __forceinline__ void cpasync16(uint32_t dst, const void* src) {
    asm volatile("cp.async.cg.shared.global [%0], [%1], 16;" :: "r"(dst), "l"(src));
}
#define CP_COMMIT() asm volatile("cp.async.commit_group;" ::: "memory")
#define CP_WAITG1() asm volatile("cp.async.wait_group 1;" ::: "memory")

#define LDSM4(r0,r1,r2,r3,a) \
    asm volatile("ldmatrix.sync.aligned.m8n8.x4.shared.b16 {%0,%1,%2,%3}, [%4];" \
        : "=r"(r0),"=r"(r1),"=r"(r2),"=r"(r3) : "r"(a))

#define MMA16816(d,a,b0,b1) \
    asm volatile("mma.sync.aligned.m16n8k16.row.col.f32.bf16.bf16.f32 " \
        "{%0,%1,%2,%3}, {%4,%5,%6,%7}, {%8,%9}, {%0,%1,%2,%3};" \
        : "+f"((d)[0]),"+f"((d)[1]),"+f"((d)[2]),"+f"((d)[3]) \
        : "r"((a)[0]),"r"((a)[1]),"r"((a)[2]),"r"((a)[3]),"r"(b0),"r"(b1))

template<int NG>
__global__ void __launch_bounds__(512, 1)
k_mmq(const __nv_bfloat16* __restrict__ Ah, const __nv_bfloat16* __restrict__ Al,
      const __nv_bfloat16* __restrict__ Bq, const float* __restrict__ Bs,
      float* __restrict__ C, int Nw, int Nlim, int K)
{
    extern __shared__ __nv_bfloat16 sh[];
    float* ss = (float*)(sh + SS_OFF);        // [NG][132] scales for this CTA's n-range
    const uint32_t sb = s2u(sh);
    const int tid  = threadIdx.x;
    const int lane = tid & 31;
    const int wid  = tid >> 5;                // 0..15
    const int m0 = blockIdx.x * 128;
    const int n0 = blockIdx.y * 128;
    const int mw = (wid >> 2) * 32;
    const int nw = (wid & 3) * 32;

    // preload scales for the CTA's 128 weight rows
    for (int idx = tid; idx < 128 * NG; idx += 512) {
        int g = idx >> 7, nl = idx & 127;
        ss[g * 132 + nl] = Bs[(size_t)(n0 + nl) * NG + g];
    }

    float acc[2][4][4];
#pragma unroll
    for (int i = 0; i < 2; i++)
#pragma unroll
        for (int j = 0; j < 4; j++)
#pragma unroll
            for (int k = 0; k < 4; k++) acc[i][j][k] = 0.f;

    const int NK = K >> 5;

#define FILLQ(buf, kc) do {                                                      \
        int kb = (kc) * 32;                                                      \
_Pragma("unroll")                                                                \
        for (int i = 0; i < 3; i++) {                                            \
            int idx = i * 512 + tid;                                             \
            int arr = idx >> 9;                                                  \
            int r   = (idx >> 2) & 127;                                          \
            int c   = idx & 3;                                                   \
            const __nv_bfloat16* sp = (arr == 0) ? (Ah + (size_t)(m0 + r) * K)   \
                                    : (arr == 1) ? (Al + (size_t)(m0 + r) * K)   \
                                                 : (Bq + (size_t)(n0 + r) * K);  \
            uint32_t dp = sb + ((buf) * BUF_H + arr * ARR_H + r * PADH + c * 8) * 2; \
            cpasync16(dp, sp + kb + c * 8);                                      \
        }                                                                        \
    } while (0)

    // prologue: prefetch chunks 0 and 1 (NK >= 2 always)
    FILLQ(0, 0);
    CP_COMMIT();
    FILLQ(1, 1);
    CP_COMMIT();

    const int rowoff = (lane & 7) + ((lane >> 3) & 1) * 8;
    const int coloff = (lane >> 4) * 8;
    const int c0 = (lane & 3) * 2;

    for (int g = 0; g < NG; g++) {
        float accg[2][4][4];
#pragma unroll
        for (int i = 0; i < 2; i++)
#pragma unroll
            for (int j = 0; j < 4; j++)
#pragma unroll
                for (int k = 0; k < 4; k++) accg[i][j][k] = 0.f;

#pragma unroll
        for (int kq = 0; kq < 4; kq++) {
            const int kc = g * 4 + kq;
            const int buf = kc % 3;

            // fill(kc) is complete when at most 1 group (fill kc+1) is pending
            CP_WAITG1();
            __syncthreads();   // also orders prior reads of stage (kc+2)%3 before refill

            if (kc + 2 < NK) FILLQ((kc + 2) % 3, kc + 2);
            CP_COMMIT();       // exactly one group per iteration (possibly empty)

#pragma unroll
            for (int kk = 0; kk < 2; kk++) {
                uint32_t afr[2][2][4];
                uint32_t bfr[2][4];
#pragma unroll
                for (int hl = 0; hl < 2; hl++)
#pragma unroll
                    for (int mi = 0; mi < 2; mi++) {
                        uint32_t a = sb + (buf * BUF_H + hl * ARR_H +
                            (mw + mi * 16 + rowoff) * PADH + kk * 16 + coloff) * 2;
                        LDSM4(afr[hl][mi][0], afr[hl][mi][1], afr[hl][mi][2], afr[hl][mi][3], a);
                    }
#pragma unroll
                for (int nj = 0; nj < 2; nj++) {
                    uint32_t a = sb + (buf * BUF_H + 2 * ARR_H +
                        (nw + nj * 16 + rowoff) * PADH + kk * 16 + coloff) * 2;
                    LDSM4(bfr[nj][0], bfr[nj][1], bfr[nj][2], bfr[nj][3], a);
                }
#pragma unroll
                for (int term = 0; term < 2; term++)
#pragma unroll
                    for (int mi = 0; mi < 2; mi++)
#pragma unroll
                        for (int ni = 0; ni < 4; ni++) {
                            int nj = ni >> 1, s = ni & 1;
                            MMA16816(accg[mi][ni], afr[term][mi],
                                     bfr[nj][s], bfr[nj][s + 2]);
                        }
            }
        }

        // fold group scales (per output column n)
#pragma unroll
        for (int ni = 0; ni < 4; ni++) {
            float2 sv = *(const float2*)&ss[g * 132 + nw + ni * 8 + c0];
#pragma unroll
            for (int mi = 0; mi < 2; mi++) {
                acc[mi][ni][0] = fmaf(sv.x, accg[mi][ni][0], acc[mi][ni][0]);
                acc[mi][ni][1] = fmaf(sv.y, accg[mi][ni][1], acc[mi][ni][1]);
                acc[mi][ni][2] = fmaf(sv.x, accg[mi][ni][2], acc[mi][ni][2]);
                acc[mi][ni][3] = fmaf(sv.y, accg[mi][ni][3], acc[mi][ni][3]);
            }
        }
    }

    // epilogue
    const int r0 = lane >> 2;
#pragma unroll
    for (int mi = 0; mi < 2; mi++) {
#pragma unroll
        for (int ni = 0; ni < 4; ni++) {
            int m = m0 + mw + mi * 16 + r0;
            int n = n0 + nw + ni * 8 + c0;
            if (n < Nlim) {
                *(float2*)&C[(size_t)m * Nw + n]       = make_float2(acc[mi][ni][0], acc[mi][ni][1]);
                *(float2*)&C[(size_t)(m + 8) * Nw + n] = make_float2(acc[mi][ni][2], acc[mi][ni][3]);
            }
        }
    }
#undef FILLQ
}

// ---------------- fq4 dequantization -> q (bf16, exact) + group scale ----------------
__global__ void k_dequantq(const float* __restrict__ src, __nv_bfloat16* __restrict__ dq,
                           float* __restrict__ ds, int ngroups)
{
    int g = blockIdx.x * 4 + (threadIdx.x >> 5);
    if (g >= ngroups) return;
    int lane = threadIdx.x & 31;
    const float* s = src + (size_t)g * 128;
    float v[4];
    float m = 0.f;
#pragma unroll
    for (int i = 0; i < 4; i++) { v[i] = s[lane + 32*i]; m = fmaxf(m, fabsf(v[i])); }
#pragma unroll
    for (int o = 16; o; o >>= 1) m = fmaxf(m, __shfl_xor_sync(0xffffffffu, m, o));
    float scale = fmaxf(m, 1e-10f) / 7.0f;
    if (lane == 0) ds[g] = scale;
#pragma unroll
    for (int i = 0; i < 4; i++) {
        float q = rintf(v[i] / scale);
        q = fminf(fmaxf(q, -8.f), 7.f);
        dq[(size_t)g * 128 + lane + 32*i] = __float2bfloat16(q);  // exact (small int)
    }
}

// ---------------- split fp32 -> bf16 hi/lo ----------------
__global__ void k_split(const float* __restrict__ src, __nv_bfloat16* __restrict__ dh,
                        __nv_bfloat16* __restrict__ dl)
{
    size_t i = ((size_t)blockIdx.x * 256 + threadIdx.x) * 4;
    float4 v = *(const float4*)(src + i);
    float vv[4] = {v.x, v.y, v.z, v.w};
#pragma unroll
    for (int k = 0; k < 4; k++) {
        __nv_bfloat16 h = __float2bfloat16(vv[k]);
        dh[i + k] = h;
        dl[i + k] = __float2bfloat16(vv[k] - __bfloat162float(h));
    }
}

// ---------------- pointwise epilogue per (b,l) row: 64 threads ----------------
__global__ void k_point(const float* __restrict__ Bb, const float* __restrict__ Cb,
                        const float* __restrict__ Alog, const float* __restrict__ dtb)
{
    int row = blockIdx.x;
    int t = threadIdx.x;
    const float* pr = g_P + (size_t)row * NPROJ;
    __shared__ float red[6];

    float dtr = pr[OFF_DT + t] + dtb[t];
    float dt = (dtr > 20.f) ? dtr : log1pf(expf(dtr));
    float Ad = -expf(Alog[t]) * dt;
    float lam = 1.f / (1.f + expf(-pr[OFF_LAM + t]));
    g_Ad[row*64 + t] = Ad;
    g_ga[row*64 + t] = lam * dt;
    g_be[row*64 + t] = (1.f - lam) * dt * expf(Ad);

    float bv = pr[OFF_B + t];
    float cv = pr[OFF_C + t];

    float s0 = dt, s1 = bv*bv, s2 = cv*cv;
#pragma unroll
    for (int o = 16; o; o >>= 1) {
        s0 += __shfl_xor_sync(0xffffffffu, s0, o);
        s1 += __shfl_xor_sync(0xffffffffu, s1, o);
        s2 += __shfl_xor_sync(0xffffffffu, s2, o);
    }
    int w = t >> 5;
    if ((t & 31) == 0) { red[w*3+0] = s0; red[w*3+1] = s1; red[w*3+2] = s2; }
    __syncthreads();
    float dt_avg = (red[0] + red[3]) * (1.f/64.f);
    float rb = rsqrtf((red[1] + red[4]) * (1.f/64.f) + RMS_EPS);
    float rc = rsqrtf((red[2] + red[5]) * (1.f/64.f) + RMS_EPS);

    g_Bv[row*64 + t] = bv * rb + Bb[t];
    g_Cv[row*64 + t] = cv * rc + Cb[t];
    if (t < 32) g_td[row*32 + t] = pr[OFF_TH + t] * dt_avg;
}

// ---------------- cumsum of theta*dt_avg over L per (b, n) ----------------
__global__ void k_scan()
{
    int b = blockIdx.x >> 5;
    int n = blockIdx.x & 31;
    int tid = threadIdx.x;
    __shared__ float ps[256];
    float loc[16];
    float run = 0.f;
    int base = (b*SEQ + tid*16) * 32 + n;
#pragma unroll
    for (int j = 0; j < 16; j++) { run += g_td[base + j*32]; loc[j] = run; }
    ps[tid] = run;
    __syncthreads();
#pragma unroll
    for (int o = 1; o < 256; o <<= 1) {
        float v = (tid >= o) ? ps[tid - o] : 0.f;
        __syncthreads();
        ps[tid] += v;
        __syncthreads();
    }
    float off = (tid > 0) ? ps[tid - 1] : 0.f;
#pragma unroll
    for (int j = 0; j < 16; j++) g_td[base + j*32] = loc[j] + off;
}

// ---------------- rope on B and C (in place) ----------------
__global__ void k_rope()
{
    int row = blockIdx.x;
    int t = threadIdx.x;
    float a = g_td[row*32 + t];
    float ca = cosf(a), sa = sinf(a);
    float br = g_Bv[row*64 + t], bi = g_Bv[row*64 + 32 + t];
    g_Bv[row*64 + t]      = br*ca - bi*sa;
    g_Bv[row*64 + 32 + t] = br*sa + bi*ca;
    float cr = g_Cv[row*64 + t], ci = g_Cv[row*64 + 32 + t];
    g_Cv[row*64 + t]      = cr*ca - ci*sa;
    g_Cv[row*64 + 32 + t] = cr*sa + ci*ca;
}

// ---------------- intra-chunk: Y_diag + per-chunk states ----------------
#define SM_CHUNK_BYTES ((4352*5 + 128) * 4)
__launch_bounds__(256)
__global__ void k_chunk()
{
    extern __shared__ float sm[];
    float* sX  = sm;
    float* sB  = sm + 4352;
    float* sBT = sm + 8704;
    float* sCT = sm + 13056;
    float* sGT = sm + 17408;
    float* sA  = sm + 21760;
    float* sW  = sm + 21824;

    const int h = blockIdx.x, c = blockIdx.y, b = blockIdx.z;
    const int tid = threadIdx.x;

    if (tid < 64) {
        int row_g = b*SEQ + c*64 + tid;
        sA[tid] = g_Ad[row_g*64 + h];
    }
    __syncthreads();
#pragma unroll
    for (int o = 1; o < 64; o <<= 1) {
        float v = (tid < 64 && tid >= o) ? sA[tid - o] : 0.f;
        __syncthreads();
        if (tid < 64) sA[tid] += v;
        __syncthreads();
    }
    float Alast = sA[63];
    if (tid < 64) {
        sW[tid] = expf(Alast - sA[tid]);
        g_eA[((b*NCHUNK + c)*NHEADS + h)*64 + tid] = expf(sA[tid]);
    }
    if (tid == 0) g_cd[(b*NCHUNK + c)*NHEADS + h] = expf(Alast);

#pragma unroll
    for (int it = 0; it < 4; it++) {
        int idx = tid + it*256;
        int l = idx >> 4;
        int p4 = (idx & 15) << 2;
        int row_g = b*SEQ + c*64 + l;
        const float* xp = g_P + (size_t)row_g*NPROJ + OFF_XC + h*64 + p4;
        float4 xc = *(const float4*)xp;
        float ga = g_ga[row_g*64 + h];
        float be = g_be[row_g*64 + h];
        float4 xv;
        xv.x = siluf(xc.x)*ga; xv.y = siluf(xc.y)*ga; xv.z = siluf(xc.z)*ga; xv.w = siluf(xc.w)*ga;
        if (c*64 + l > 0) {
            float4 xq = *(const float4*)(xp - NPROJ);
            xv.x += siluf(xq.x)*be; xv.y += siluf(xq.y)*be; xv.z += siluf(xq.z)*be; xv.w += siluf(xq.w)*be;
        }
        *(float4*)&sX[l*68 + p4] = xv;
        float4 bb = *(const float4*)&g_Bv[row_g*64 + p4];
        *(float4*)&sB[l*68 + p4] = bb;
        sBT[(p4+0)*68 + l] = bb.x; sBT[(p4+1)*68 + l] = bb.y;
        sBT[(p4+2)*68 + l] = bb.z; sBT[(p4+3)*68 + l] = bb.w;
        float4 cc = *(const float4*)&g_Cv[row_g*64 + p4];
        sCT[(p4+0)*68 + l] = cc.x; sCT[(p4+1)*68 + l] = cc.y;
        sCT[(p4+2)*68 + l] = cc.z; sCT[(p4+3)*68 + l] = cc.w;
    }
    __syncthreads();

    const int ti = tid >> 4, tj = tid & 15;

    {
        const int l0 = ti*4, s0 = tj*4;
        float acc[4][4];
#pragma unroll
        for (int i = 0; i < 4; i++)
#pragma unroll
            for (int j = 0; j < 4; j++) acc[i][j] = 0.f;
#pragma unroll
        for (int n = 0; n < 64; n++) {
            float4 cl = *(const float4*)&sCT[n*68 + l0];
            float4 bs = *(const float4*)&sBT[n*68 + s0];
            float clv[4] = {cl.x, cl.y, cl.z, cl.w};
            float bsv[4] = {bs.x, bs.y, bs.z, bs.w};
#pragma unroll
            for (int i = 0; i < 4; i++)
#pragma unroll
                for (int j = 0; j < 4; j++)
                    acc[i][j] = fmaf(clv[i], bsv[j], acc[i][j]);
        }
        float al[4];
#pragma unroll
        for (int i = 0; i < 4; i++) al[i] = sA[l0 + i];
#pragma unroll
        for (int j = 0; j < 4; j++) {
            int s = s0 + j;
            float as = sA[s];
#pragma unroll
            for (int i = 0; i < 4; i++) {
                int l = l0 + i;
                sGT[s*68 + l] = (s <= l) ? acc[i][j] * expf(al[i] - as) : 0.f;
            }
        }
    }
    __syncthreads();

    {
        const int l0 = ti*4, p0 = tj*4;
        float acc[4][4];
#pragma unroll
        for (int i = 0; i < 4; i++)
#pragma unroll
            for (int j = 0; j < 4; j++) acc[i][j] = 0.f;
        const int smax = l0 + 4;
#pragma unroll 4
        for (int s = 0; s < smax; s++) {
            float4 gt = *(const float4*)&sGT[s*68 + l0];
            float4 xr = *(const float4*)&sX[s*68 + p0];
            float gv[4] = {gt.x, gt.y, gt.z, gt.w};
            float xvv[4] = {xr.x, xr.y, xr.z, xr.w};
#pragma unroll
            for (int i = 0; i < 4; i++)
#pragma unroll
                for (int j = 0; j < 4; j++)
                    acc[i][j] = fmaf(gv[i], xvv[j], acc[i][j]);
        }
#pragma unroll
        for (int i = 0; i < 4; i++) {
            int row_g = b*SEQ + c*64 + l0 + i;
            *(float4*)&g_Y[(size_t)row_g*D_INNER + h*64 + p0] =
                make_float4(acc[i][0], acc[i][1], acc[i][2], acc[i][3]);
        }
    }

    {
        const int p0 = ti*4, n0 = tj*4;
        float acc[4][4];
#pragma unroll
        for (int i = 0; i < 4; i++)
#pragma unroll
            for (int j = 0; j < 4; j++) acc[i][j] = 0.f;
#pragma unroll
        for (int l = 0; l < 64; l++) {
            float w = sW[l];
            float4 xr = *(const float4*)&sX[l*68 + p0];
            float4 br = *(const float4*)&sB[l*68 + n0];
            float wx[4] = {w*xr.x, w*xr.y, w*xr.z, w*xr.w};
            float bvv[4] = {br.x, br.y, br.z, br.w};
#pragma unroll
            for (int i = 0; i < 4; i++)
#pragma unroll
                for (int j = 0; j < 4; j++)
                    acc[i][j] = fmaf(wx[i], bvv[j], acc[i][j]);
        }
        size_t base = (size_t)((b*NCHUNK + c)*NHEADS + h) * 4096;
#pragma unroll
        for (int i = 0; i < 4; i++)
            *(float4*)&g_S[base + (p0 + i)*64 + n0] =
                make_float4(acc[i][0], acc[i][1], acc[i][2], acc[i][3]);
    }
}

// ---------------- inter-chunk scan: 512 CTAs, one (b,h,quarter) each ----------------
__global__ void k_cscan()
{
    int q = blockIdx.x & 3;
    int h = (blockIdx.x >> 2) & 63;
    int b = blockIdx.x >> 8;
    int tid = threadIdx.x;
    int off = q * 1024 + tid * 4;
    float s0 = 0.f, s1 = 0.f, s2 = 0.f, s3 = 0.f;
    const float* cdp = g_cd + b * NCHUNK * NHEADS + h;
    for (int c = 0; c < NCHUNK; c++) {
        size_t base = ((size_t)((b*NCHUNK + c)*NHEADS + h) << 12) + off;
        float cd = cdp[c * NHEADS];
        float4 t = *(const float4*)&g_S[base];
        *(float4*)&g_S[base] = make_float4(s0, s1, s2, s3);
        s0 = fmaf(cd, s0, t.x);
        s1 = fmaf(cd, s1, t.y);
        s2 = fmaf(cd, s2, t.z);
        s3 = fmaf(cd, s3, t.w);
    }
}

// ---------------- Y_off + D skip + z gating ----------------
__launch_bounds__(256)
__global__ void k_off(const float* __restrict__ Dp)
{
    __shared__ float sST[64*68];
    __shared__ float sCT[64*68];
    const int h = blockIdx.x, c = blockIdx.y, b = blockIdx.z;
    const int tid = threadIdx.x;
    size_t sbase = (size_t)((b*NCHUNK + c)*NHEADS + h) * 4096;
#pragma unroll
    for (int it = 0; it < 4; it++) {
        int idx = tid + it*256;
        int r = idx >> 4;
        int n4 = (idx & 15) << 2;
        float4 sv = *(const float4*)&g_S[sbase + r*64 + n4];
        sST[(n4+0)*68 + r] = sv.x; sST[(n4+1)*68 + r] = sv.y;
        sST[(n4+2)*68 + r] = sv.z; sST[(n4+3)*68 + r] = sv.w;
        int row_g = b*SEQ + c*64 + r;
        float4 cv = *(const float4*)&g_Cv[row_g*64 + n4];
        sCT[(n4+0)*68 + r] = cv.x; sCT[(n4+1)*68 + r] = cv.y;
        sCT[(n4+2)*68 + r] = cv.z; sCT[(n4+3)*68 + r] = cv.w;
    }
    __syncthreads();
    const int ti = tid >> 4, tj = tid & 15;
    const int l0 = ti*4, p0 = tj*4;
    float acc[4][4];
#pragma unroll
    for (int i = 0; i < 4; i++)
#pragma unroll
        for (int j = 0; j < 4; j++) acc[i][j] = 0.f;
#pragma unroll
    for (int n = 0; n < 64; n++) {
        float4 cl = *(const float4*)&sCT[n*68 + l0];
        float4 sp = *(const float4*)&sST[n*68 + p0];
        float clv[4] = {cl.x, cl.y, cl.z, cl.w};
        float spv[4] = {sp.x, sp.y, sp.z, sp.w};
#pragma unroll
        for (int i = 0; i < 4; i++)
#pragma unroll
            for (int j = 0; j < 4; j++)
                acc[i][j] = fmaf(clv[i], spv[j], acc[i][j]);
    }
    float Dh = Dp[h];
#pragma unroll
    for (int i = 0; i < 4; i++) {
        int l = l0 + i;
        int row_g = b*SEQ + c*64 + l;
        float e = g_eA[((b*NCHUNK + c)*NHEADS + h)*64 + l];
        const float* pr = g_P + (size_t)row_g*NPROJ;
        float4 xc = *(const float4*)&pr[OFF_XC + h*64 + p0];
        float4 zz = *(const float4*)&pr[OFF_Z  + h*64 + p0];
        float* yp = &g_Y[(size_t)row_g*D_INNER + h*64 + p0];
        float4 yd = *(const float4*)yp;
        float4 o;
        o.x = (yd.x + e*acc[i][0] + Dh*siluf(xc.x)) * siluf(zz.x);
        o.y = (yd.y + e*acc[i][1] + Dh*siluf(xc.y)) * siluf(zz.y);
        o.z = (yd.z + e*acc[i][2] + Dh*siluf(xc.z)) * siluf(zz.z);
        o.w = (yd.w + e*acc[i][3] + Dh*siluf(xc.w)) * siluf(zz.w);
        *(float4*)yp = o;
    }
}

// ---------------- rmsnorm over 4096 per row -> bf16 hi/lo ----------------
__global__ void k_rms()
{
    int row = blockIdx.x;
    int tid = threadIdx.x;
    const float* Yp = g_Y + (size_t)row * D_INNER;
    float4 v[4];
    float ss = 0.f;
#pragma unroll
    for (int i = 0; i < 4; i++) {
        v[i] = *(const float4*)&Yp[tid*16 + i*4];
        ss += v[i].x*v[i].x + v[i].y*v[i].y + v[i].z*v[i].z + v[i].w*v[i].w;
    }
#pragma unroll
    for (int o = 16; o; o >>= 1) ss += __shfl_xor_sync(0xffffffffu, ss, o);
    __shared__ float red[8];
    if ((tid & 31) == 0) red[tid >> 5] = ss;
    __syncthreads();
    float tot = 0.f;
#pragma unroll
    for (int i = 0; i < 8; i++) tot += red[i];
    float r = rsqrtf(tot * (1.f/4096.f) + RMS_EPS);
    size_t base = (size_t)row * D_INNER + tid*16;
#pragma unroll
    for (int i = 0; i < 4; i++) {
        float vv[4] = {v[i].x*r, v[i].y*r, v[i].z*r, v[i].w*r};
#pragma unroll
        for (int k = 0; k < 4; k++) {
            __nv_bfloat16 h = __float2bfloat16(vv[k]);
            g_Yh[base + i*4 + k] = h;
            g_Yl[base + i*4 + k] = __float2bfloat16(vv[k] - __bfloat162float(h));
        }
    }
}

// ---------------- launcher ----------------
extern "C" void kernel_launch(void* const* d_in, const int* in_sizes, int n_in,
                              void* d_out, int out_size)
{
    const float* x    = (const float*)d_in[0];
    const float* Win  = (const float*)d_in[1];
    const float* Wth  = (const float*)d_in[2];
    const float* Wla  = (const float*)d_in[3];
    const float* Wout = (const float*)d_in[4];
    const float* Bb   = (const float*)d_in[5];
    const float* Cb   = (const float*)d_in[6];
    const float* Alog = (const float*)d_in[7];
    const float* Dp   = (const float*)d_in[8];
    const float* dtb  = (const float*)d_in[9];
    float* out = (float*)d_out;

    __nv_bfloat16 *pWq, *pWoq, *pxh, *pxl, *pYh, *pYl;
    float *pWs, *pWos, *pP;
    cudaGetSymbolAddress((void**)&pWq,  g_Wq);
    cudaGetSymbolAddress((void**)&pWs,  g_Ws);
    cudaGetSymbolAddress((void**)&pWoq, g_Woq);
    cudaGetSymbolAddress((void**)&pWos, g_Wos);
    cudaGetSymbolAddress((void**)&pxh,  g_xh);
    cudaGetSymbolAddress((void**)&pxl,  g_xl);
    cudaGetSymbolAddress((void**)&pYh,  g_Yh);
    cudaGetSymbolAddress((void**)&pYl,  g_Yl);
    cudaGetSymbolAddress((void**)&pP,   g_P);

    const int smem1 = (SS_OFF * 2) + 16 * 132 * 4;   // 92160 + 8448
    const int smem2 = (SS_OFF * 2) + 32 * 132 * 4;   // 92160 + 16896

    cudaFuncSetAttribute(k_chunk,    cudaFuncAttributeMaxDynamicSharedMemorySize, SM_CHUNK_BYTES);
    cudaFuncSetAttribute(k_mmq<16>,  cudaFuncAttributeMaxDynamicSharedMemorySize, smem1);
    cudaFuncSetAttribute(k_mmq<32>,  cudaFuncAttributeMaxDynamicSharedMemorySize, smem2);

    // fq4 dequant -> q + scales into fused weight buffer (pad rows stay zero)
    k_dequantq<<<(8384*16 + 3)/4, 128>>>(Win, pWq, pWs, 8384*16);
    k_dequantq<<<(512 + 3)/4,    128>>>(Wth, pWq + (size_t)8384*DIMK, pWs + (size_t)8384*16, 512);
    k_dequantq<<<(1024 + 3)/4,   128>>>(Wla, pWq + (size_t)8416*DIMK, pWs + (size_t)8416*16, 1024);
    k_dequantq<<<65536/4,        128>>>(Wout, pWoq, pWos, 65536);

    // split activations
    k_split<<<ROWS*DIMK/1024, 256>>>(x, pxh, pxl);

    // in-projection GEMM: 8192 x 8480 x 2048 (2-term + group-scale fold)
    k_mmq<16><<<dim3(ROWS/128, NPROJ_PAD/128), 512, smem1>>>(
        pxh, pxl, pWq, pWs, pP, NPROJ, NPROJ, DIMK);

    k_point<<<ROWS, 64>>>(Bb, Cb, Alog, dtb);
    k_scan <<<64, 256>>>();
    k_rope <<<ROWS, 32>>>();

    k_chunk<<<dim3(NHEADS, NCHUNK, BATCH), 256, SM_CHUNK_BYTES>>>();
    k_cscan<<<512, 256>>>();
    k_off  <<<dim3(NHEADS, NCHUNK, BATCH), 256>>>(Dp);

    k_rms<<<ROWS, 256>>>();

    // out-projection GEMM: 8192 x 2048 x 4096 (2-term + group-scale fold)
    k_mmq<32><<<dim3(ROWS/128, DIMK/128), 512, smem2>>>(
        pYh, pYl, pWoq, pWos, out, DIMK, DIMK, D_INNER);
}

// round 10
// speedup vs baseline: 1.5198x; 1.0700x over previous
#include <cuda_runtime.h>
#include <cuda_bf16.h>
#include <math.h>
#include <stdint.h>

#define SEQ     4096
#define BATCH   2
#define ROWS    (BATCH*SEQ)     // 8192
#define DIMK    2048
#define D_INNER 4096
#define NHEADS  64
#define NPROJ   8480            // 8384 (in_proj) + 32 (theta) + 64 (lambda)
#define NPROJ_PAD 8576          // 67 * 128
#define OFF_Z   0
#define OFF_XC  4096
#define OFF_B   8192
#define OFF_C   8256
#define OFF_DT  8320
#define OFF_TH  8384
#define OFF_LAM 8416
#define NCHUNK  64
#define RMS_EPS 1.1920929e-07f

// ---------------- device scratch (no allocation allowed) ----------------
__device__ __nv_bfloat16 g_Wq [NPROJ_PAD * DIMK];   // fused in-proj q (4-bit ints, exact in bf16)
__device__ float         g_Ws [NPROJ_PAD * 16];     // per-group scales (16 groups of 128 per row)
__device__ __nv_bfloat16 g_Woq[DIMK * D_INNER];     // out-proj q
__device__ float         g_Wos[DIMK * 32];          // out-proj scales (32 groups per row)
__device__ __nv_bfloat16 g_xh [ROWS * DIMK];
__device__ __nv_bfloat16 g_xl [ROWS * DIMK];
__device__ __nv_bfloat16 g_Yh [ROWS * D_INNER];
__device__ __nv_bfloat16 g_Yl [ROWS * D_INNER];
__device__ float g_P [ROWS * NPROJ];                // projection output
__device__ float g_Bv[ROWS * 64];
__device__ float g_Cv[ROWS * 64];
__device__ float g_Ad[ROWS * 64];
__device__ float g_ga[ROWS * 64];
__device__ float g_be[ROWS * 64];
__device__ float g_td[ROWS * 32];
__device__ float g_Y [ROWS * D_INNER];
__device__ float g_S [BATCH * NCHUNK * NHEADS * 64 * 64];
__device__ float g_eA[BATCH * NCHUNK * NHEADS * 64];
__device__ float g_cd[BATCH * NCHUNK * NHEADS];

__device__ __forceinline__ float siluf(float x) { return x / (1.f + expf(-x)); }

__device__ __forceinline__ uint32_t s2u(const void* p) {
    uint32_t a;
    asm("{ .reg .u64 t; cvta.to.shared.u64 t, %1; cvt.u32.u64 %0, t; }" : "=r"(a) : "l"(p));
    return a;
}

// ================= quant-aware emulated-fp32 GEMM via mma.sync =================
// C[M,Nw] = A[M,K] * B[N,K]^T where B = q * scale(group of 128 along K).
// A pre-split into bf16 hi/lo (2 MMA terms), q exact in bf16, scale folded in fp32
// at each 128-K group boundary.
// CTA 128x128, 16 warps (4x4) of 32x32 warp tiles, K-chunk 64,
// THREE-stage cp.async ring: 1 barrier per 64-K chunk, depth-2 prefetch.
#define PADH 72                      // 64 halves + 8 pad (144B pitch: 16B-aligned, conflict-free)
#define ARR_H (128*PADH)             // 9216 halves per sub-tile
#define BUF_H (3*ARR_H)              // Ah, Al, Bq per stage (27648 halves)
#define SS_OFF (3*BUF_H)             // halves offset where fp32 scales start (3 stages)

__device__ __forceinline__ void cpasync16(uint32_t dst, const void* src) {
    asm volatile("cp.async.cg.shared.global [%0], [%1], 16;" :: "r"(dst), "l"(src));
}
#define CP_COMMIT() asm volatile("cp.async.commit_group;" ::: "memory")
#define CP_WAITG1() asm volatile("cp.async.wait_group 1;" ::: "memory")

#define LDSM4(r0,r1,r2,r3,a) \
    asm volatile("ldmatrix.sync.aligned.m8n8.x4.shared.b16 {%0,%1,%2,%3}, [%4];" \
        : "=r"(r0),"=r"(r1),"=r"(r2),"=r"(r3) : "r"(a))

#define MMA16816(d,a,b0,b1) \
    asm volatile("mma.sync.aligned.m16n8k16.row.col.f32.bf16.bf16.f32 " \
        "{%0,%1,%2,%3}, {%4,%5,%6,%7}, {%8,%9}, {%0,%1,%2,%3};" \
        : "+f"((d)[0]),"+f"((d)[1]),"+f"((d)[2]),"+f"((d)[3]) \
        : "r"((a)[0]),"r"((a)[1]),"r"((a)[2]),"r"((a)[3]),"r"(b0),"r"(b1))

template<int NG>
__global__ void __launch_bounds__(512, 1)
k_mmq(const __nv_bfloat16* __restrict__ Ah, const __nv_bfloat16* __restrict__ Al,
      const __nv_bfloat16* __restrict__ Bq, const float* __restrict__ Bs,
      float* __restrict__ C, int Nw, int Nlim, int K)
{
    extern __shared__ __nv_bfloat16 sh[];
    float* ss = (float*)(sh + SS_OFF);        // [NG][132] scales for this CTA's n-range
    const uint32_t sb = s2u(sh);
    const int tid  = threadIdx.x;
    const int lane = tid & 31;
    const int wid  = tid >> 5;                // 0..15
    const int m0 = blockIdx.x * 128;
    const int n0 = blockIdx.y * 128;
    const int mw = (wid >> 2) * 32;
    const int nw = (wid & 3) * 32;

    // preload scales for the CTA's 128 weight rows
    for (int idx = tid; idx < 128 * NG; idx += 512) {
        int g = idx >> 7, nl = idx & 127;
        ss[g * 132 + nl] = Bs[(size_t)(n0 + nl) * NG + g];
    }

    float acc[2][4][4];
#pragma unroll
    for (int i = 0; i < 2; i++)
#pragma unroll
        for (int j = 0; j < 4; j++)
#pragma unroll
            for (int k = 0; k < 4; k++) acc[i][j][k] = 0.f;

    const int NK = K >> 6;     // 64-K chunks

    // fill one 64-K chunk into stage buf: 3 arrays x 128 rows x 128B = 3072 x 16B ops
#define FILLQ(buf, kc) do {                                                      \
        int kb = (kc) * 64;                                                      \
_Pragma("unroll")                                                                \
        for (int i = 0; i < 6; i++) {                                            \
            int idx = i * 512 + tid;                                             \
            int arr = idx >> 10;                                                 \
            int r   = (idx >> 3) & 127;                                          \
            int c   = idx & 7;                                                   \
            const __nv_bfloat16* sp = (arr == 0) ? (Ah + (size_t)(m0 + r) * K)   \
                                    : (arr == 1) ? (Al + (size_t)(m0 + r) * K)   \
                                                 : (Bq + (size_t)(n0 + r) * K);  \
            uint32_t dp = sb + ((buf) * BUF_H + arr * ARR_H + r * PADH + c * 8) * 2; \
            cpasync16(dp, sp + kb + c * 8);                                      \
        }                                                                        \
    } while (0)

    // prologue: prefetch chunks 0 and 1 (NK >= 2 always)
    FILLQ(0, 0);
    CP_COMMIT();
    FILLQ(1, 1);
    CP_COMMIT();

    const int rowoff = (lane & 7) + ((lane >> 3) & 1) * 8;
    const int coloff = (lane >> 4) * 8;
    const int c0 = (lane & 3) * 2;

    for (int g = 0; g < NG; g++) {
        float accg[2][4][4];
#pragma unroll
        for (int i = 0; i < 2; i++)
#pragma unroll
            for (int j = 0; j < 4; j++)
#pragma unroll
                for (int k = 0; k < 4; k++) accg[i][j][k] = 0.f;

#pragma unroll
        for (int kq = 0; kq < 2; kq++) {
            const int kc = g * 2 + kq;
            const int buf = kc % 3;

            // fill(kc) complete when at most 1 group (fill kc+1) pending
            CP_WAITG1();
            __syncthreads();   // orders prior reads of stage (kc+2)%3 before refill

            if (kc + 2 < NK) FILLQ((kc + 2) % 3, kc + 2);
            CP_COMMIT();       // exactly one group per iteration (possibly empty)

#pragma unroll
            for (int kk = 0; kk < 4; kk++) {
                uint32_t afr[2][2][4];
                uint32_t bfr[2][4];
#pragma unroll
                for (int hl = 0; hl < 2; hl++)
#pragma unroll
                    for (int mi = 0; mi < 2; mi++) {
                        uint32_t a = sb + (buf * BUF_H + hl * ARR_H +
                            (mw + mi * 16 + rowoff) * PADH + kk * 16 + coloff) * 2;
                        LDSM4(afr[hl][mi][0], afr[hl][mi][1], afr[hl][mi][2], afr[hl][mi][3], a);
                    }
#pragma unroll
                for (int nj = 0; nj < 2; nj++) {
                    uint32_t a = sb + (buf * BUF_H + 2 * ARR_H +
                        (nw + nj * 16 + rowoff) * PADH + kk * 16 + coloff) * 2;
                    LDSM4(bfr[nj][0], bfr[nj][1], bfr[nj][2], bfr[nj][3], a);
                }
#pragma unroll
                for (int term = 0; term < 2; term++)
#pragma unroll
                    for (int mi = 0; mi < 2; mi++)
#pragma unroll
                        for (int ni = 0; ni < 4; ni++) {
                            int nj = ni >> 1, s = ni & 1;
                            MMA16816(accg[mi][ni], afr[term][mi],
                                     bfr[nj][s], bfr[nj][s + 2]);
                        }
            }
        }

        // fold group scales (per output column n)
#pragma unroll
        for (int ni = 0; ni < 4; ni++) {
            float2 sv = *(const float2*)&ss[g * 132 + nw + ni * 8 + c0];
#pragma unroll
            for (int mi = 0; mi < 2; mi++) {
                acc[mi][ni][0] = fmaf(sv.x, accg[mi][ni][0], acc[mi][ni][0]);
                acc[mi][ni][1] = fmaf(sv.y, accg[mi][ni][1], acc[mi][ni][1]);
                acc[mi][ni][2] = fmaf(sv.x, accg[mi][ni][2], acc[mi][ni][2]);
                acc[mi][ni][3] = fmaf(sv.y, accg[mi][ni][3], acc[mi][ni][3]);
            }
        }
    }

    // epilogue
    const int r0 = lane >> 2;
#pragma unroll
    for (int mi = 0; mi < 2; mi++) {
#pragma unroll
        for (int ni = 0; ni < 4; ni++) {
            int m = m0 + mw + mi * 16 + r0;
            int n = n0 + nw + ni * 8 + c0;
            if (n < Nlim) {
                *(float2*)&C[(size_t)m * Nw + n]       = make_float2(acc[mi][ni][0], acc[mi][ni][1]);
                *(float2*)&C[(size_t)(m + 8) * Nw + n] = make_float2(acc[mi][ni][2], acc[mi][ni][3]);
            }
        }
    }
#undef FILLQ
}

// ---------------- fq4 dequantization -> q (bf16, exact) + group scale ----------------
__global__ void k_dequantq(const float* __restrict__ src, __nv_bfloat16* __restrict__ dq,
                           float* __restrict__ ds, int ngroups)
{
    int g = blockIdx.x * 4 + (threadIdx.x >> 5);
    if (g >= ngroups) return;
    int lane = threadIdx.x & 31;
    const float* s = src + (size_t)g * 128;
    float v[4];
    float m = 0.f;
#pragma unroll
    for (int i = 0; i < 4; i++) { v[i] = s[lane + 32*i]; m = fmaxf(m, fabsf(v[i])); }
#pragma unroll
    for (int o = 16; o; o >>= 1) m = fmaxf(m, __shfl_xor_sync(0xffffffffu, m, o));
    float scale = fmaxf(m, 1e-10f) / 7.0f;
    if (lane == 0) ds[g] = scale;
#pragma unroll
    for (int i = 0; i < 4; i++) {
        float q = rintf(v[i] / scale);
        q = fminf(fmaxf(q, -8.f), 7.f);
        dq[(size_t)g * 128 + lane + 32*i] = __float2bfloat16(q);  // exact (small int)
    }
}

// ---------------- split fp32 -> bf16 hi/lo ----------------
__global__ void k_split(const float* __restrict__ src, __nv_bfloat16* __restrict__ dh,
                        __nv_bfloat16* __restrict__ dl)
{
    size_t i = ((size_t)blockIdx.x * 256 + threadIdx.x) * 4;
    float4 v = *(const float4*)(src + i);
    float vv[4] = {v.x, v.y, v.z, v.w};
#pragma unroll
    for (int k = 0; k < 4; k++) {
        __nv_bfloat16 h = __float2bfloat16(vv[k]);
        dh[i + k] = h;
        dl[i + k] = __float2bfloat16(vv[k] - __bfloat162float(h));
    }
}

// ---------------- pointwise epilogue per (b,l) row: 64 threads ----------------
__global__ void k_point(const float* __restrict__ Bb, const float* __restrict__ Cb,
                        const float* __restrict__ Alog, const float* __restrict__ dtb)
{
    int row = blockIdx.x;
    int t = threadIdx.x;
    const float* pr = g_P + (size_t)row * NPROJ;
    __shared__ float red[6];

    float dtr = pr[OFF_DT + t] + dtb[t];
    float dt = (dtr > 20.f) ? dtr : log1pf(expf(dtr));
    float Ad = -expf(Alog[t]) * dt;
    float lam = 1.f / (1.f + expf(-pr[OFF_LAM + t]));
    g_Ad[row*64 + t] = Ad;
    g_ga[row*64 + t] = lam * dt;
    g_be[row*64 + t] = (1.f - lam) * dt * expf(Ad);

    float bv = pr[OFF_B + t];
    float cv = pr[OFF_C + t];

    float s0 = dt, s1 = bv*bv, s2 = cv*cv;
#pragma unroll
    for (int o = 16; o; o >>= 1) {
        s0 += __shfl_xor_sync(0xffffffffu, s0, o);
        s1 += __shfl_xor_sync(0xffffffffu, s1, o);
        s2 += __shfl_xor_sync(0xffffffffu, s2, o);
    }
    int w = t >> 5;
    if ((t & 31) == 0) { red[w*3+0] = s0; red[w*3+1] = s1; red[w*3+2] = s2; }
    __syncthreads();
    float dt_avg = (red[0] + red[3]) * (1.f/64.f);
    float rb = rsqrtf((red[1] + red[4]) * (1.f/64.f) + RMS_EPS);
    float rc = rsqrtf((red[2] + red[5]) * (1.f/64.f) + RMS_EPS);

    g_Bv[row*64 + t] = bv * rb + Bb[t];
    g_Cv[row*64 + t] = cv * rc + Cb[t];
    if (t < 32) g_td[row*32 + t] = pr[OFF_TH + t] * dt_avg;
}

// ---------------- cumsum of theta*dt_avg over L per (b, n) ----------------
__global__ void k_scan()
{
    int b = blockIdx.x >> 5;
    int n = blockIdx.x & 31;
    int tid = threadIdx.x;
    __shared__ float ps[256];
    float loc[16];
    float run = 0.f;
    int base = (b*SEQ + tid*16) * 32 + n;
#pragma unroll
    for (int j = 0; j < 16; j++) { run += g_td[base + j*32]; loc[j] = run; }
    ps[tid] = run;
    __syncthreads();
#pragma unroll
    for (int o = 1; o < 256; o <<= 1) {
        float v = (tid >= o) ? ps[tid - o] : 0.f;
        __syncthreads();
        ps[tid] += v;
        __syncthreads();
    }
    float off = (tid > 0) ? ps[tid - 1] : 0.f;
#pragma unroll
    for (int j = 0; j < 16; j++) g_td[base + j*32] = loc[j] + off;
}

// ---------------- rope on B and C (in place) ----------------
__global__ void k_rope()
{
    int row = blockIdx.x;
    int t = threadIdx.x;
    float a = g_td[row*32 + t];
    float ca = cosf(a), sa = sinf(a);
    float br = g_Bv[row*64 + t], bi = g_Bv[row*64 + 32 + t];
    g_Bv[row*64 + t]      = br*ca - bi*sa;
    g_Bv[row*64 + 32 + t] = br*sa + bi*ca;
    float cr = g_Cv[row*64 + t], ci = g_Cv[row*64 + 32 + t];
    g_Cv[row*64 + t]      = cr*ca - ci*sa;
    g_Cv[row*64 + 32 + t] = cr*sa + ci*ca;
}

// ---------------- intra-chunk: Y_diag + per-chunk states ----------------
#define SM_CHUNK_BYTES ((4352*5 + 128) * 4)
__launch_bounds__(256)
__global__ void k_chunk()
{
    extern __shared__ float sm[];
    float* sX  = sm;
    float* sB  = sm + 4352;
    float* sBT = sm + 8704;
    float* sCT = sm + 13056;
    float* sGT = sm + 17408;
    float* sA  = sm + 21760;
    float* sW  = sm + 21824;

    const int h = blockIdx.x, c = blockIdx.y, b = blockIdx.z;
    const int tid = threadIdx.x;

    if (tid < 64) {
        int row_g = b*SEQ + c*64 + tid;
        sA[tid] = g_Ad[row_g*64 + h];
    }
    __syncthreads();
#pragma unroll
    for (int o = 1; o < 64; o <<= 1) {
        float v = (tid < 64 && tid >= o) ? sA[tid - o] : 0.f;
        __syncthreads();
        if (tid < 64) sA[tid] += v;
        __syncthreads();
    }
    float Alast = sA[63];
    if (tid < 64) {
        sW[tid] = expf(Alast - sA[tid]);
        g_eA[((b*NCHUNK + c)*NHEADS + h)*64 + tid] = expf(sA[tid]);
    }
    if (tid == 0) g_cd[(b*NCHUNK + c)*NHEADS + h] = expf(Alast);

#pragma unroll
    for (int it = 0; it < 4; it++) {
        int idx = tid + it*256;
        int l = idx >> 4;
        int p4 = (idx & 15) << 2;
        int row_g = b*SEQ + c*64 + l;
        const float* xp = g_P + (size_t)row_g*NPROJ + OFF_XC + h*64 + p4;
        float4 xc = *(const float4*)xp;
        float ga = g_ga[row_g*64 + h];
        float be = g_be[row_g*64 + h];
        float4 xv;
        xv.x = siluf(xc.x)*ga; xv.y = siluf(xc.y)*ga; xv.z = siluf(xc.z)*ga; xv.w = siluf(xc.w)*ga;
        if (c*64 + l > 0) {
            float4 xq = *(const float4*)(xp - NPROJ);
            xv.x += siluf(xq.x)*be; xv.y += siluf(xq.y)*be; xv.z += siluf(xq.z)*be; xv.w += siluf(xq.w)*be;
        }
        *(float4*)&sX[l*68 + p4] = xv;
        float4 bb = *(const float4*)&g_Bv[row_g*64 + p4];
        *(float4*)&sB[l*68 + p4] = bb;
        sBT[(p4+0)*68 + l] = bb.x; sBT[(p4+1)*68 + l] = bb.y;
        sBT[(p4+2)*68 + l] = bb.z; sBT[(p4+3)*68 + l] = bb.w;
        float4 cc = *(const float4*)&g_Cv[row_g*64 + p4];
        sCT[(p4+0)*68 + l] = cc.x; sCT[(p4+1)*68 + l] = cc.y;
        sCT[(p4+2)*68 + l] = cc.z; sCT[(p4+3)*68 + l] = cc.w;
    }
    __syncthreads();

    const int ti = tid >> 4, tj = tid & 15;

    // G tile (ti,tj) is fully masked (s > l everywhere) when tj > ti, and
    // Y_diag's truncated loop never reads those entries -> skip entirely.
    if (tj <= ti) {
        const int l0 = ti*4, s0 = tj*4;
        float acc[4][4];
#pragma unroll
        for (int i = 0; i < 4; i++)
#pragma unroll
            for (int j = 0; j < 4; j++) acc[i][j] = 0.f;
#pragma unroll
        for (int n = 0; n < 64; n++) {
            float4 cl = *(const float4*)&sCT[n*68 + l0];
            float4 bs = *(const float4*)&sBT[n*68 + s0];
            float clv[4] = {cl.x, cl.y, cl.z, cl.w};
            float bsv[4] = {bs.x, bs.y, bs.z, bs.w};
#pragma unroll
            for (int i = 0; i < 4; i++)
#pragma unroll
                for (int j = 0; j < 4; j++)
                    acc[i][j] = fmaf(clv[i], bsv[j], acc[i][j]);
        }
        float al[4];
#pragma unroll
        for (int i = 0; i < 4; i++) al[i] = sA[l0 + i];
#pragma unroll
        for (int j = 0; j < 4; j++) {
            int s = s0 + j;
            float as = sA[s];
#pragma unroll
            for (int i = 0; i < 4; i++) {
                int l = l0 + i;
                sGT[s*68 + l] = (s <= l) ? acc[i][j] * expf(al[i] - as) : 0.f;
            }
        }
    }
    __syncthreads();

    {
        const int l0 = ti*4, p0 = tj*4;
        float acc[4][4];
#pragma unroll
        for (int i = 0; i < 4; i++)
#pragma unroll
            for (int j = 0; j < 4; j++) acc[i][j] = 0.f;
        const int smax = l0 + 4;
#pragma unroll 4
        for (int s = 0; s < smax; s++) {
            float4 gt = *(const float4*)&sGT[s*68 + l0];
            float4 xr = *(const float4*)&sX[s*68 + p0];
            float gv[4] = {gt.x, gt.y, gt.z, gt.w};
            float xvv[4] = {xr.x, xr.y, xr.z, xr.w};
#pragma unroll
            for (int i = 0; i < 4; i++)
#pragma unroll
                for (int j = 0; j < 4; j++)
                    acc[i][j] = fmaf(gv[i], xvv[j], acc[i][j]);
        }
#pragma unroll
        for (int i = 0; i < 4; i++) {
            int row_g = b*SEQ + c*64 + l0 + i;
            *(float4*)&g_Y[(size_t)row_g*D_INNER + h*64 + p0] =
                make_float4(acc[i][0], acc[i][1], acc[i][2], acc[i][3]);
        }
    }

    {
        const int p0 = ti*4, n0 = tj*4;
        float acc[4][4];
#pragma unroll
        for (int i = 0; i < 4; i++)
#pragma unroll
            for (int j = 0; j < 4; j++) acc[i][j] = 0.f;
#pragma unroll
        for (int l = 0; l < 64; l++) {
            float w = sW[l];
            float4 xr = *(const float4*)&sX[l*68 + p0];
            float4 br = *(const float4*)&sB[l*68 + n0];
            float wx[4] = {w*xr.x, w*xr.y, w*xr.z, w*xr.w};
            float bvv[4] = {br.x, br.y, br.z, br.w};
#pragma unroll
            for (int i = 0; i < 4; i++)
#pragma unroll
                for (int j = 0; j < 4; j++)
                    acc[i][j] = fmaf(wx[i], bvv[j], acc[i][j]);
        }
        size_t base = (size_t)((b*NCHUNK + c)*NHEADS + h) * 4096;
#pragma unroll
        for (int i = 0; i < 4; i++)
            *(float4*)&g_S[base + (p0 + i)*64 + n0] =
                make_float4(acc[i][0], acc[i][1], acc[i][2], acc[i][3]);
    }
}

// ---------------- inter-chunk scan: 512 CTAs, one (b,h,quarter) each ----------------
__global__ void k_cscan()
{
    int q = blockIdx.x & 3;
    int h = (blockIdx.x >> 2) & 63;
    int b = blockIdx.x >> 8;
    int tid = threadIdx.x;
    int off = q * 1024 + tid * 4;
    float s0 = 0.f, s1 = 0.f, s2 = 0.f, s3 = 0.f;
    const float* cdp = g_cd + b * NCHUNK * NHEADS + h;
    for (int c = 0; c < NCHUNK; c++) {
        size_t base = ((size_t)((b*NCHUNK + c)*NHEADS + h) << 12) + off;
        float cd = cdp[c * NHEADS];
        float4 t = *(const float4*)&g_S[base];
        *(float4*)&g_S[base] = make_float4(s0, s1, s2, s3);
        s0 = fmaf(cd, s0, t.x);
        s1 = fmaf(cd, s1, t.y);
        s2 = fmaf(cd, s2, t.z);
        s3 = fmaf(cd, s3, t.w);
    }
}

// ---------------- Y_off + D skip + z gating ----------------
__launch_bounds__(256)
__global__ void k_off(const float* __restrict__ Dp)
{
    __shared__ float sST[64*68];
    __shared__ float sCT[64*68];
    const int h = blockIdx.x, c = blockIdx.y, b = blockIdx.z;
    const int tid = threadIdx.x;
    size_t sbase = (size_t)((b*NCHUNK + c)*NHEADS + h) * 4096;
#pragma unroll
    for (int it = 0; it < 4; it++) {
        int idx = tid + it*256;
        int r = idx >> 4;
        int n4 = (idx & 15) << 2;
        float4 sv = *(const float4*)&g_S[sbase + r*64 + n4];
        sST[(n4+0)*68 + r] = sv.x; sST[(n4+1)*68 + r] = sv.y;
        sST[(n4+2)*68 + r] = sv.z; sST[(n4+3)*68 + r] = sv.w;
        int row_g = b*SEQ + c*64 + r;
        float4 cv = *(const float4*)&g_Cv[row_g*64 + n4];
        sCT[(n4+0)*68 + r] = cv.x; sCT[(n4+1)*68 + r] = cv.y;
        sCT[(n4+2)*68 + r] = cv.z; sCT[(n4+3)*68 + r] = cv.w;
    }
    __syncthreads();
    const int ti = tid >> 4, tj = tid & 15;
    const int l0 = ti*4, p0 = tj*4;
    float acc[4][4];
#pragma unroll
    for (int i = 0; i < 4; i++)
#pragma unroll
        for (int j = 0; j < 4; j++) acc[i][j] = 0.f;
#pragma unroll
    for (int n = 0; n < 64; n++) {
        float4 cl = *(const float4*)&sCT[n*68 + l0];
        float4 sp = *(const float4*)&sST[n*68 + p0];
        float clv[4] = {cl.x, cl.y, cl.z, cl.w};
        float spv[4] = {sp.x, sp.y, sp.z, sp.w};
#pragma unroll
        for (int i = 0; i < 4; i++)
#pragma unroll
            for (int j = 0; j < 4; j++)
                acc[i][j] = fmaf(clv[i], spv[j], acc[i][j]);
    }
    float Dh = Dp[h];
#pragma unroll
    for (int i = 0; i < 4; i++) {
        int l = l0 + i;
        int row_g = b*SEQ + c*64 + l;
        float e = g_eA[((b*NCHUNK + c)*NHEADS + h)*64 + l];
        const float* pr = g_P + (size_t)row_g*NPROJ;
        float4 xc = *(const float4*)&pr[OFF_XC + h*64 + p0];
        float4 zz = *(const float4*)&pr[OFF_Z  + h*64 + p0];
        float* yp = &g_Y[(size_t)row_g*D_INNER + h*64 + p0];
        float4 yd = *(const float4*)yp;
        float4 o;
        o.x = (yd.x + e*acc[i][0] + Dh*siluf(xc.x)) * siluf(zz.x);
        o.y = (yd.y + e*acc[i][1] + Dh*siluf(xc.y)) * siluf(zz.y);
        o.z = (yd.z + e*acc[i][2] + Dh*siluf(xc.z)) * siluf(zz.z);
        o.w = (yd.w + e*acc[i][3] + Dh*siluf(xc.w)) * siluf(zz.w);
        *(float4*)yp = o;
    }
}

// ---------------- rmsnorm over 4096 per row -> bf16 hi/lo ----------------
__global__ void k_rms()
{
    int row = blockIdx.x;
    int tid = threadIdx.x;
    const float* Yp = g_Y + (size_t)row * D_INNER;
    float4 v[4];
    float ss = 0.f;
#pragma unroll
    for (int i = 0; i < 4; i++) {
        v[i] = *(const float4*)&Yp[tid*16 + i*4];
        ss += v[i].x*v[i].x + v[i].y*v[i].y + v[i].z*v[i].z + v[i].w*v[i].w;
    }
#pragma unroll
    for (int o = 16; o; o >>= 1) ss += __shfl_xor_sync(0xffffffffu, ss, o);
    __shared__ float red[8];
    if ((tid & 31) == 0) red[tid >> 5] = ss;
    __syncthreads();
    float tot = 0.f;
#pragma unroll
    for (int i = 0; i < 8; i++) tot += red[i];
    float r = rsqrtf(tot * (1.f/4096.f) + RMS_EPS);
    size_t base = (size_t)row * D_INNER + tid*16;
#pragma unroll
    for (int i = 0; i < 4; i++) {
        float vv[4] = {v[i].x*r, v[i].y*r, v[i].z*r, v[i].w*r};
#pragma unroll
        for (int k = 0; k < 4; k++) {
            __nv_bfloat16 h = __float2bfloat16(vv[k]);
            g_Yh[base + i*4 + k] = h;
            g_Yl[base + i*4 + k] = __float2bfloat16(vv[k] - __bfloat162float(h));
        }
    }
}

// ---------------- launcher ----------------
extern "C" void kernel_launch(void* const* d_in, const int* in_sizes, int n_in,
                              void* d_out, int out_size)
{
    const float* x    = (const float*)d_in[0];
    const float* Win  = (const float*)d_in[1];
    const float* Wth  = (const float*)d_in[2];
    const float* Wla  = (const float*)d_in[3];
    const float* Wout = (const float*)d_in[4];
    const float* Bb   = (const float*)d_in[5];
    const float* Cb   = (const float*)d_in[6];
    const float* Alog = (const float*)d_in[7];
    const float* Dp   = (const float*)d_in[8];
    const float* dtb  = (const float*)d_in[9];
    float* out = (float*)d_out;

    __nv_bfloat16 *pWq, *pWoq, *pxh, *pxl, *pYh, *pYl;
    float *pWs, *pWos, *pP;
    cudaGetSymbolAddress((void**)&pWq,  g_Wq);
    cudaGetSymbolAddress((void**)&pWs,  g_Ws);
    cudaGetSymbolAddress((void**)&pWoq, g_Woq);
    cudaGetSymbolAddress((void**)&pWos, g_Wos);
    cudaGetSymbolAddress((void**)&pxh,  g_xh);
    cudaGetSymbolAddress((void**)&pxl,  g_xl);
    cudaGetSymbolAddress((void**)&pYh,  g_Yh);
    cudaGetSymbolAddress((void**)&pYl,  g_Yl);
    cudaGetSymbolAddress((void**)&pP,   g_P);

    const int smem1 = (SS_OFF * 2) + 16 * 132 * 4;   // 165888 + 8448  = 174336
    const int smem2 = (SS_OFF * 2) + 32 * 132 * 4;   // 165888 + 16896 = 182784

    cudaFuncSetAttribute(k_chunk,    cudaFuncAttributeMaxDynamicSharedMemorySize, SM_CHUNK_BYTES);
    cudaFuncSetAttribute(k_mmq<16>,  cudaFuncAttributeMaxDynamicSharedMemorySize, smem1);
    cudaFuncSetAttribute(k_mmq<32>,  cudaFuncAttributeMaxDynamicSharedMemorySize, smem2);

    // fq4 dequant -> q + scales into fused weight buffer (pad rows stay zero)
    k_dequantq<<<(8384*16 + 3)/4, 128>>>(Win, pWq, pWs, 8384*16);
    k_dequantq<<<(512 + 3)/4,    128>>>(Wth, pWq + (size_t)8384*DIMK, pWs + (size_t)8384*16, 512);
    k_dequantq<<<(1024 + 3)/4,   128>>>(Wla, pWq + (size_t)8416*DIMK, pWs + (size_t)8416*16, 1024);
    k_dequantq<<<65536/4,        128>>>(Wout, pWoq, pWos, 65536);

    // split activations
    k_split<<<ROWS*DIMK/1024, 256>>>(x, pxh, pxl);

    // in-projection GEMM: 8192 x 8480 x 2048 (2-term + group-scale fold)
    k_mmq<16><<<dim3(ROWS/128, NPROJ_PAD/128), 512, smem1>>>(
        pxh, pxl, pWq, pWs, pP, NPROJ, NPROJ, DIMK);

    k_point<<<ROWS, 64>>>(Bb, Cb, Alog, dtb);
    k_scan <<<64, 256>>>();
    k_rope <<<ROWS, 32>>>();

    k_chunk<<<dim3(NHEADS, NCHUNK, BATCH), 256, SM_CHUNK_BYTES>>>();
    k_cscan<<<512, 256>>>();
    k_off  <<<dim3(NHEADS, NCHUNK, BATCH), 256>>>(Dp);

    k_rms<<<ROWS, 256>>>();

    // out-projection GEMM: 8192 x 2048 x 4096 (2-term + group-scale fold)
    k_mmq<32><<<dim3(ROWS/128, DIMK/128), 512, smem2>>>(
        pYh, pYl, pWoq, pWos, out, DIMK, DIMK, D_INNER);
}

// round 11
// speedup vs baseline: 1.6873x; 1.1102x over previous
#include <cuda.h>
#include <cuda_runtime.h>
#include <cuda_bf16.h>
#include <math.h>
#include <stdint.h>

#define SEQ     4096
#define BATCH   2
#define ROWS    (BATCH*SEQ)     // 8192
#define DIMK    2048
#define D_INNER 4096
#define NHEADS  64
#define NPROJ   8480            // 8384 (in_proj) + 32 (theta) + 64 (lambda)
#define NPROJ_PAD 8576          // 67 * 128
#define OFF_Z   0
#define OFF_XC  4096
#define OFF_B   8192
#define OFF_C   8256
#define OFF_DT  8320
#define OFF_TH  8384
#define OFF_LAM 8416
#define NCHUNK  64
#define RMS_EPS 1.1920929e-07f

// ---------------- device scratch (no allocation allowed) ----------------
__device__ __nv_bfloat16 g_Wq [NPROJ_PAD * DIMK];   // fused in-proj q (4-bit ints, exact in bf16)
__device__ float         g_Ws [NPROJ_PAD * 16];     // per-group scales (16 groups of 128 per row)
__device__ __nv_bfloat16 g_Woq[DIMK * D_INNER];     // out-proj q
__device__ float         g_Wos[DIMK * 32];          // out-proj scales (32 groups per row)
__device__ __nv_bfloat16 g_xh [ROWS * DIMK];
__device__ __nv_bfloat16 g_xl [ROWS * DIMK];
__device__ __nv_bfloat16 g_Yh [ROWS * D_INNER];
__device__ __nv_bfloat16 g_Yl [ROWS * D_INNER];
__device__ float g_P [ROWS * NPROJ];                // projection output
__device__ float g_Bv[ROWS * 64];
__device__ float g_Cv[ROWS * 64];
__device__ float g_Ad[ROWS * 64];
__device__ float g_ga[ROWS * 64];
__device__ float g_be[ROWS * 64];
__device__ float g_td[ROWS * 32];
__device__ float g_Y [ROWS * D_INNER];
__device__ float g_S [BATCH * NCHUNK * NHEADS * 64 * 64];
__device__ float g_eA[BATCH * NCHUNK * NHEADS * 64];
__device__ float g_cd[BATCH * NCHUNK * NHEADS];

__device__ __forceinline__ float siluf(float x) { return x / (1.f + expf(-x)); }

__device__ __forceinline__ uint32_t s2u(const void* p) {
    uint32_t a;
    asm("{ .reg .u64 t; cvta.to.shared.u64 t, %1; cvt.u32.u64 %0, t; }" : "=r"(a) : "l"(p));
    return a;
}

// ================= TMA-fed quant-aware emulated-fp32 GEMM =================
// C[M,Nw] = A[M,K] * B[N,K]^T where B = q * scale(group of 128 along K).
// A pre-split into bf16 hi/lo (2 MMA terms), q exact in bf16, scale folded in fp32
// at each 128-K group boundary.
// CTA 128x128, 16 warps (4x4) of 32x32 warp tiles, K-chunk 64,
// THREE-stage TMA ring (SW128), mbarrier expect_tx completion, depth-2 prefetch.
#define TILE_B  16384                 // one sub-tile: 128 rows x 128 bytes
#define STAGE_B (3*TILE_B)            // Ah | Al | Bq  = 49152 bytes
#define MB_OFF  (3*STAGE_B)           // 147456: three mbarriers live here
#define SSB_OFF (MB_OFF + 64)         // 147520: fp32 scales

#define SWZ(o) ((o) ^ ((((uint32_t)(o)) >> 3) & 0x70u))

#define LDSM4(r0,r1,r2,r3,a) \
    asm volatile("ldmatrix.sync.aligned.m8n8.x4.shared.b16 {%0,%1,%2,%3}, [%4];" \
        : "=r"(r0),"=r"(r1),"=r"(r2),"=r"(r3) : "r"(a))

#define MMA16816(d,a,b0,b1) \
    asm volatile("mma.sync.aligned.m16n8k16.row.col.f32.bf16.bf16.f32 " \
        "{%0,%1,%2,%3}, {%4,%5,%6,%7}, {%8,%9}, {%0,%1,%2,%3};" \
        : "+f"((d)[0]),"+f"((d)[1]),"+f"((d)[2]),"+f"((d)[3]) \
        : "r"((a)[0]),"r"((a)[1]),"r"((a)[2]),"r"((a)[3]),"r"(b0),"r"(b1))

#define MBAR_INIT(a, c) asm volatile("mbarrier.init.shared.b64 [%0], %1;" :: "r"(a), "r"(c) : "memory")
#define FENCE_ASYNC()   asm volatile("fence.proxy.async.shared::cta;" ::: "memory")
#define MBAR_EXPECT(a, bytes) \
    asm volatile("mbarrier.arrive.expect_tx.shared.b64 _, [%0], %1;" :: "r"(a), "r"(bytes) : "memory")

__device__ __forceinline__ void mbar_wait(uint32_t a, uint32_t ph) {
    asm volatile(
        "{\n\t.reg .pred P;\n\t"
        "WL%=:\n\tmbarrier.try_wait.parity.acquire.cta.shared::cta.b64 P, [%0], %1, 0x989680;\n\t"
        "@P bra WD%=;\n\tbra WL%=;\n\tWD%=:\n\t}"
        :: "r"(a), "r"(ph) : "memory");
}

__device__ __forceinline__ void tma2d(uint32_t dst, const CUtensorMap* m, int x, int y, uint32_t mbar) {
    asm volatile(
        "cp.async.bulk.tensor.2d.shared::cta.global.tile.mbarrier::complete_tx::bytes "
        "[%0], [%1, {%2, %3}], [%4];"
        :: "r"(dst), "l"(m), "r"(x), "r"(y), "r"(mbar) : "memory");
}

template<int NG>
__global__ void __launch_bounds__(512, 1)
k_mmt(const __grid_constant__ CUtensorMap tAh,
      const __grid_constant__ CUtensorMap tAl,
      const __grid_constant__ CUtensorMap tBq,
      const float* __restrict__ Bs, float* __restrict__ C,
      int Nw, int Nlim, int K)
{
    extern __shared__ __align__(1024) uint8_t sh8[];
    float* ss = (float*)(sh8 + SSB_OFF);
    const uint32_t sb = s2u(sh8);
    const uint32_t mb = sb + MB_OFF;
    const int tid  = threadIdx.x;
    const int lane = tid & 31;
    const int wid  = tid >> 5;                // 0..15
    const int m0 = blockIdx.x * 128;
    const int n0 = blockIdx.y * 128;
    const int mw = (wid >> 2) * 32;
    const int nw = (wid & 3) * 32;

    if (tid == 0) {
        MBAR_INIT(mb + 0, 1);
        MBAR_INIT(mb + 8, 1);
        MBAR_INIT(mb + 16, 1);
    }
    // preload scales for the CTA's 128 weight rows
    for (int idx = tid; idx < 128 * NG; idx += 512) {
        int g = idx >> 7, nl = idx & 127;
        ss[g * 132 + nl] = Bs[(size_t)(n0 + nl) * NG + g];
    }
    __syncthreads();

    const int NK = K >> 6;     // 64-K chunks

#define TFILL(buf, kc) do {                                   \
        uint32_t mba = mb + (buf) * 8;                        \
        MBAR_EXPECT(mba, 3 * TILE_B);                         \
        uint32_t d = sb + (buf) * STAGE_B;                    \
        tma2d(d,             &tAh, (kc) * 64, m0, mba);       \
        tma2d(d + TILE_B,    &tAl, (kc) * 64, m0, mba);       \
        tma2d(d + 2*TILE_B,  &tBq, (kc) * 64, n0, mba);       \
    } while (0)

    // prologue: prefetch chunks 0 and 1 (NK >= 2 always)
    if (tid == 0) {
        FENCE_ASYNC();
        TFILL(0, 0);
        TFILL(1, 1);
    }

    float acc[2][4][4];
#pragma unroll
    for (int i = 0; i < 2; i++)
#pragma unroll
        for (int j = 0; j < 4; j++)
#pragma unroll
            for (int k = 0; k < 4; k++) acc[i][j][k] = 0.f;

    const int rowoff = (lane & 7) + ((lane >> 3) & 1) * 8;   // 0..15
    const int colb2  = (lane >> 4) * 16;                     // byte offset 0 or 16
    const int c0 = (lane & 3) * 2;

    for (int g = 0; g < NG; g++) {
        float accg[2][4][4];
#pragma unroll
        for (int i = 0; i < 2; i++)
#pragma unroll
            for (int j = 0; j < 4; j++)
#pragma unroll
                for (int k = 0; k < 4; k++) accg[i][j][k] = 0.f;

#pragma unroll
        for (int kq = 0; kq < 2; kq++) {
            const int kc = g * 2 + kq;
            const int buf = kc % 3;
            const uint32_t ph = (kc / 3) & 1;

            mbar_wait(mb + buf * 8, ph);
            __syncthreads();   // all warps done reading stage (kc+2)%3 (used at kc-1)

            if (tid == 0 && kc + 2 < NK) {
                FENCE_ASYNC();
                TFILL((kc + 2) % 3, kc + 2);
            }

            const uint32_t stg = sb + buf * STAGE_B;
#pragma unroll
            for (int kk = 0; kk < 4; kk++) {
                uint32_t afr[2][2][4];
                uint32_t bfr[2][4];
#pragma unroll
                for (int hl = 0; hl < 2; hl++)
#pragma unroll
                    for (int mi = 0; mi < 2; mi++) {
                        uint32_t off = (uint32_t)(mw + mi * 16 + rowoff) * 128 + kk * 32 + colb2;
                        uint32_t a = stg + hl * TILE_B + SWZ(off);
                        LDSM4(afr[hl][mi][0], afr[hl][mi][1], afr[hl][mi][2], afr[hl][mi][3], a);
                    }
#pragma unroll
                for (int nj = 0; nj < 2; nj++) {
                    uint32_t off = (uint32_t)(nw + nj * 16 + rowoff) * 128 + kk * 32 + colb2;
                    uint32_t a = stg + 2 * TILE_B + SWZ(off);
                    LDSM4(bfr[nj][0], bfr[nj][1], bfr[nj][2], bfr[nj][3], a);
                }
#pragma unroll
                for (int term = 0; term < 2; term++)
#pragma unroll
                    for (int mi = 0; mi < 2; mi++)
#pragma unroll
                        for (int ni = 0; ni < 4; ni++) {
                            int nj = ni >> 1, s = ni & 1;
                            MMA16816(accg[mi][ni], afr[term][mi],
                                     bfr[nj][s], bfr[nj][s + 2]);
                        }
            }
        }

        // fold group scales (per output column n)
#pragma unroll
        for (int ni = 0; ni < 4; ni++) {
            float2 sv = *(const float2*)&ss[g * 132 + nw + ni * 8 + c0];
#pragma unroll
            for (int mi = 0; mi < 2; mi++) {
                acc[mi][ni][0] = fmaf(sv.x, accg[mi][ni][0], acc[mi][ni][0]);
                acc[mi][ni][1] = fmaf(sv.y, accg[mi][ni][1], acc[mi][ni][1]);
                acc[mi][ni][2] = fmaf(sv.x, accg[mi][ni][2], acc[mi][ni][2]);
                acc[mi][ni][3] = fmaf(sv.y, accg[mi][ni][3], acc[mi][ni][3]);
            }
        }
    }

    // epilogue
    const int r0 = lane >> 2;
#pragma unroll
    for (int mi = 0; mi < 2; mi++) {
#pragma unroll
        for (int ni = 0; ni < 4; ni++) {
            int m = m0 + mw + mi * 16 + r0;
            int n = n0 + nw + ni * 8 + c0;
            if (n < Nlim) {
                *(float2*)&C[(size_t)m * Nw + n]       = make_float2(acc[mi][ni][0], acc[mi][ni][1]);
                *(float2*)&C[(size_t)(m + 8) * Nw + n] = make_float2(acc[mi][ni][2], acc[mi][ni][3]);
            }
        }
    }
#undef TFILL
}

// ---------------- fq4 dequantization -> q (bf16, exact) + group scale ----------------
__global__ void k_dequantq(const float* __restrict__ src, __nv_bfloat16* __restrict__ dq,
                           float* __restrict__ ds, int ngroups)
{
    int g = blockIdx.x * 4 + (threadIdx.x >> 5);
    if (g >= ngroups) return;
    int lane = threadIdx.x & 31;
    const float* s = src + (size_t)g * 128;
    float v[4];
    float m = 0.f;
#pragma unroll
    for (int i = 0; i < 4; i++) { v[i] = s[lane + 32*i]; m = fmaxf(m, fabsf(v[i])); }
#pragma unroll
    for (int o = 16; o; o >>= 1) m = fmaxf(m, __shfl_xor_sync(0xffffffffu, m, o));
    float scale = fmaxf(m, 1e-10f) / 7.0f;
    if (lane == 0) ds[g] = scale;
#pragma unroll
    for (int i = 0; i < 4; i++) {
        float q = rintf(v[i] / scale);
        q = fminf(fmaxf(q, -8.f), 7.f);
        dq[(size_t)g * 128 + lane + 32*i] = __float2bfloat16(q);  // exact (small int)
    }
}

// ---------------- split fp32 -> bf16 hi/lo ----------------
__global__ void k_split(const float* __restrict__ src, __nv_bfloat16* __restrict__ dh,
                        __nv_bfloat16* __restrict__ dl)
{
    size_t i = ((size_t)blockIdx.x * 256 + threadIdx.x) * 4;
    float4 v = *(const float4*)(src + i);
    float vv[4] = {v.x, v.y, v.z, v.w};
#pragma unroll
    for (int k = 0; k < 4; k++) {
        __nv_bfloat16 h = __float2bfloat16(vv[k]);
        dh[i + k] = h;
        dl[i + k] = __float2bfloat16(vv[k] - __bfloat162float(h));
    }
}

// ---------------- pointwise epilogue per (b,l) row: 64 threads ----------------
__global__ void k_point(const float* __restrict__ Bb, const float* __restrict__ Cb,
                        const float* __restrict__ Alog, const float* __restrict__ dtb)
{
    int row = blockIdx.x;
    int t = threadIdx.x;
    const float* pr = g_P + (size_t)row * NPROJ;
    __shared__ float red[6];

    float dtr = pr[OFF_DT + t] + dtb[t];
    float dt = (dtr > 20.f) ? dtr : log1pf(expf(dtr));
    float Ad = -expf(Alog[t]) * dt;
    float lam = 1.f / (1.f + expf(-pr[OFF_LAM + t]));
    g_Ad[row*64 + t] = Ad;
    g_ga[row*64 + t] = lam * dt;
    g_be[row*64 + t] = (1.f - lam) * dt * expf(Ad);

    float bv = pr[OFF_B + t];
    float cv = pr[OFF_C + t];

    float s0 = dt, s1 = bv*bv, s2 = cv*cv;
#pragma unroll
    for (int o = 16; o; o >>= 1) {
        s0 += __shfl_xor_sync(0xffffffffu, s0, o);
        s1 += __shfl_xor_sync(0xffffffffu, s1, o);
        s2 += __shfl_xor_sync(0xffffffffu, s2, o);
    }
    int w = t >> 5;
    if ((t & 31) == 0) { red[w*3+0] = s0; red[w*3+1] = s1; red[w*3+2] = s2; }
    __syncthreads();
    float dt_avg = (red[0] + red[3]) * (1.f/64.f);
    float rb = rsqrtf((red[1] + red[4]) * (1.f/64.f) + RMS_EPS);
    float rc = rsqrtf((red[2] + red[5]) * (1.f/64.f) + RMS_EPS);

    g_Bv[row*64 + t] = bv * rb + Bb[t];
    g_Cv[row*64 + t] = cv * rc + Cb[t];
    if (t < 32) g_td[row*32 + t] = pr[OFF_TH + t] * dt_avg;
}

// ---------------- cumsum of theta*dt_avg over L per (b, n) ----------------
__global__ void k_scan()
{
    int b = blockIdx.x >> 5;
    int n = blockIdx.x & 31;
    int tid = threadIdx.x;
    __shared__ float ps[256];
    float loc[16];
    float run = 0.f;
    int base = (b*SEQ + tid*16) * 32 + n;
#pragma unroll
    for (int j = 0; j < 16; j++) { run += g_td[base + j*32]; loc[j] = run; }
    ps[tid] = run;
    __syncthreads();
#pragma unroll
    for (int o = 1; o < 256; o <<= 1) {
        float v = (tid >= o) ? ps[tid - o] : 0.f;
        __syncthreads();
        ps[tid] += v;
        __syncthreads();
    }
    float off = (tid > 0) ? ps[tid - 1] : 0.f;
#pragma unroll
    for (int j = 0; j < 16; j++) g_td[base + j*32] = loc[j] + off;
}

// ---------------- rope on B and C (in place) ----------------
__global__ void k_rope()
{
    int row = blockIdx.x;
    int t = threadIdx.x;
    float a = g_td[row*32 + t];
    float ca = cosf(a), sa = sinf(a);
    float br = g_Bv[row*64 + t], bi = g_Bv[row*64 + 32 + t];
    g_Bv[row*64 + t]      = br*ca - bi*sa;
    g_Bv[row*64 + 32 + t] = br*sa + bi*ca;
    float cr = g_Cv[row*64 + t], ci = g_Cv[row*64 + 32 + t];
    g_Cv[row*64 + t]      = cr*ca - ci*sa;
    g_Cv[row*64 + 32 + t] = cr*sa + ci*ca;
}

// ---------------- intra-chunk: Y_diag + per-chunk states ----------------
#define SM_CHUNK_BYTES ((4352*5 + 128) * 4)
__launch_bounds__(256)
__global__ void k_chunk()
{
    extern __shared__ float sm[];
    float* sX  = sm;
    float* sB  = sm + 4352;
    float* sBT = sm + 8704;
    float* sCT = sm + 13056;
    float* sGT = sm + 17408;
    float* sA  = sm + 21760;
    float* sW  = sm + 21824;

    const int h = blockIdx.x, c = blockIdx.y, b = blockIdx.z;
    const int tid = threadIdx.x;

    if (tid < 64) {
        int row_g = b*SEQ + c*64 + tid;
        sA[tid] = g_Ad[row_g*64 + h];
    }
    __syncthreads();
#pragma unroll
    for (int o = 1; o < 64; o <<= 1) {
        float v = (tid < 64 && tid >= o) ? sA[tid - o] : 0.f;
        __syncthreads();
        if (tid < 64) sA[tid] += v;
        __syncthreads();
    }
    float Alast = sA[63];
    if (tid < 64) {
        sW[tid] = expf(Alast - sA[tid]);
        g_eA[((b*NCHUNK + c)*NHEADS + h)*64 + tid] = expf(sA[tid]);
    }
    if (tid == 0) g_cd[(b*NCHUNK + c)*NHEADS + h] = expf(Alast);

#pragma unroll
    for (int it = 0; it < 4; it++) {
        int idx = tid + it*256;
        int l = idx >> 4;
        int p4 = (idx & 15) << 2;
        int row_g = b*SEQ + c*64 + l;
        const float* xp = g_P + (size_t)row_g*NPROJ + OFF_XC + h*64 + p4;
        float4 xc = *(const float4*)xp;
        float ga = g_ga[row_g*64 + h];
        float be = g_be[row_g*64 + h];
        float4 xv;
        xv.x = siluf(xc.x)*ga; xv.y = siluf(xc.y)*ga; xv.z = siluf(xc.z)*ga; xv.w = siluf(xc.w)*ga;
        if (c*64 + l > 0) {
            float4 xq = *(const float4*)(xp - NPROJ);
            xv.x += siluf(xq.x)*be; xv.y += siluf(xq.y)*be; xv.z += siluf(xq.z)*be; xv.w += siluf(xq.w)*be;
        }
        *(float4*)&sX[l*68 + p4] = xv;
        float4 bb = *(const float4*)&g_Bv[row_g*64 + p4];
        *(float4*)&sB[l*68 + p4] = bb;
        sBT[(p4+0)*68 + l] = bb.x; sBT[(p4+1)*68 + l] = bb.y;
        sBT[(p4+2)*68 + l] = bb.z; sBT[(p4+3)*68 + l] = bb.w;
        float4 cc = *(const float4*)&g_Cv[row_g*64 + p4];
        sCT[(p4+0)*68 + l] = cc.x; sCT[(p4+1)*68 + l] = cc.y;
        sCT[(p4+2)*68 + l] = cc.z; sCT[(p4+3)*68 + l] = cc.w;
    }
    __syncthreads();

    const int ti = tid >> 4, tj = tid & 15;

    // G tile (ti,tj) is fully masked (s > l everywhere) when tj > ti, and
    // Y_diag's truncated loop never reads those entries -> skip entirely.
    if (tj <= ti) {
        const int l0 = ti*4, s0 = tj*4;
        float acc[4][4];
#pragma unroll
        for (int i = 0; i < 4; i++)
#pragma unroll
            for (int j = 0; j < 4; j++) acc[i][j] = 0.f;
#pragma unroll
        for (int n = 0; n < 64; n++) {
            float4 cl = *(const float4*)&sCT[n*68 + l0];
            float4 bs = *(const float4*)&sBT[n*68 + s0];
            float clv[4] = {cl.x, cl.y, cl.z, cl.w};
            float bsv[4] = {bs.x, bs.y, bs.z, bs.w};
#pragma unroll
            for (int i = 0; i < 4; i++)
#pragma unroll
                for (int j = 0; j < 4; j++)
                    acc[i][j] = fmaf(clv[i], bsv[j], acc[i][j]);
        }
        float al[4];
#pragma unroll
        for (int i = 0; i < 4; i++) al[i] = sA[l0 + i];
#pragma unroll
        for (int j = 0; j < 4; j++) {
            int s = s0 + j;
            float as = sA[s];
#pragma unroll
            for (int i = 0; i < 4; i++) {
                int l = l0 + i;
                sGT[s*68 + l] = (s <= l) ? acc[i][j] * expf(al[i] - as) : 0.f;
            }
        }
    }
    __syncthreads();

    {
        const int l0 = ti*4, p0 = tj*4;
        float acc[4][4];
#pragma unroll
        for (int i = 0; i < 4; i++)
#pragma unroll
            for (int j = 0; j < 4; j++) acc[i][j] = 0.f;
        const int smax = l0 + 4;
#pragma unroll 4
        for (int s = 0; s < smax; s++) {
            float4 gt = *(const float4*)&sGT[s*68 + l0];
            float4 xr = *(const float4*)&sX[s*68 + p0];
            float gv[4] = {gt.x, gt.y, gt.z, gt.w};
            float xvv[4] = {xr.x, xr.y, xr.z, xr.w};
#pragma unroll
            for (int i = 0; i < 4; i++)
#pragma unroll
                for (int j = 0; j < 4; j++)
                    acc[i][j] = fmaf(gv[i], xvv[j], acc[i][j]);
        }
#pragma unroll
        for (int i = 0; i < 4; i++) {
            int row_g = b*SEQ + c*64 + l0 + i;
            *(float4*)&g_Y[(size_t)row_g*D_INNER + h*64 + p0] =
                make_float4(acc[i][0], acc[i][1], acc[i][2], acc[i][3]);
        }
    }

    {
        const int p0 = ti*4, n0 = tj*4;
        float acc[4][4];
#pragma unroll
        for (int i = 0; i < 4; i++)
#pragma unroll
            for (int j = 0; j < 4; j++) acc[i][j] = 0.f;
#pragma unroll
        for (int l = 0; l < 64; l++) {
            float w = sW[l];
            float4 xr = *(const float4*)&sX[l*68 + p0];
            float4 br = *(const float4*)&sB[l*68 + n0];
            float wx[4] = {w*xr.x, w*xr.y, w*xr.z, w*xr.w};
            float bvv[4] = {br.x, br.y, br.z, br.w};
#pragma unroll
            for (int i = 0; i < 4; i++)
#pragma unroll
                for (int j = 0; j < 4; j++)
                    acc[i][j] = fmaf(wx[i], bvv[j], acc[i][j]);
        }
        size_t base = (size_t)((b*NCHUNK + c)*NHEADS + h) * 4096;
#pragma unroll
        for (int i = 0; i < 4; i++)
            *(float4*)&g_S[base + (p0 + i)*64 + n0] =
                make_float4(acc[i][0], acc[i][1], acc[i][2], acc[i][3]);
    }
}

// ---------------- inter-chunk scan: 512 CTAs, one (b,h,quarter) each ----------------
__global__ void k_cscan()
{
    int q = blockIdx.x & 3;
    int h = (blockIdx.x >> 2) & 63;
    int b = blockIdx.x >> 8;
    int tid = threadIdx.x;
    int off = q * 1024 + tid * 4;
    float s0 = 0.f, s1 = 0.f, s2 = 0.f, s3 = 0.f;
    const float* cdp = g_cd + b * NCHUNK * NHEADS + h;
    for (int c = 0; c < NCHUNK; c++) {
        size_t base = ((size_t)((b*NCHUNK + c)*NHEADS + h) << 12) + off;
        float cd = cdp[c * NHEADS];
        float4 t = *(const float4*)&g_S[base];
        *(float4*)&g_S[base] = make_float4(s0, s1, s2, s3);
        s0 = fmaf(cd, s0, t.x);
        s1 = fmaf(cd, s1, t.y);
        s2 = fmaf(cd, s2, t.z);
        s3 = fmaf(cd, s3, t.w);
    }
}

// ---------------- Y_off + D skip + z gating ----------------
__launch_bounds__(256)
__global__ void k_off(const float* __restrict__ Dp)
{
    __shared__ float sST[64*68];
    __shared__ float sCT[64*68];
    const int h = blockIdx.x, c = blockIdx.y, b = blockIdx.z;
    const int tid = threadIdx.x;
    size_t sbase = (size_t)((b*NCHUNK + c)*NHEADS + h) * 4096;
#pragma unroll
    for (int it = 0; it < 4; it++) {
        int idx = tid + it*256;
        int r = idx >> 4;
        int n4 = (idx & 15) << 2;
        float4 sv = *(const float4*)&g_S[sbase + r*64 + n4];
        sST[(n4+0)*68 + r] = sv.x; sST[(n4+1)*68 + r] = sv.y;
        sST[(n4+2)*68 + r] = sv.z; sST[(n4+3)*68 + r] = sv.w;
        int row_g = b*SEQ + c*64 + r;
        float4 cv = *(const float4*)&g_Cv[row_g*64 + n4];
        sCT[(n4+0)*68 + r] = cv.x; sCT[(n4+1)*68 + r] = cv.y;
        sCT[(n4+2)*68 + r] = cv.z; sCT[(n4+3)*68 + r] = cv.w;
    }
    __syncthreads();
    const int ti = tid >> 4, tj = tid & 15;
    const int l0 = ti*4, p0 = tj*4;
    float acc[4][4];
#pragma unroll
    for (int i = 0; i < 4; i++)
#pragma unroll
        for (int j = 0; j < 4; j++) acc[i][j] = 0.f;
#pragma unroll
    for (int n = 0; n < 64; n++) {
        float4 cl = *(const float4*)&sCT[n*68 + l0];
        float4 sp = *(const float4*)&sST[n*68 + p0];
        float clv[4] = {cl.x, cl.y, cl.z, cl.w};
        float spv[4] = {sp.x, sp.y, sp.z, sp.w};
#pragma unroll
        for (int i = 0; i < 4; i++)
#pragma unroll
            for (int j = 0; j < 4; j++)
                acc[i][j] = fmaf(clv[i], spv[j], acc[i][j]);
    }
    float Dh = Dp[h];
#pragma unroll
    for (int i = 0; i < 4; i++) {
        int l = l0 + i;
        int row_g = b*SEQ + c*64 + l;
        float e = g_eA[((b*NCHUNK + c)*NHEADS + h)*64 + l];
        const float* pr = g_P + (size_t)row_g*NPROJ;
        float4 xc = *(const float4*)&pr[OFF_XC + h*64 + p0];
        float4 zz = *(const float4*)&pr[OFF_Z  + h*64 + p0];
        float* yp = &g_Y[(size_t)row_g*D_INNER + h*64 + p0];
        float4 yd = *(const float4*)yp;
        float4 o;
        o.x = (yd.x + e*acc[i][0] + Dh*siluf(xc.x)) * siluf(zz.x);
        o.y = (yd.y + e*acc[i][1] + Dh*siluf(xc.y)) * siluf(zz.y);
        o.z = (yd.z + e*acc[i][2] + Dh*siluf(xc.z)) * siluf(zz.z);
        o.w = (yd.w + e*acc[i][3] + Dh*siluf(xc.w)) * siluf(zz.w);
        *(float4*)yp = o;
    }
}

// ---------------- rmsnorm over 4096 per row -> bf16 hi/lo ----------------
__global__ void k_rms()
{
    int row = blockIdx.x;
    int tid = threadIdx.x;
    const float* Yp = g_Y + (size_t)row * D_INNER;
    float4 v[4];
    float ss = 0.f;
#pragma unroll
    for (int i = 0; i < 4; i++) {
        v[i] = *(const float4*)&Yp[tid*16 + i*4];
        ss += v[i].x*v[i].x + v[i].y*v[i].y + v[i].z*v[i].z + v[i].w*v[i].w;
    }
#pragma unroll
    for (int o = 16; o; o >>= 1) ss += __shfl_xor_sync(0xffffffffu, ss, o);
    __shared__ float red[8];
    if ((tid & 31) == 0) red[tid >> 5] = ss;
    __syncthreads();
    float tot = 0.f;
#pragma unroll
    for (int i = 0; i < 8; i++) tot += red[i];
    float r = rsqrtf(tot * (1.f/4096.f) + RMS_EPS);
    size_t base = (size_t)row * D_INNER + tid*16;
#pragma unroll
    for (int i = 0; i < 4; i++) {
        float vv[4] = {v[i].x*r, v[i].y*r, v[i].z*r, v[i].w*r};
#pragma unroll
        for (int k = 0; k < 4; k++) {
            __nv_bfloat16 h = __float2bfloat16(vv[k]);
            g_Yh[base + i*4 + k] = h;
            g_Yl[base + i*4 + k] = __float2bfloat16(vv[k] - __bfloat162float(h));
        }
    }
}

// ---------------- host: tensormap construction via driver entry point ----------------
typedef CUresult (*PFN_encodeTiled)(
    CUtensorMap*, CUtensorMapDataType, cuuint32_t, void*,
    const cuuint64_t*, const cuuint64_t*, const cuuint32_t*, const cuuint32_t*,
    CUtensorMapInterleave, CUtensorMapSwizzle, CUtensorMapL2promotion, CUtensorMapFloatOOBfill);

static void mk2d(PFN_encodeTiled enc, CUtensorMap* m, void* ptr, uint64_t k, uint64_t rows)
{
    cuuint64_t dims[2]    = {k, rows};
    cuuint64_t strides[1] = {k * 2};          // bytes per row (bf16)
    cuuint32_t box[2]     = {64, 128};        // 128B x 128 rows = one SW128 tile
    cuuint32_t es[2]      = {1, 1};
    enc(m, CU_TENSOR_MAP_DATA_TYPE_BFLOAT16, 2, ptr, dims, strides, box, es,
        CU_TENSOR_MAP_INTERLEAVE_NONE, CU_TENSOR_MAP_SWIZZLE_128B,
        CU_TENSOR_MAP_L2_PROMOTION_L2_128B, CU_TENSOR_MAP_FLOAT_OOB_FILL_NONE);
}

// ---------------- launcher ----------------
extern "C" void kernel_launch(void* const* d_in, const int* in_sizes, int n_in,
                              void* d_out, int out_size)
{
    const float* x    = (const float*)d_in[0];
    const float* Win  = (const float*)d_in[1];
    const float* Wth  = (const float*)d_in[2];
    const float* Wla  = (const float*)d_in[3];
    const float* Wout = (const float*)d_in[4];
    const float* Bb   = (const float*)d_in[5];
    const float* Cb   = (const float*)d_in[6];
    const float* Alog = (const float*)d_in[7];
    const float* Dp   = (const float*)d_in[8];
    const float* dtb  = (const float*)d_in[9];
    float* out = (float*)d_out;

    __nv_bfloat16 *pWq, *pWoq, *pxh, *pxl, *pYh, *pYl;
    float *pWs, *pWos, *pP;
    cudaGetSymbolAddress((void**)&pWq,  g_Wq);
    cudaGetSymbolAddress((void**)&pWs,  g_Ws);
    cudaGetSymbolAddress((void**)&pWoq, g_Woq);
    cudaGetSymbolAddress((void**)&pWos, g_Wos);
    cudaGetSymbolAddress((void**)&pxh,  g_xh);
    cudaGetSymbolAddress((void**)&pxl,  g_xl);
    cudaGetSymbolAddress((void**)&pYh,  g_Yh);
    cudaGetSymbolAddress((void**)&pYl,  g_Yl);
    cudaGetSymbolAddress((void**)&pP,   g_P);

    // tensormaps (host-side, CPU-only; device globals are stable across replays)
    PFN_encodeTiled enc = nullptr;
    {
        void* fp = nullptr;
        cudaDriverEntryPointQueryResult qr;
        cudaGetDriverEntryPoint("cuTensorMapEncodeTiled", &fp, cudaEnableDefault, &qr);
        enc = (PFN_encodeTiled)fp;
    }
    CUtensorMap t1Ah, t1Al, t1Bq, t2Ah, t2Al, t2Bq;
    mk2d(enc, &t1Ah, pxh,  DIMK,    ROWS);
    mk2d(enc, &t1Al, pxl,  DIMK,    ROWS);
    mk2d(enc, &t1Bq, pWq,  DIMK,    NPROJ_PAD);
    mk2d(enc, &t2Ah, pYh,  D_INNER, ROWS);
    mk2d(enc, &t2Al, pYl,  D_INNER, ROWS);
    mk2d(enc, &t2Bq, pWoq, D_INNER, DIMK);

    const int smem1 = SSB_OFF + 16 * 132 * 4;   // 147520 + 8448  = 155968
    const int smem2 = SSB_OFF + 32 * 132 * 4;   // 147520 + 16896 = 164416

    cudaFuncSetAttribute(k_chunk,    cudaFuncAttributeMaxDynamicSharedMemorySize, SM_CHUNK_BYTES);
    cudaFuncSetAttribute(k_mmt<16>,  cudaFuncAttributeMaxDynamicSharedMemorySize, smem1);
    cudaFuncSetAttribute(k_mmt<32>,  cudaFuncAttributeMaxDynamicSharedMemorySize, smem2);

    // fq4 dequant -> q + scales into fused weight buffer (pad rows stay zero)
    k_dequantq<<<(8384*16 + 3)/4, 128>>>(Win, pWq, pWs, 8384*16);
    k_dequantq<<<(512 + 3)/4,    128>>>(Wth, pWq + (size_t)8384*DIMK, pWs + (size_t)8384*16, 512);
    k_dequantq<<<(1024 + 3)/4,   128>>>(Wla, pWq + (size_t)8416*DIMK, pWs + (size_t)8416*16, 1024);
    k_dequantq<<<65536/4,        128>>>(Wout, pWoq, pWos, 65536);

    // split activations
    k_split<<<ROWS*DIMK/1024, 256>>>(x, pxh, pxl);

    // in-projection GEMM: 8192 x 8480 x 2048 (TMA-fed, 2-term + group-scale fold)
    k_mmt<16><<<dim3(ROWS/128, NPROJ_PAD/128), 512, smem1>>>(
        t1Ah, t1Al, t1Bq, pWs, pP, NPROJ, NPROJ, DIMK);

    k_point<<<ROWS, 64>>>(Bb, Cb, Alog, dtb);
    k_scan <<<64, 256>>>();
    k_rope <<<ROWS, 32>>>();

    k_chunk<<<dim3(NHEADS, NCHUNK, BATCH), 256, SM_CHUNK_BYTES>>>();
    k_cscan<<<512, 256>>>();
    k_off  <<<dim3(NHEADS, NCHUNK, BATCH), 256>>>(Dp);

    k_rms<<<ROWS, 256>>>();

    // out-projection GEMM: 8192 x 2048 x 4096 (TMA-fed, 2-term + group-scale fold)
    k_mmt<32><<<dim3(ROWS/128, DIMK/128), 512, smem2>>>(
        t2Ah, t2Al, t2Bq, pWos, out, DIMK, DIMK, D_INNER);
}